// round 8
// baseline (speedup 1.0000x reference)
#include <cuda_runtime.h>
#include <cuda_bf16.h>
#include <cstdint>

#define NNODES 50000
#define NODPAD 50048
#define NEDGES 800000
#define F_IN   128
#define HID    256
#define NOUT   40
#define MTILES (NODPAD / 128)   // 391
#define NSEG   4
#define SEGT   98                // tiles per segment (last = 97)

// ---------------- scratch (static device memory, no allocations) ------------
__device__ int   g_cnt[NNODES];
__device__ int   g_off[NNODES];
__device__ int   g_cur[NNODES];
__device__ int   g_total;
__device__ float g_dinv[NNODES];
__device__ __align__(8) int2 g_edge[NEDGES];   // (src, weight bits)
__device__ __align__(16) __nv_bfloat16 g_ax_hi[(size_t)NODPAD * F_IN];
__device__ __align__(16) __nv_bfloat16 g_ax_lo[(size_t)NODPAD * F_IN];
__device__ __align__(16) __nv_bfloat16 g_a1_hi[(size_t)NODPAD * HID];
__device__ __align__(16) __nv_bfloat16 g_a1_lo[(size_t)NODPAD * HID];
__device__ __align__(16) float g_h1[(size_t)NNODES * HID];
__device__ __align__(16) float g_h2[(size_t)NNODES * HID];
__device__ __align__(16) __nv_bfloat16 g_w1hi[HID * F_IN];
__device__ __align__(16) __nv_bfloat16 g_w1lo[HID * F_IN];
__device__ __align__(16) __nv_bfloat16 g_w2hi[HID * HID];
__device__ __align__(16) __nv_bfloat16 g_w2lo[HID * HID];

// ---------------- helpers ------------------------------------------------------
__device__ __forceinline__ void split1(float v, __nv_bfloat16& h, __nv_bfloat16& l) {
    h = __float2bfloat16(v);
    l = __float2bfloat16(v - __bfloat162float(h));
}

__device__ __forceinline__ void split4(float4 a, uint2& hi, uint2& lo) {
    __nv_bfloat16 h0, h1, h2, h3, l0, l1, l2, l3;
    split1(a.x, h0, l0); split1(a.y, h1, l1);
    split1(a.z, h2, l2); split1(a.w, h3, l3);
    __nv_bfloat162 hp0 = __halves2bfloat162(h0, h1);
    __nv_bfloat162 hp1 = __halves2bfloat162(h2, h3);
    __nv_bfloat162 lp0 = __halves2bfloat162(l0, l1);
    __nv_bfloat162 lp1 = __halves2bfloat162(l2, l3);
    hi.x = *(uint32_t*)&hp0; hi.y = *(uint32_t*)&hp1;
    lo.x = *(uint32_t*)&lp0; lo.y = *(uint32_t*)&lp1;
}

// ---------------- graph preprocessing ---------------------------------------
__global__ void k_init()
{
    int i = blockIdx.x * blockDim.x + threadIdx.x;
    if (i < NNODES) { g_cnt[i] = 0; g_cur[i] = 0; }
    if (i == 0) g_total = 0;
}

__global__ void k_count(const int* __restrict__ ei)
{
    int e = blockIdx.x * blockDim.x + threadIdx.x;
    if (e < NEDGES) atomicAdd(&g_cnt[ei[NEDGES + e]], 1);
}

__global__ void k_offsets()
{
    int i = blockIdx.x * blockDim.x + threadIdx.x;
    if (i >= NNODES) return;
    int c = g_cnt[i];
    g_off[i]  = atomicAdd(&g_total, c);
    g_dinv[i] = rsqrtf((float)(c + 1));
}

__global__ void k_scatter(const int* __restrict__ ei)
{
    int e = blockIdx.x * blockDim.x + threadIdx.x;
    if (e >= NEDGES) return;
    int s = ei[e];
    int d = ei[NEDGES + e];
    int pos = g_off[d] + atomicAdd(&g_cur[d], 1);
    g_edge[pos] = make_int2(s, __float_as_int(g_dinv[s] * g_dinv[d]));
}

__global__ void k_prepw(const float* __restrict__ W1, const float* __restrict__ W2)
{
    int i = blockIdx.x * blockDim.x + threadIdx.x;
    if (i < HID * F_IN) {
        int n = i / F_IN, k = i % F_IN;
        split1(W1[k * HID + n], g_w1hi[i], g_w1lo[i]);
    }
    int j = i - HID * F_IN;
    if (j >= 0 && j < HID * HID) {
        int n = j / HID, k = j % HID;
        split1(W2[k * HID + n], g_w2hi[j], g_w2lo[j]);
    }
}

// ---------------- sparse aggregation: warp per destination node --------------
template <int F>
__device__ __forceinline__ void agg_impl(const float* __restrict__ in,
                                         __nv_bfloat16* __restrict__ ohi,
                                         __nv_bfloat16* __restrict__ olo,
                                         int node_base, int node_end)
{
    const int warp = node_base + ((blockIdx.x * blockDim.x + threadIdx.x) >> 5);
    const int lane = threadIdx.x & 31;
    if (warp >= node_end) return;

    constexpr int V = F / 128;
    float4 acc[V];

    const float dn = g_dinv[warp];
    const float w0 = dn * dn;
    const float4* selfrow = (const float4*)(in + (size_t)warp * F);
    #pragma unroll
    for (int v = 0; v < V; v++) {
        float4 t = __ldg(&selfrow[lane + 32 * v]);
        acc[v].x = w0 * t.x; acc[v].y = w0 * t.y;
        acc[v].z = w0 * t.z; acc[v].w = w0 * t.w;
    }

    const int beg = g_off[warp];
    const int end = beg + g_cnt[warp];
    int i = beg;
    for (; i + 2 <= end; i += 2) {
        const int2 e0 = g_edge[i];
        const int2 e1 = g_edge[i + 1];
        const float4* r0 = (const float4*)(in + (size_t)e0.x * F);
        const float4* r1 = (const float4*)(in + (size_t)e1.x * F);
        const float we0 = __int_as_float(e0.y);
        const float we1 = __int_as_float(e1.y);
        #pragma unroll
        for (int v = 0; v < V; v++) {
            float4 t0 = __ldg(&r0[lane + 32 * v]);
            float4 t1 = __ldg(&r1[lane + 32 * v]);
            acc[v].x += we0 * t0.x; acc[v].y += we0 * t0.y;
            acc[v].z += we0 * t0.z; acc[v].w += we0 * t0.w;
            acc[v].x += we1 * t1.x; acc[v].y += we1 * t1.y;
            acc[v].z += we1 * t1.z; acc[v].w += we1 * t1.w;
        }
    }
    if (i < end) {
        const int2 e0 = g_edge[i];
        const float4* r0 = (const float4*)(in + (size_t)e0.x * F);
        const float we0 = __int_as_float(e0.y);
        #pragma unroll
        for (int v = 0; v < V; v++) {
            float4 t0 = __ldg(&r0[lane + 32 * v]);
            acc[v].x += we0 * t0.x; acc[v].y += we0 * t0.y;
            acc[v].z += we0 * t0.z; acc[v].w += we0 * t0.w;
        }
    }

    #pragma unroll
    for (int v = 0; v < V; v++) {
        size_t o = (size_t)warp * F + 4 * (lane + 32 * v);
        uint2 hi, lo;
        split4(acc[v], hi, lo);
        *(uint2*)(ohi + o) = hi;
        *(uint2*)(olo + o) = lo;
    }
}

__global__ void k_agg_x(const float* __restrict__ x, int nb, int ne)
{
    agg_impl<F_IN>(x, g_ax_hi, g_ax_lo, nb, ne);
}
__global__ void k_agg_h1(int nb, int ne)
{
    agg_impl<HID>(g_h1, g_a1_hi, g_a1_lo, nb, ne);
}

// ---------------- HMMA bf16 GEMM: C = relu(A' @ B'^T + bias) -----------------
#define SROWB 80
#define A_STG (128 * SROWB)
#define B_STG (256 * SROWB)
#define GEMM_SMEM (2 * A_STG + 2 * B_STG)   // 61440 B

template <int F>
__device__ __forceinline__ void gemm_body(const __nv_bfloat16* __restrict__ Ahi,
                                          const __nv_bfloat16* __restrict__ Alo,
                                          const __nv_bfloat16* __restrict__ Bhi,
                                          const __nv_bfloat16* __restrict__ Blo,
                                          const float* __restrict__ bias,
                                          float* __restrict__ C, int tile_base)
{
    extern __shared__ __align__(16) uint8_t smem_dyn[];
    uint32_t sA;
    asm("{ .reg .u64 t; cvta.to.shared.u64 t, %1; cvt.u32.u64 %0, t; }"
        : "=r"(sA) : "l"(&smem_dyn[0]));
    const uint32_t sB = sA + 2 * A_STG;

    const int tid  = threadIdx.x;
    const int lane = tid & 31;
    const int wid  = tid >> 5;
    const int g    = lane >> 2;
    const int tg   = lane & 3;
    const int wm   = (wid & 1) * 64;
    const int wn   = (wid >> 1) * 64;
    const int brow = (tile_base + blockIdx.x) * 128;

    float acc[4][8][4];
    #pragma unroll
    for (int mi = 0; mi < 4; mi++)
        #pragma unroll
        for (int ni = 0; ni < 8; ni++)
            #pragma unroll
            for (int c = 0; c < 4; c++) acc[mi][ni][c] = 0.f;

    const int lrow = tid >> 2;
    const int lseg = tid & 3;
    auto load_stage = [&](int st, int k0) {
        const int seg = k0 / F;
        const int kk0 = k0 - seg * F;
        const __nv_bfloat16* a_src = (seg == 1) ? Alo : Ahi;
        const __nv_bfloat16* b_src = (seg == 2) ? Blo : Bhi;
        #pragma unroll
        for (int i = 0; i < 2; i++) {
            int row = lrow + i * 64;
            uint32_t so = sA + (uint32_t)st * A_STG + row * SROWB + lseg * 16;
            const __nv_bfloat16* ga = a_src + (size_t)(brow + row) * F + kk0 + lseg * 8;
            asm volatile("cp.async.cg.shared.global [%0], [%1], 16;"
                         :: "r"(so), "l"(ga));
        }
        #pragma unroll
        for (int i = 0; i < 4; i++) {
            int row = lrow + i * 64;
            uint32_t so = sB + (uint32_t)st * B_STG + row * SROWB + lseg * 16;
            const __nv_bfloat16* gb = b_src + (size_t)row * F + kk0 + lseg * 8;
            asm volatile("cp.async.cg.shared.global [%0], [%1], 16;"
                         :: "r"(so), "l"(gb));
        }
        asm volatile("cp.async.commit_group;");
    };

    constexpr int NK = 3 * F / 32;
    load_stage(0, 0);

    const int lr  = lane & 15;
    const int lhi = (lane >> 4) * 16;

    for (int ki = 0; ki < NK; ki++) {
        if (ki + 1 < NK) {
            load_stage((ki + 1) & 1, (ki + 1) * 32);
            asm volatile("cp.async.wait_group 1;");
        } else {
            asm volatile("cp.async.wait_group 0;");
        }
        __syncthreads();

        const uint32_t bufA = sA + (ki & 1) * A_STG;
        const uint32_t bufB = sB + (ki & 1) * B_STG;

        #pragma unroll
        for (int kk = 0; kk < 2; kk++) {
            const uint32_t kb = kk * 32;
            uint32_t af[4][4];
            #pragma unroll
            for (int mi = 0; mi < 4; mi++) {
                uint32_t addr = bufA + (wm + mi * 16 + lr) * SROWB + kb + lhi;
                asm volatile("ldmatrix.sync.aligned.m8n8.x4.shared.b16 {%0,%1,%2,%3}, [%4];"
                             : "=r"(af[mi][0]), "=r"(af[mi][1]),
                               "=r"(af[mi][2]), "=r"(af[mi][3]) : "r"(addr));
            }
            #pragma unroll
            for (int p = 0; p < 4; p++) {
                uint32_t r0, r1, r2, r3;
                uint32_t addr = bufB + (wn + p * 16 + lr) * SROWB + kb + lhi;
                asm volatile("ldmatrix.sync.aligned.m8n8.x4.shared.b16 {%0,%1,%2,%3}, [%4];"
                             : "=r"(r0), "=r"(r1), "=r"(r2), "=r"(r3) : "r"(addr));
                #pragma unroll
                for (int mi = 0; mi < 4; mi++) {
                    asm volatile(
                        "mma.sync.aligned.m16n8k16.row.col.f32.bf16.bf16.f32 "
                        "{%0,%1,%2,%3},{%4,%5,%6,%7},{%8,%9},{%0,%1,%2,%3};"
                        : "+f"(acc[mi][2 * p][0]), "+f"(acc[mi][2 * p][1]),
                          "+f"(acc[mi][2 * p][2]), "+f"(acc[mi][2 * p][3])
                        : "r"(af[mi][0]), "r"(af[mi][1]), "r"(af[mi][2]), "r"(af[mi][3]),
                          "r"(r0), "r"(r2));
                    asm volatile(
                        "mma.sync.aligned.m16n8k16.row.col.f32.bf16.bf16.f32 "
                        "{%0,%1,%2,%3},{%4,%5,%6,%7},{%8,%9},{%0,%1,%2,%3};"
                        : "+f"(acc[mi][2 * p + 1][0]), "+f"(acc[mi][2 * p + 1][1]),
                          "+f"(acc[mi][2 * p + 1][2]), "+f"(acc[mi][2 * p + 1][3])
                        : "r"(af[mi][0]), "r"(af[mi][1]), "r"(af[mi][2]), "r"(af[mi][3]),
                          "r"(r1), "r"(r3));
                }
            }
        }
        __syncthreads();
    }

    #pragma unroll
    for (int ni = 0; ni < 8; ni++) {
        const int col = wn + ni * 8 + tg * 2;
        const float b0 = __ldg(bias + col);
        const float b1 = __ldg(bias + col + 1);
        #pragma unroll
        for (int mi = 0; mi < 4; mi++) {
            int r0 = brow + wm + mi * 16 + g;
            if (r0 < NNODES) {
                float2 o;
                o.x = fmaxf(acc[mi][ni][0] + b0, 0.f);
                o.y = fmaxf(acc[mi][ni][1] + b1, 0.f);
                *(float2*)(C + (size_t)r0 * HID + col) = o;
            }
            int r1 = r0 + 8;
            if (r1 < NNODES) {
                float2 o;
                o.x = fmaxf(acc[mi][ni][2] + b0, 0.f);
                o.y = fmaxf(acc[mi][ni][3] + b1, 0.f);
                *(float2*)(C + (size_t)r1 * HID + col) = o;
            }
        }
    }
}

__global__ void __launch_bounds__(256) k_gemm1(const float* __restrict__ b1, int tb)
{
    gemm_body<F_IN>(g_ax_hi, g_ax_lo, g_w1hi, g_w1lo, b1, g_h1, tb);
}
__global__ void __launch_bounds__(256) k_gemm2(const float* __restrict__ b2, int tb)
{
    gemm_body<HID>(g_a1_hi, g_a1_lo, g_w2hi, g_w2lo, b2, g_h2, tb);
}

// ---------------- classifier: out[Nx40] = h2[Nx256] @ Wc[256x40] + bc --------
__global__ void __launch_bounds__(256) k_cls(const float* __restrict__ Wc,
                                             const float* __restrict__ bc,
                                             float* __restrict__ out, int tb)
{
    __shared__ float Ws[HID * NOUT];
    const int tid = threadIdx.x;
    for (int i = tid; i < HID * NOUT; i += 256) Ws[i] = Wc[i];
    __syncthreads();

    const int s  = tid >> 2;
    const int cg = (tid & 3) * 10;
    const int r0 = (tb + blockIdx.x) * 128 + s;
    const int r1 = r0 + 64;
    const bool v0 = r0 < NNODES;
    const bool v1 = r1 < NNODES;
    if (!v0) return;

    const float* h0 = g_h2 + (size_t)r0 * HID;
    const float* h1 = g_h2 + (size_t)(v1 ? r1 : r0) * HID;

    unsigned long long acc0[5] = {0, 0, 0, 0, 0};
    unsigned long long acc1[5] = {0, 0, 0, 0, 0};

    #pragma unroll 2
    for (int k = 0; k < HID; k += 4) {
        float4 a0 = *(const float4*)(h0 + k);
        float4 a1 = *(const float4*)(h1 + k);
        const float av0[4] = {a0.x, a0.y, a0.z, a0.w};
        const float av1[4] = {a1.x, a1.y, a1.z, a1.w};
        #pragma unroll
        for (int kk = 0; kk < 4; kk++) {
            unsigned long long hb0, hb1;
            asm("mov.b64 %0, {%1, %1};" : "=l"(hb0) : "r"(__float_as_uint(av0[kk])));
            asm("mov.b64 %0, {%1, %1};" : "=l"(hb1) : "r"(__float_as_uint(av1[kk])));
            const float* wrow = Ws + (k + kk) * NOUT + cg;
            #pragma unroll
            for (int j = 0; j < 5; j++) {
                unsigned long long w = *(const unsigned long long*)(wrow + 2 * j);
                asm("fma.rn.f32x2 %0, %1, %2, %0;" : "+l"(acc0[j]) : "l"(hb0), "l"(w));
                asm("fma.rn.f32x2 %0, %1, %2, %0;" : "+l"(acc1[j]) : "l"(hb1), "l"(w));
            }
        }
    }

    #pragma unroll
    for (int j = 0; j < 5; j++) {
        uint32_t lo, hi;
        float bcl = __ldg(bc + cg + 2 * j);
        float bch = __ldg(bc + cg + 2 * j + 1);
        asm("mov.b64 {%0, %1}, %2;" : "=r"(lo), "=r"(hi) : "l"(acc0[j]));
        out[(size_t)r0 * NOUT + cg + 2 * j]     = __uint_as_float(lo) + bcl;
        out[(size_t)r0 * NOUT + cg + 2 * j + 1] = __uint_as_float(hi) + bch;
        if (v1) {
            asm("mov.b64 {%0, %1}, %2;" : "=r"(lo), "=r"(hi) : "l"(acc1[j]));
            out[(size_t)r1 * NOUT + cg + 2 * j]     = __uint_as_float(lo) + bcl;
            out[(size_t)r1 * NOUT + cg + 2 * j + 1] = __uint_as_float(hi) + bch;
        }
    }
}

// ---------------- stream/event context (created once at module init) ----------
struct PipeCtx {
    cudaStream_t s[NSEG];
    cudaEvent_t evStart, evPrep, evAx[NSEG], evG1[NSEG], evAh[NSEG], evC[NSEG];
    PipeCtx() {
        for (int i = 0; i < NSEG; i++)
            cudaStreamCreateWithFlags(&s[i], cudaStreamNonBlocking);
        cudaEventCreateWithFlags(&evStart, cudaEventDisableTiming);
        cudaEventCreateWithFlags(&evPrep,  cudaEventDisableTiming);
        for (int i = 0; i < NSEG; i++) {
            cudaEventCreateWithFlags(&evAx[i], cudaEventDisableTiming);
            cudaEventCreateWithFlags(&evG1[i], cudaEventDisableTiming);
            cudaEventCreateWithFlags(&evAh[i], cudaEventDisableTiming);
            cudaEventCreateWithFlags(&evC[i],  cudaEventDisableTiming);
        }
    }
};
static PipeCtx g_pipe;

// ---------------- launch ------------------------------------------------------
extern "C" void kernel_launch(void* const* d_in, const int* in_sizes, int n_in,
                              void* d_out, int out_size)
{
    const float* x   = (const float*)d_in[0];
    const float* W1  = (const float*)d_in[1];
    const float* b1  = (const float*)d_in[2];
    const float* W2  = (const float*)d_in[3];
    const float* b2  = (const float*)d_in[4];
    const float* Wc  = (const float*)d_in[5];
    const float* bc  = (const float*)d_in[6];
    const int*   ei  = (const int*)  d_in[7];
    float*       out = (float*)d_out;

    cudaFuncSetAttribute(k_gemm1, cudaFuncAttributeMaxDynamicSharedMemorySize, GEMM_SMEM);
    cudaFuncSetAttribute(k_gemm2, cudaFuncAttributeMaxDynamicSharedMemorySize, GEMM_SMEM);

    const cudaStream_t s0 = 0;   // origin (legacy default) stream

    // --- CSR build on s0; prepw forked ---
    k_init<<<(NNODES + 255) / 256, 256, 0, s0>>>();
    cudaEventRecord(g_pipe.evStart, s0);
    cudaStreamWaitEvent(g_pipe.s[0], g_pipe.evStart, 0);
    k_prepw<<<(HID * F_IN + HID * HID + 255) / 256, 256, 0, g_pipe.s[0]>>>(W1, W2);
    cudaEventRecord(g_pipe.evPrep, g_pipe.s[0]);

    k_count  <<<(NEDGES + 255) / 256, 256, 0, s0>>>(ei);
    k_offsets<<<(NNODES + 255) / 256, 256, 0, s0>>>();
    k_scatter<<<(NEDGES + 255) / 256, 256, 0, s0>>>(ei);

    // --- stage 1: agg_x segments on s0, gemm1 per-segment forked ---
    for (int i = 0; i < NSEG; i++) {
        const int nb = SEGT * 128 * i;
        const int ne = (i == NSEG - 1) ? NNODES : SEGT * 128 * (i + 1);
        const int tiles = (i == NSEG - 1) ? (MTILES - SEGT * (NSEG - 1)) : SEGT;
        k_agg_x<<<(ne - nb + 7) / 8, 256, 0, s0>>>(x, nb, ne);
        cudaEventRecord(g_pipe.evAx[i], s0);
        cudaStreamWaitEvent(g_pipe.s[i], g_pipe.evAx[i], 0);
        if (i > 0) cudaStreamWaitEvent(g_pipe.s[i], g_pipe.evPrep, 0);
        k_gemm1<<<tiles, 256, GEMM_SMEM, g_pipe.s[i]>>>(b1, SEGT * i);
        cudaEventRecord(g_pipe.evG1[i], g_pipe.s[i]);
    }
    // join: agg_h1 gathers arbitrary h1 rows -> needs all gemm1 segments
    for (int i = 0; i < NSEG; i++) cudaStreamWaitEvent(s0, g_pipe.evG1[i], 0);

    // --- stage 2: agg_h1 segments on s0, gemm2+cls per-segment forked ---
    for (int i = 0; i < NSEG; i++) {
        const int nb = SEGT * 128 * i;
        const int ne = (i == NSEG - 1) ? NNODES : SEGT * 128 * (i + 1);
        const int tiles = (i == NSEG - 1) ? (MTILES - SEGT * (NSEG - 1)) : SEGT;
        k_agg_h1<<<(ne - nb + 7) / 8, 256, 0, s0>>>(nb, ne);
        cudaEventRecord(g_pipe.evAh[i], s0);
        cudaStreamWaitEvent(g_pipe.s[i], g_pipe.evAh[i], 0);
        k_gemm2<<<tiles, 256, GEMM_SMEM, g_pipe.s[i]>>>(b2, SEGT * i);
        k_cls<<<tiles, 256, 0, g_pipe.s[i]>>>(Wc, bc, out, SEGT * i);
        cudaEventRecord(g_pipe.evC[i], g_pipe.s[i]);
    }
    // join everything back into the origin stream
    for (int i = 0; i < NSEG; i++) cudaStreamWaitEvent(s0, g_pipe.evC[i], 0);
}

// round 9
// speedup vs baseline: 1.0816x; 1.0816x over previous
#include <cuda_runtime.h>
#include <cuda_bf16.h>
#include <cstdint>

#define NNODES 50000
#define NODPAD 50048
#define NEDGES 800000
#define F_IN   128
#define HID    256
#define NOUT   40
#define MTILES (NODPAD / 128)   // 391

// ---------------- scratch (static device memory, no allocations) ------------
__device__ int   g_cnt[NNODES];
__device__ int   g_off[NNODES];
__device__ int   g_cur[NNODES];
__device__ int   g_total;
__device__ float g_dinv[NNODES];
__device__ __align__(8) int2 g_edge[NEDGES];   // (src, weight bits)
__device__ __align__(16) __nv_bfloat16 g_ax_hi[(size_t)NODPAD * F_IN];
__device__ __align__(16) __nv_bfloat16 g_ax_lo[(size_t)NODPAD * F_IN];
__device__ __align__(16) __nv_bfloat16 g_a1_hi[(size_t)NODPAD * HID];
__device__ __align__(16) __nv_bfloat16 g_a1_lo[(size_t)NODPAD * HID];
__device__ __align__(16) float g_h1[(size_t)NNODES * HID];
__device__ __align__(16) float g_h2[(size_t)NNODES * HID];
__device__ __align__(16) __nv_bfloat16 g_w1hi[HID * F_IN];
__device__ __align__(16) __nv_bfloat16 g_w1lo[HID * F_IN];
__device__ __align__(16) __nv_bfloat16 g_w2hi[HID * HID];
__device__ __align__(16) __nv_bfloat16 g_w2lo[HID * HID];

// ---------------- helpers ------------------------------------------------------
__device__ __forceinline__ void split1(float v, __nv_bfloat16& h, __nv_bfloat16& l) {
    h = __float2bfloat16(v);
    l = __float2bfloat16(v - __bfloat162float(h));
}

__device__ __forceinline__ void split4(float4 a, uint2& hi, uint2& lo) {
    __nv_bfloat16 h0, h1, h2, h3, l0, l1, l2, l3;
    split1(a.x, h0, l0); split1(a.y, h1, l1);
    split1(a.z, h2, l2); split1(a.w, h3, l3);
    __nv_bfloat162 hp0 = __halves2bfloat162(h0, h1);
    __nv_bfloat162 hp1 = __halves2bfloat162(h2, h3);
    __nv_bfloat162 lp0 = __halves2bfloat162(l0, l1);
    __nv_bfloat162 lp1 = __halves2bfloat162(l2, l3);
    hi.x = *(uint32_t*)&hp0; hi.y = *(uint32_t*)&hp1;
    lo.x = *(uint32_t*)&lp0; lo.y = *(uint32_t*)&lp1;
}

// ---------------- graph preprocessing ---------------------------------------
__global__ void k_init()
{
    int i = blockIdx.x * blockDim.x + threadIdx.x;
    if (i < NNODES) { g_cnt[i] = 0; g_cur[i] = 0; }
    if (i == 0) g_total = 0;
}

__global__ void k_count(const int* __restrict__ ei)
{
    int e = blockIdx.x * blockDim.x + threadIdx.x;
    if (e < NEDGES) atomicAdd(&g_cnt[ei[NEDGES + e]], 1);
}

__global__ void k_offsets()
{
    int i = blockIdx.x * blockDim.x + threadIdx.x;
    if (i >= NNODES) return;
    int c = g_cnt[i];
    g_off[i]  = atomicAdd(&g_total, c);
    g_dinv[i] = rsqrtf((float)(c + 1));
}

// two edges per thread for doubled MLP (latency-bound kernel)
__global__ void k_scatter(const int* __restrict__ ei)
{
    int e = (blockIdx.x * blockDim.x + threadIdx.x) * 2;
    if (e >= NEDGES) return;
    int s0 = ei[e],          d0 = ei[NEDGES + e];
    float w0 = g_dinv[s0] * g_dinv[d0];
    int p0 = g_off[d0] + atomicAdd(&g_cur[d0], 1);
    if (e + 1 < NEDGES) {
        int s1 = ei[e + 1], d1 = ei[NEDGES + e + 1];
        float w1 = g_dinv[s1] * g_dinv[d1];
        int p1 = g_off[d1] + atomicAdd(&g_cur[d1], 1);
        g_edge[p0] = make_int2(s0, __float_as_int(w0));
        g_edge[p1] = make_int2(s1, __float_as_int(w1));
    } else {
        g_edge[p0] = make_int2(s0, __float_as_int(w0));
    }
}

__global__ void k_prepw(const float* __restrict__ W1, const float* __restrict__ W2)
{
    int i = blockIdx.x * blockDim.x + threadIdx.x;
    if (i < HID * F_IN) {
        int n = i / F_IN, k = i % F_IN;
        split1(W1[k * HID + n], g_w1hi[i], g_w1lo[i]);
    }
    int j = i - HID * F_IN;
    if (j >= 0 && j < HID * HID) {
        int n = j / HID, k = j % HID;
        split1(W2[k * HID + n], g_w2hi[j], g_w2lo[j]);
    }
}

// ---------------- sparse aggregation: warp per destination node --------------
template <int F>
__device__ __forceinline__ void agg_impl(const float* __restrict__ in,
                                         __nv_bfloat16* __restrict__ ohi,
                                         __nv_bfloat16* __restrict__ olo)
{
    const int warp = (blockIdx.x * blockDim.x + threadIdx.x) >> 5;
    const int lane = threadIdx.x & 31;
    if (warp >= NNODES) return;

    constexpr int V = F / 128;
    float4 acc[V];

    const float dn = g_dinv[warp];
    const float w0 = dn * dn;
    const float4* selfrow = (const float4*)(in + (size_t)warp * F);
    #pragma unroll
    for (int v = 0; v < V; v++) {
        float4 t = __ldg(&selfrow[lane + 32 * v]);
        acc[v].x = w0 * t.x; acc[v].y = w0 * t.y;
        acc[v].z = w0 * t.z; acc[v].w = w0 * t.w;
    }

    const int beg = g_off[warp];
    const int end = beg + g_cnt[warp];
    int i = beg;
    for (; i + 2 <= end; i += 2) {
        const int2 e0 = g_edge[i];
        const int2 e1 = g_edge[i + 1];
        const float4* r0 = (const float4*)(in + (size_t)e0.x * F);
        const float4* r1 = (const float4*)(in + (size_t)e1.x * F);
        const float we0 = __int_as_float(e0.y);
        const float we1 = __int_as_float(e1.y);
        #pragma unroll
        for (int v = 0; v < V; v++) {
            float4 t0 = __ldg(&r0[lane + 32 * v]);
            float4 t1 = __ldg(&r1[lane + 32 * v]);
            acc[v].x += we0 * t0.x; acc[v].y += we0 * t0.y;
            acc[v].z += we0 * t0.z; acc[v].w += we0 * t0.w;
            acc[v].x += we1 * t1.x; acc[v].y += we1 * t1.y;
            acc[v].z += we1 * t1.z; acc[v].w += we1 * t1.w;
        }
    }
    if (i < end) {
        const int2 e0 = g_edge[i];
        const float4* r0 = (const float4*)(in + (size_t)e0.x * F);
        const float we0 = __int_as_float(e0.y);
        #pragma unroll
        for (int v = 0; v < V; v++) {
            float4 t0 = __ldg(&r0[lane + 32 * v]);
            acc[v].x += we0 * t0.x; acc[v].y += we0 * t0.y;
            acc[v].z += we0 * t0.z; acc[v].w += we0 * t0.w;
        }
    }

    #pragma unroll
    for (int v = 0; v < V; v++) {
        size_t o = (size_t)warp * F + 4 * (lane + 32 * v);
        uint2 hi, lo;
        split4(acc[v], hi, lo);
        *(uint2*)(ohi + o) = hi;
        *(uint2*)(olo + o) = lo;
    }
}

__global__ void k_agg_x(const float* __restrict__ x) { agg_impl<F_IN>(x, g_ax_hi, g_ax_lo); }
__global__ void k_agg_h1()                           { agg_impl<HID>(g_h1, g_a1_hi, g_a1_lo); }

// ---------------- HMMA bf16 GEMM: C = relu(A' @ B'^T + bias) -----------------
// Virtual K' = 3F, A' = [hi|lo|hi], B' = [hi|hi|lo] -> AhBh + AlBh + AhBl.
// Block 128x128, 8 warps of 64x32. 3-stage cp.async pipeline, ONE sync/iter,
// 2 blocks/SM for cross-block latency hiding.
#define SROWB 80
#define T_STG (128 * SROWB)                  // 10240 B per operand stage
#define GEMM_SMEM (6 * T_STG)                // 61440 B: 3 stages x (A+B)

template <int F>
__device__ __forceinline__ void gemm_body(const __nv_bfloat16* __restrict__ Ahi,
                                          const __nv_bfloat16* __restrict__ Alo,
                                          const __nv_bfloat16* __restrict__ Bhi,
                                          const __nv_bfloat16* __restrict__ Blo,
                                          const float* __restrict__ bias,
                                          float* __restrict__ C)
{
    extern __shared__ __align__(16) uint8_t smem_dyn[];
    uint32_t sA;
    asm("{ .reg .u64 t; cvta.to.shared.u64 t, %1; cvt.u32.u64 %0, t; }"
        : "=r"(sA) : "l"(&smem_dyn[0]));
    const uint32_t sB = sA + 3 * T_STG;

    const int tid  = threadIdx.x;
    const int lane = tid & 31;
    const int wid  = tid >> 5;
    const int g    = lane >> 2;
    const int tg   = lane & 3;
    const int wm   = (wid & 1) * 64;
    const int wn   = (wid >> 1) * 32;
    const int brow = blockIdx.y * 128;
    const int bcol = blockIdx.x * 128;

    float acc[4][4][4];
    #pragma unroll
    for (int mi = 0; mi < 4; mi++)
        #pragma unroll
        for (int ni = 0; ni < 4; ni++)
            #pragma unroll
            for (int c = 0; c < 4; c++) acc[mi][ni][c] = 0.f;

    const int lrow = tid >> 2;       // 0..63
    const int lseg = tid & 3;
    auto load_stage = [&](int st, int k0) {
        const int seg = k0 / F;
        const int kk0 = k0 - seg * F;
        const __nv_bfloat16* a_src = (seg == 1) ? Alo : Ahi;
        const __nv_bfloat16* b_src = (seg == 2) ? Blo : Bhi;
        #pragma unroll
        for (int i = 0; i < 2; i++) {
            int row = lrow + i * 64;
            uint32_t soA = sA + (uint32_t)st * T_STG + row * SROWB + lseg * 16;
            const __nv_bfloat16* ga = a_src + (size_t)(brow + row) * F + kk0 + lseg * 8;
            asm volatile("cp.async.cg.shared.global [%0], [%1], 16;"
                         :: "r"(soA), "l"(ga));
            uint32_t soB = sB + (uint32_t)st * T_STG + row * SROWB + lseg * 16;
            const __nv_bfloat16* gb = b_src + (size_t)(bcol + row) * F + kk0 + lseg * 8;
            asm volatile("cp.async.cg.shared.global [%0], [%1], 16;"
                         :: "r"(soB), "l"(gb));
        }
        asm volatile("cp.async.commit_group;");
    };

    constexpr int NK = 3 * F / 32;
    load_stage(0, 0);
    load_stage(1, 32);

    const int lr  = lane & 15;
    const int lhi = (lane >> 4) * 16;

    int st = 0;                         // stage index = ki % 3
    for (int ki = 0; ki < NK; ki++) {
        asm volatile("cp.async.wait_group 1;");   // stage ki complete
        __syncthreads();                          // data ready + (ki-1) consumed
        if (ki + 2 < NK) {
            int st2 = st + 2; if (st2 >= 3) st2 -= 3;
            load_stage(st2, (ki + 2) * 32);       // overwrites stage ki-1 buffer
        }

        const uint32_t bufA = sA + st * T_STG;
        const uint32_t bufB = sB + st * T_STG;

        #pragma unroll
        for (int kk = 0; kk < 2; kk++) {
            const uint32_t kb = kk * 32;
            uint32_t af[4][4];
            #pragma unroll
            for (int mi = 0; mi < 4; mi++) {
                uint32_t addr = bufA + (wm + mi * 16 + lr) * SROWB + kb + lhi;
                asm volatile("ldmatrix.sync.aligned.m8n8.x4.shared.b16 {%0,%1,%2,%3}, [%4];"
                             : "=r"(af[mi][0]), "=r"(af[mi][1]),
                               "=r"(af[mi][2]), "=r"(af[mi][3]) : "r"(addr));
            }
            #pragma unroll
            for (int p = 0; p < 2; p++) {
                uint32_t r0, r1, r2, r3;
                uint32_t addr = bufB + (wn + p * 16 + lr) * SROWB + kb + lhi;
                asm volatile("ldmatrix.sync.aligned.m8n8.x4.shared.b16 {%0,%1,%2,%3}, [%4];"
                             : "=r"(r0), "=r"(r1), "=r"(r2), "=r"(r3) : "r"(addr));
                #pragma unroll
                for (int mi = 0; mi < 4; mi++) {
                    asm volatile(
                        "mma.sync.aligned.m16n8k16.row.col.f32.bf16.bf16.f32 "
                        "{%0,%1,%2,%3},{%4,%5,%6,%7},{%8,%9},{%0,%1,%2,%3};"
                        : "+f"(acc[mi][2 * p][0]), "+f"(acc[mi][2 * p][1]),
                          "+f"(acc[mi][2 * p][2]), "+f"(acc[mi][2 * p][3])
                        : "r"(af[mi][0]), "r"(af[mi][1]), "r"(af[mi][2]), "r"(af[mi][3]),
                          "r"(r0), "r"(r2));
                    asm volatile(
                        "mma.sync.aligned.m16n8k16.row.col.f32.bf16.bf16.f32 "
                        "{%0,%1,%2,%3},{%4,%5,%6,%7},{%8,%9},{%0,%1,%2,%3};"
                        : "+f"(acc[mi][2 * p + 1][0]), "+f"(acc[mi][2 * p + 1][1]),
                          "+f"(acc[mi][2 * p + 1][2]), "+f"(acc[mi][2 * p + 1][3])
                        : "r"(af[mi][0]), "r"(af[mi][1]), "r"(af[mi][2]), "r"(af[mi][3]),
                          "r"(r1), "r"(r3));
                }
            }
        }
        if (++st == 3) st = 0;
    }

    // ---- epilogue: bias + relu ----
    #pragma unroll
    for (int ni = 0; ni < 4; ni++) {
        const int col = bcol + wn + ni * 8 + tg * 2;
        const float b0 = __ldg(bias + col);
        const float b1 = __ldg(bias + col + 1);
        #pragma unroll
        for (int mi = 0; mi < 4; mi++) {
            int r0 = brow + wm + mi * 16 + g;
            if (r0 < NNODES) {
                float2 o;
                o.x = fmaxf(acc[mi][ni][0] + b0, 0.f);
                o.y = fmaxf(acc[mi][ni][1] + b1, 0.f);
                *(float2*)(C + (size_t)r0 * HID + col) = o;
            }
            int r1 = r0 + 8;
            if (r1 < NNODES) {
                float2 o;
                o.x = fmaxf(acc[mi][ni][2] + b0, 0.f);
                o.y = fmaxf(acc[mi][ni][3] + b1, 0.f);
                *(float2*)(C + (size_t)r1 * HID + col) = o;
            }
        }
    }
}

__global__ void __launch_bounds__(256, 2) k_gemm1(const float* __restrict__ b1)
{
    gemm_body<F_IN>(g_ax_hi, g_ax_lo, g_w1hi, g_w1lo, b1, g_h1);
}
__global__ void __launch_bounds__(256, 2) k_gemm2(const float* __restrict__ b2)
{
    gemm_body<HID>(g_a1_hi, g_a1_lo, g_w2hi, g_w2lo, b2, g_h2);
}

// ---------------- classifier: out[Nx40] = h2[Nx256] @ Wc[256x40] + bc --------
__global__ void __launch_bounds__(256) k_cls(const float* __restrict__ Wc,
                                             const float* __restrict__ bc,
                                             float* __restrict__ out)
{
    __shared__ float Ws[HID * NOUT];
    const int tid = threadIdx.x;
    for (int i = tid; i < HID * NOUT; i += 256) Ws[i] = Wc[i];
    __syncthreads();

    const int s  = tid >> 2;
    const int cg = (tid & 3) * 10;
    const int r0 = blockIdx.x * 128 + s;
    const int r1 = r0 + 64;
    const bool v0 = r0 < NNODES;
    const bool v1 = r1 < NNODES;
    if (!v0) return;

    const float* h0 = g_h2 + (size_t)r0 * HID;
    const float* h1 = g_h2 + (size_t)(v1 ? r1 : r0) * HID;

    unsigned long long acc0[5] = {0, 0, 0, 0, 0};
    unsigned long long acc1[5] = {0, 0, 0, 0, 0};

    #pragma unroll 2
    for (int k = 0; k < HID; k += 4) {
        float4 a0 = *(const float4*)(h0 + k);
        float4 a1 = *(const float4*)(h1 + k);
        const float av0[4] = {a0.x, a0.y, a0.z, a0.w};
        const float av1[4] = {a1.x, a1.y, a1.z, a1.w};
        #pragma unroll
        for (int kk = 0; kk < 4; kk++) {
            unsigned long long hb0, hb1;
            asm("mov.b64 %0, {%1, %1};" : "=l"(hb0) : "r"(__float_as_uint(av0[kk])));
            asm("mov.b64 %0, {%1, %1};" : "=l"(hb1) : "r"(__float_as_uint(av1[kk])));
            const float* wrow = Ws + (k + kk) * NOUT + cg;
            #pragma unroll
            for (int j = 0; j < 5; j++) {
                unsigned long long w = *(const unsigned long long*)(wrow + 2 * j);
                asm("fma.rn.f32x2 %0, %1, %2, %0;" : "+l"(acc0[j]) : "l"(hb0), "l"(w));
                asm("fma.rn.f32x2 %0, %1, %2, %0;" : "+l"(acc1[j]) : "l"(hb1), "l"(w));
            }
        }
    }

    #pragma unroll
    for (int j = 0; j < 5; j++) {
        uint32_t lo, hi;
        float bcl = __ldg(bc + cg + 2 * j);
        float bch = __ldg(bc + cg + 2 * j + 1);
        asm("mov.b64 {%0, %1}, %2;" : "=r"(lo), "=r"(hi) : "l"(acc0[j]));
        out[(size_t)r0 * NOUT + cg + 2 * j]     = __uint_as_float(lo) + bcl;
        out[(size_t)r0 * NOUT + cg + 2 * j + 1] = __uint_as_float(hi) + bch;
        if (v1) {
            asm("mov.b64 {%0, %1}, %2;" : "=r"(lo), "=r"(hi) : "l"(acc1[j]));
            out[(size_t)r1 * NOUT + cg + 2 * j]     = __uint_as_float(lo) + bcl;
            out[(size_t)r1 * NOUT + cg + 2 * j + 1] = __uint_as_float(hi) + bch;
        }
    }
}

// ---------------- launch ------------------------------------------------------
extern "C" void kernel_launch(void* const* d_in, const int* in_sizes, int n_in,
                              void* d_out, int out_size)
{
    const float* x   = (const float*)d_in[0];
    const float* W1  = (const float*)d_in[1];
    const float* b1  = (const float*)d_in[2];
    const float* W2  = (const float*)d_in[3];
    const float* b2  = (const float*)d_in[4];
    const float* Wc  = (const float*)d_in[5];
    const float* bc  = (const float*)d_in[6];
    const int*   ei  = (const int*)  d_in[7];
    float*       out = (float*)d_out;

    cudaFuncSetAttribute(k_gemm1, cudaFuncAttributeMaxDynamicSharedMemorySize, GEMM_SMEM);
    cudaFuncSetAttribute(k_gemm2, cudaFuncAttributeMaxDynamicSharedMemorySize, GEMM_SMEM);

    // --- CSR build (scan-free offsets) ---
    k_init   <<<(NNODES + 255) / 256, 256>>>();
    k_count  <<<(NEDGES + 255) / 256, 256>>>(ei);
    k_offsets<<<(NNODES + 255) / 256, 256>>>();
    k_scatter<<<(NEDGES / 2 + 255) / 256, 256>>>(ei);

    // --- weight transpose + bf16 split ---
    k_prepw<<<(HID * F_IN + HID * HID + 255) / 256, 256>>>(W1, W2);

    const int aggBlocks = (NNODES * 32 + 255) / 256;
    dim3 gemmGrid(HID / 128, MTILES);

    // --- layer 1: relu(agg(x) @ W1 + b1) ---
    k_agg_x<<<aggBlocks, 256>>>(x);
    k_gemm1<<<gemmGrid, 256, GEMM_SMEM>>>(b1);

    // --- layer 2: relu(agg(h1) @ W2 + b2) ---
    k_agg_h1<<<aggBlocks, 256>>>();
    k_gemm2<<<gemmGrid, 256, GEMM_SMEM>>>(b2);

    // --- classifier ---
    k_cls<<<MTILES, 256>>>(Wc, bc, out);
}

// round 10
// speedup vs baseline: 1.1229x; 1.0383x over previous
#include <cuda_runtime.h>
#include <cuda_bf16.h>
#include <cuda_fp16.h>
#include <cstdint>

#define NNODES 50000
#define NODPAD 50048
#define NEDGES 800000
#define F_IN   128
#define HID    256
#define NOUT   40
#define MTILES (NODPAD / 128)   // 391

// ---------------- scratch (static device memory, no allocations) ------------
__device__ int   g_cnt[NNODES];
__device__ int   g_off[NNODES];
__device__ int   g_cur[NNODES];
__device__ int   g_total;
__device__ float g_dinv[NNODES];
__device__ int   g_esrc[NEDGES];                  // CSR src only (4B/edge)
__device__ __align__(16) __half g_xh[(size_t)NNODES * F_IN];    // fp16 copy of x
__device__ __align__(16) __half g_h1h[(size_t)NNODES * HID];    // fp16 h1
__device__ __align__(16) __nv_bfloat16 g_ax_hi[(size_t)NODPAD * F_IN];
__device__ __align__(16) __nv_bfloat16 g_ax_lo[(size_t)NODPAD * F_IN];
__device__ __align__(16) __nv_bfloat16 g_a1_hi[(size_t)NODPAD * HID];
__device__ __align__(16) __nv_bfloat16 g_a1_lo[(size_t)NODPAD * HID];
__device__ __align__(16) float g_h2[(size_t)NNODES * HID];
__device__ __align__(16) __nv_bfloat16 g_w1hi[HID * F_IN];
__device__ __align__(16) __nv_bfloat16 g_w1lo[HID * F_IN];
__device__ __align__(16) __nv_bfloat16 g_w2hi[HID * HID];
__device__ __align__(16) __nv_bfloat16 g_w2lo[HID * HID];

// ---------------- helpers ------------------------------------------------------
__device__ __forceinline__ void split1(float v, __nv_bfloat16& h, __nv_bfloat16& l) {
    h = __float2bfloat16(v);
    l = __float2bfloat16(v - __bfloat162float(h));
}

__device__ __forceinline__ void split4(float4 a, uint2& hi, uint2& lo) {
    __nv_bfloat16 h0, h1, h2, h3, l0, l1, l2, l3;
    split1(a.x, h0, l0); split1(a.y, h1, l1);
    split1(a.z, h2, l2); split1(a.w, h3, l3);
    __nv_bfloat162 hp0 = __halves2bfloat162(h0, h1);
    __nv_bfloat162 hp1 = __halves2bfloat162(h2, h3);
    __nv_bfloat162 lp0 = __halves2bfloat162(l0, l1);
    __nv_bfloat162 lp1 = __halves2bfloat162(l2, l3);
    hi.x = *(uint32_t*)&hp0; hi.y = *(uint32_t*)&hp1;
    lo.x = *(uint32_t*)&lp0; lo.y = *(uint32_t*)&lp1;
}

// ---------------- graph preprocessing ---------------------------------------
__global__ void k_init()
{
    int i = blockIdx.x * blockDim.x + threadIdx.x;
    if (i < NNODES) g_cnt[i] = 0;
    if (i == 0) g_total = 0;
}

__global__ void k_count(const int* __restrict__ ei)
{
    int e = blockIdx.x * blockDim.x + threadIdx.x;
    if (e < NEDGES) atomicAdd(&g_cnt[ei[NEDGES + e]], 1);
}

__global__ void k_offsets()
{
    int i = blockIdx.x * blockDim.x + threadIdx.x;
    if (i >= NNODES) return;
    int c = g_cnt[i];
    int off = atomicAdd(&g_total, c);
    g_off[i]  = off;
    g_cur[i]  = off;                       // scatter cursor starts at offset
    g_dinv[i] = rsqrtf((float)(c + 1));
}

// single atomic per edge; weight recomputed in agg
__global__ void k_scatter(const int* __restrict__ ei)
{
    int e = blockIdx.x * blockDim.x + threadIdx.x;
    if (e >= NEDGES) return;
    int s = ei[e];
    int d = ei[NEDGES + e];
    int pos = atomicAdd(&g_cur[d], 1);
    g_esrc[pos] = s;
}

__global__ void k_prepw(const float* __restrict__ W1, const float* __restrict__ W2)
{
    int i = blockIdx.x * blockDim.x + threadIdx.x;
    if (i < HID * F_IN) {
        int n = i / F_IN, k = i % F_IN;
        split1(W1[k * HID + n], g_w1hi[i], g_w1lo[i]);
    }
    int j = i - HID * F_IN;
    if (j >= 0 && j < HID * HID) {
        int n = j / HID, k = j % HID;
        split1(W2[k * HID + n], g_w2hi[j], g_w2lo[j]);
    }
}

// convert x to fp16 (4 elems / thread)
__global__ void k_prepx(const float* __restrict__ x)
{
    int i = blockIdx.x * blockDim.x + threadIdx.x;
    if (i >= NNODES * F_IN / 4) return;
    float4 v = ((const float4*)x)[i];
    __half2 a = __floats2half2_rn(v.x, v.y);
    __half2 b = __floats2half2_rn(v.z, v.w);
    uint2 u;
    u.x = *(uint32_t*)&a; u.y = *(uint32_t*)&b;
    ((uint2*)g_xh)[i] = u;
}

// ---------------- sparse aggregation: warp per destination node --------------
// gathers fp16 rows, accumulates fp32, emits bf16 hi/lo split
template <int F>
__device__ __forceinline__ void agg_impl(const __half* __restrict__ in,
                                         __nv_bfloat16* __restrict__ ohi,
                                         __nv_bfloat16* __restrict__ olo)
{
    const int warp = (blockIdx.x * blockDim.x + threadIdx.x) >> 5;
    const int lane = threadIdx.x & 31;
    if (warp >= NNODES) return;

    constexpr int V = F / 128;          // uint2 (4 halves) chunks per lane
    float4 acc[V];

    const float dn = g_dinv[warp];
    const float w0 = dn * dn;
    const uint2* selfrow = (const uint2*)(in + (size_t)warp * F);
    #pragma unroll
    for (int v = 0; v < V; v++) {
        uint2 u = __ldg(&selfrow[lane + 32 * v]);
        float2 f0 = __half22float2(*(const __half2*)&u.x);
        float2 f1 = __half22float2(*(const __half2*)&u.y);
        acc[v].x = w0 * f0.x; acc[v].y = w0 * f0.y;
        acc[v].z = w0 * f1.x; acc[v].w = w0 * f1.y;
    }

    const int beg = g_off[warp];
    const int end = beg + g_cnt[warp];
    int i = beg;
    for (; i + 2 <= end; i += 2) {
        const int s0 = g_esrc[i];
        const int s1 = g_esrc[i + 1];
        const float we0 = g_dinv[s0] * dn;
        const float we1 = g_dinv[s1] * dn;
        const uint2* r0 = (const uint2*)(in + (size_t)s0 * F);
        const uint2* r1 = (const uint2*)(in + (size_t)s1 * F);
        #pragma unroll
        for (int v = 0; v < V; v++) {
            uint2 u0 = __ldg(&r0[lane + 32 * v]);
            uint2 u1 = __ldg(&r1[lane + 32 * v]);
            float2 a0 = __half22float2(*(const __half2*)&u0.x);
            float2 a1 = __half22float2(*(const __half2*)&u0.y);
            float2 b0 = __half22float2(*(const __half2*)&u1.x);
            float2 b1 = __half22float2(*(const __half2*)&u1.y);
            acc[v].x += we0 * a0.x; acc[v].y += we0 * a0.y;
            acc[v].z += we0 * a1.x; acc[v].w += we0 * a1.y;
            acc[v].x += we1 * b0.x; acc[v].y += we1 * b0.y;
            acc[v].z += we1 * b1.x; acc[v].w += we1 * b1.y;
        }
    }
    if (i < end) {
        const int s0 = g_esrc[i];
        const float we0 = g_dinv[s0] * dn;
        const uint2* r0 = (const uint2*)(in + (size_t)s0 * F);
        #pragma unroll
        for (int v = 0; v < V; v++) {
            uint2 u0 = __ldg(&r0[lane + 32 * v]);
            float2 a0 = __half22float2(*(const __half2*)&u0.x);
            float2 a1 = __half22float2(*(const __half2*)&u0.y);
            acc[v].x += we0 * a0.x; acc[v].y += we0 * a0.y;
            acc[v].z += we0 * a1.x; acc[v].w += we0 * a1.y;
        }
    }

    #pragma unroll
    for (int v = 0; v < V; v++) {
        size_t o = (size_t)warp * F + 4 * (lane + 32 * v);
        uint2 hi, lo;
        split4(acc[v], hi, lo);
        *(uint2*)(ohi + o) = hi;
        *(uint2*)(olo + o) = lo;
    }
}

__global__ void k_agg_x()  { agg_impl<F_IN>(g_xh,  g_ax_hi, g_ax_lo); }
__global__ void k_agg_h1() { agg_impl<HID>(g_h1h, g_a1_hi, g_a1_lo); }

// ---------------- HMMA bf16 GEMM: C = relu(A' @ B'^T + bias) -----------------
// Virtual K' = 3F, A' = [hi|lo|hi], B' = [hi|hi|lo] -> AhBh + AlBh + AhBl.
// Block 128x128, 8 warps of 64x32. 3-stage cp.async pipeline, ONE sync/iter,
// 2 blocks/SM. OutT selects fp16 (h1) or fp32 (h2) output.
#define SROWB 80
#define T_STG (128 * SROWB)
#define GEMM_SMEM (6 * T_STG)                // 61440 B

template <int F, typename OutT>
__device__ __forceinline__ void gemm_body(const __nv_bfloat16* __restrict__ Ahi,
                                          const __nv_bfloat16* __restrict__ Alo,
                                          const __nv_bfloat16* __restrict__ Bhi,
                                          const __nv_bfloat16* __restrict__ Blo,
                                          const float* __restrict__ bias,
                                          OutT* __restrict__ C)
{
    extern __shared__ __align__(16) uint8_t smem_dyn[];
    uint32_t sA;
    asm("{ .reg .u64 t; cvta.to.shared.u64 t, %1; cvt.u32.u64 %0, t; }"
        : "=r"(sA) : "l"(&smem_dyn[0]));
    const uint32_t sB = sA + 3 * T_STG;

    const int tid  = threadIdx.x;
    const int lane = tid & 31;
    const int wid  = tid >> 5;
    const int g    = lane >> 2;
    const int tg   = lane & 3;
    const int wm   = (wid & 1) * 64;
    const int wn   = (wid >> 1) * 32;
    const int brow = blockIdx.y * 128;
    const int bcol = blockIdx.x * 128;

    float acc[4][4][4];
    #pragma unroll
    for (int mi = 0; mi < 4; mi++)
        #pragma unroll
        for (int ni = 0; ni < 4; ni++)
            #pragma unroll
            for (int c = 0; c < 4; c++) acc[mi][ni][c] = 0.f;

    const int lrow = tid >> 2;
    const int lseg = tid & 3;
    auto load_stage = [&](int st, int k0) {
        const int seg = k0 / F;
        const int kk0 = k0 - seg * F;
        const __nv_bfloat16* a_src = (seg == 1) ? Alo : Ahi;
        const __nv_bfloat16* b_src = (seg == 2) ? Blo : Bhi;
        #pragma unroll
        for (int i = 0; i < 2; i++) {
            int row = lrow + i * 64;
            uint32_t soA = sA + (uint32_t)st * T_STG + row * SROWB + lseg * 16;
            const __nv_bfloat16* ga = a_src + (size_t)(brow + row) * F + kk0 + lseg * 8;
            asm volatile("cp.async.cg.shared.global [%0], [%1], 16;"
                         :: "r"(soA), "l"(ga));
            uint32_t soB = sB + (uint32_t)st * T_STG + row * SROWB + lseg * 16;
            const __nv_bfloat16* gb = b_src + (size_t)(bcol + row) * F + kk0 + lseg * 8;
            asm volatile("cp.async.cg.shared.global [%0], [%1], 16;"
                         :: "r"(soB), "l"(gb));
        }
        asm volatile("cp.async.commit_group;");
    };

    constexpr int NK = 3 * F / 32;
    load_stage(0, 0);
    load_stage(1, 32);

    const int lr  = lane & 15;
    const int lhi = (lane >> 4) * 16;

    int st = 0;
    for (int ki = 0; ki < NK; ki++) {
        asm volatile("cp.async.wait_group 1;");
        __syncthreads();
        if (ki + 2 < NK) {
            int st2 = st + 2; if (st2 >= 3) st2 -= 3;
            load_stage(st2, (ki + 2) * 32);
        }

        const uint32_t bufA = sA + st * T_STG;
        const uint32_t bufB = sB + st * T_STG;

        #pragma unroll
        for (int kk = 0; kk < 2; kk++) {
            const uint32_t kb = kk * 32;
            uint32_t af[4][4];
            #pragma unroll
            for (int mi = 0; mi < 4; mi++) {
                uint32_t addr = bufA + (wm + mi * 16 + lr) * SROWB + kb + lhi;
                asm volatile("ldmatrix.sync.aligned.m8n8.x4.shared.b16 {%0,%1,%2,%3}, [%4];"
                             : "=r"(af[mi][0]), "=r"(af[mi][1]),
                               "=r"(af[mi][2]), "=r"(af[mi][3]) : "r"(addr));
            }
            #pragma unroll
            for (int p = 0; p < 2; p++) {
                uint32_t r0, r1, r2, r3;
                uint32_t addr = bufB + (wn + p * 16 + lr) * SROWB + kb + lhi;
                asm volatile("ldmatrix.sync.aligned.m8n8.x4.shared.b16 {%0,%1,%2,%3}, [%4];"
                             : "=r"(r0), "=r"(r1), "=r"(r2), "=r"(r3) : "r"(addr));
                #pragma unroll
                for (int mi = 0; mi < 4; mi++) {
                    asm volatile(
                        "mma.sync.aligned.m16n8k16.row.col.f32.bf16.bf16.f32 "
                        "{%0,%1,%2,%3},{%4,%5,%6,%7},{%8,%9},{%0,%1,%2,%3};"
                        : "+f"(acc[mi][2 * p][0]), "+f"(acc[mi][2 * p][1]),
                          "+f"(acc[mi][2 * p][2]), "+f"(acc[mi][2 * p][3])
                        : "r"(af[mi][0]), "r"(af[mi][1]), "r"(af[mi][2]), "r"(af[mi][3]),
                          "r"(r0), "r"(r2));
                    asm volatile(
                        "mma.sync.aligned.m16n8k16.row.col.f32.bf16.bf16.f32 "
                        "{%0,%1,%2,%3},{%4,%5,%6,%7},{%8,%9},{%0,%1,%2,%3};"
                        : "+f"(acc[mi][2 * p + 1][0]), "+f"(acc[mi][2 * p + 1][1]),
                          "+f"(acc[mi][2 * p + 1][2]), "+f"(acc[mi][2 * p + 1][3])
                        : "r"(af[mi][0]), "r"(af[mi][1]), "r"(af[mi][2]), "r"(af[mi][3]),
                          "r"(r1), "r"(r3));
                }
            }
        }
        if (++st == 3) st = 0;
    }

    // ---- epilogue: bias + relu, fp16 or fp32 store ----
    #pragma unroll
    for (int ni = 0; ni < 4; ni++) {
        const int col = bcol + wn + ni * 8 + tg * 2;
        const float b0 = __ldg(bias + col);
        const float b1 = __ldg(bias + col + 1);
        #pragma unroll
        for (int mi = 0; mi < 4; mi++) {
            int r0 = brow + wm + mi * 16 + g;
            if (r0 < NNODES) {
                float v0 = fmaxf(acc[mi][ni][0] + b0, 0.f);
                float v1 = fmaxf(acc[mi][ni][1] + b1, 0.f);
                if constexpr (sizeof(OutT) == 2) {
                    __half2 o = __floats2half2_rn(v0, v1);
                    *(__half2*)((__half*)C + (size_t)r0 * HID + col) = o;
                } else {
                    *(float2*)((float*)C + (size_t)r0 * HID + col) = make_float2(v0, v1);
                }
            }
            int r1 = r0 + 8;
            if (r1 < NNODES) {
                float v0 = fmaxf(acc[mi][ni][2] + b0, 0.f);
                float v1 = fmaxf(acc[mi][ni][3] + b1, 0.f);
                if constexpr (sizeof(OutT) == 2) {
                    __half2 o = __floats2half2_rn(v0, v1);
                    *(__half2*)((__half*)C + (size_t)r1 * HID + col) = o;
                } else {
                    *(float2*)((float*)C + (size_t)r1 * HID + col) = make_float2(v0, v1);
                }
            }
        }
    }
}

__global__ void __launch_bounds__(256, 2) k_gemm1(const float* __restrict__ b1)
{
    gemm_body<F_IN, __half>(g_ax_hi, g_ax_lo, g_w1hi, g_w1lo, b1, g_h1h);
}
__global__ void __launch_bounds__(256, 2) k_gemm2(const float* __restrict__ b2)
{
    gemm_body<HID, float>(g_a1_hi, g_a1_lo, g_w2hi, g_w2lo, b2, g_h2);
}

// ---------------- classifier: out[Nx40] = h2[Nx256] @ Wc[256x40] + bc --------
__global__ void __launch_bounds__(256) k_cls(const float* __restrict__ Wc,
                                             const float* __restrict__ bc,
                                             float* __restrict__ out)
{
    __shared__ float Ws[HID * NOUT];
    const int tid = threadIdx.x;
    for (int i = tid; i < HID * NOUT; i += 256) Ws[i] = Wc[i];
    __syncthreads();

    const int s  = tid >> 2;
    const int cg = (tid & 3) * 10;
    const int r0 = blockIdx.x * 128 + s;
    const int r1 = r0 + 64;
    const bool v0 = r0 < NNODES;
    const bool v1 = r1 < NNODES;
    if (!v0) return;

    const float* h0 = g_h2 + (size_t)r0 * HID;
    const float* h1 = g_h2 + (size_t)(v1 ? r1 : r0) * HID;

    unsigned long long acc0[5] = {0, 0, 0, 0, 0};
    unsigned long long acc1[5] = {0, 0, 0, 0, 0};

    #pragma unroll 2
    for (int k = 0; k < HID; k += 4) {
        float4 a0 = *(const float4*)(h0 + k);
        float4 a1 = *(const float4*)(h1 + k);
        const float av0[4] = {a0.x, a0.y, a0.z, a0.w};
        const float av1[4] = {a1.x, a1.y, a1.z, a1.w};
        #pragma unroll
        for (int kk = 0; kk < 4; kk++) {
            unsigned long long hb0, hb1;
            asm("mov.b64 %0, {%1, %1};" : "=l"(hb0) : "r"(__float_as_uint(av0[kk])));
            asm("mov.b64 %0, {%1, %1};" : "=l"(hb1) : "r"(__float_as_uint(av1[kk])));
            const float* wrow = Ws + (k + kk) * NOUT + cg;
            #pragma unroll
            for (int j = 0; j < 5; j++) {
                unsigned long long w = *(const unsigned long long*)(wrow + 2 * j);
                asm("fma.rn.f32x2 %0, %1, %2, %0;" : "+l"(acc0[j]) : "l"(hb0), "l"(w));
                asm("fma.rn.f32x2 %0, %1, %2, %0;" : "+l"(acc1[j]) : "l"(hb1), "l"(w));
            }
        }
    }

    #pragma unroll
    for (int j = 0; j < 5; j++) {
        uint32_t lo, hi;
        float bcl = __ldg(bc + cg + 2 * j);
        float bch = __ldg(bc + cg + 2 * j + 1);
        asm("mov.b64 {%0, %1}, %2;" : "=r"(lo), "=r"(hi) : "l"(acc0[j]));
        out[(size_t)r0 * NOUT + cg + 2 * j]     = __uint_as_float(lo) + bcl;
        out[(size_t)r0 * NOUT + cg + 2 * j + 1] = __uint_as_float(hi) + bch;
        if (v1) {
            asm("mov.b64 {%0, %1}, %2;" : "=r"(lo), "=r"(hi) : "l"(acc1[j]));
            out[(size_t)r1 * NOUT + cg + 2 * j]     = __uint_as_float(lo) + bcl;
            out[(size_t)r1 * NOUT + cg + 2 * j + 1] = __uint_as_float(hi) + bch;
        }
    }
}

// ---------------- launch ------------------------------------------------------
extern "C" void kernel_launch(void* const* d_in, const int* in_sizes, int n_in,
                              void* d_out, int out_size)
{
    const float* x   = (const float*)d_in[0];
    const float* W1  = (const float*)d_in[1];
    const float* b1  = (const float*)d_in[2];
    const float* W2  = (const float*)d_in[3];
    const float* b2  = (const float*)d_in[4];
    const float* Wc  = (const float*)d_in[5];
    const float* bc  = (const float*)d_in[6];
    const int*   ei  = (const int*)  d_in[7];
    float*       out = (float*)d_out;

    cudaFuncSetAttribute(k_gemm1, cudaFuncAttributeMaxDynamicSharedMemorySize, GEMM_SMEM);
    cudaFuncSetAttribute(k_gemm2, cudaFuncAttributeMaxDynamicSharedMemorySize, GEMM_SMEM);

    // --- CSR build (scan-free offsets, single-atomic scatter) ---
    k_init   <<<(NNODES + 255) / 256, 256>>>();
    k_count  <<<(NEDGES + 255) / 256, 256>>>(ei);
    k_offsets<<<(NNODES + 255) / 256, 256>>>();
    k_scatter<<<(NEDGES + 255) / 256, 256>>>(ei);

    // --- weight transpose/split + x fp16 conversion ---
    k_prepw<<<(HID * F_IN + HID * HID + 255) / 256, 256>>>(W1, W2);
    k_prepx<<<(NNODES * F_IN / 4 + 255) / 256, 256>>>(x);

    const int aggBlocks = (NNODES * 32 + 255) / 256;
    dim3 gemmGrid(HID / 128, MTILES);

    // --- layer 1: relu(agg(x) @ W1 + b1) -> fp16 h1 ---
    k_agg_x<<<aggBlocks, 256>>>();
    k_gemm1<<<gemmGrid, 256, GEMM_SMEM>>>(b1);

    // --- layer 2: relu(agg(h1) @ W2 + b2) -> fp32 h2 ---
    k_agg_h1<<<aggBlocks, 256>>>();
    k_gemm2<<<gemmGrid, 256, GEMM_SMEM>>>(b2);

    // --- classifier ---
    k_cls<<<MTILES, 256>>>(Wc, bc, out);
}

// round 11
// speedup vs baseline: 1.1529x; 1.0267x over previous
#include <cuda_runtime.h>
#include <cuda_bf16.h>
#include <cuda_fp16.h>
#include <cstdint>

#define NNODES 50000
#define NODPAD 50048
#define NEDGES 800000
#define F_IN   128
#define HID    256
#define NOUT   40
#define MTILES (NODPAD / 128)   // 391

// ---------------- scratch (static device memory, no allocations) ------------
__device__ int   g_cnt[NNODES];
__device__ int   g_off[NNODES];
__device__ int   g_cur[NNODES];
__device__ int   g_total;
__device__ float g_dinv[NNODES];
__device__ __align__(16) int2 g_edge[NEDGES];   // (src, weight bits)
__device__ __align__(16) __half g_xh[(size_t)NNODES * F_IN];    // fp16 copy of x
__device__ __align__(16) __half g_h1h[(size_t)NNODES * HID];    // fp16 h1
__device__ __align__(16) __nv_bfloat16 g_ax_hi[(size_t)NODPAD * F_IN];
__device__ __align__(16) __nv_bfloat16 g_ax_lo[(size_t)NODPAD * F_IN];
__device__ __align__(16) __nv_bfloat16 g_a1_hi[(size_t)NODPAD * HID];
__device__ __align__(16) __nv_bfloat16 g_a1_lo[(size_t)NODPAD * HID];
__device__ __align__(16) float g_h2[(size_t)NNODES * HID];
__device__ __align__(16) __nv_bfloat16 g_w1hi[HID * F_IN];
__device__ __align__(16) __nv_bfloat16 g_w1lo[HID * F_IN];
__device__ __align__(16) __nv_bfloat16 g_w2hi[HID * HID];
__device__ __align__(16) __nv_bfloat16 g_w2lo[HID * HID];

// ---------------- helpers ------------------------------------------------------
__device__ __forceinline__ void split1(float v, __nv_bfloat16& h, __nv_bfloat16& l) {
    h = __float2bfloat16(v);
    l = __float2bfloat16(v - __bfloat162float(h));
}

__device__ __forceinline__ void split4(float4 a, uint2& hi, uint2& lo) {
    __nv_bfloat16 h0, h1, h2, h3, l0, l1, l2, l3;
    split1(a.x, h0, l0); split1(a.y, h1, l1);
    split1(a.z, h2, l2); split1(a.w, h3, l3);
    __nv_bfloat162 hp0 = __halves2bfloat162(h0, h1);
    __nv_bfloat162 hp1 = __halves2bfloat162(h2, h3);
    __nv_bfloat162 lp0 = __halves2bfloat162(l0, l1);
    __nv_bfloat162 lp1 = __halves2bfloat162(l2, l3);
    hi.x = *(uint32_t*)&hp0; hi.y = *(uint32_t*)&hp1;
    lo.x = *(uint32_t*)&lp0; lo.y = *(uint32_t*)&lp1;
}

// ---------------- graph preprocessing ---------------------------------------
__global__ void k_init()
{
    int i = blockIdx.x * blockDim.x + threadIdx.x;
    if (i < NNODES) g_cnt[i] = 0;
    if (i == 0) g_total = 0;
}

__global__ void k_count(const int* __restrict__ ei)
{
    int e = blockIdx.x * blockDim.x + threadIdx.x;
    if (e < NEDGES) atomicAdd(&g_cnt[ei[NEDGES + e]], 1);
}

__global__ void k_offsets()
{
    int i = blockIdx.x * blockDim.x + threadIdx.x;
    if (i >= NNODES) return;
    int c = g_cnt[i];
    int off = atomicAdd(&g_total, c);
    g_off[i]  = off;
    g_cur[i]  = off;                       // scatter cursor starts at offset
    g_dinv[i] = rsqrtf((float)(c + 1));
}

// single atomic per edge; packed (src, weight) record
__global__ void k_scatter(const int* __restrict__ ei)
{
    int e = blockIdx.x * blockDim.x + threadIdx.x;
    if (e >= NEDGES) return;
    int s = ei[e];
    int d = ei[NEDGES + e];
    float w = g_dinv[s] * g_dinv[d];
    int pos = atomicAdd(&g_cur[d], 1);
    g_edge[pos] = make_int2(s, __float_as_int(w));
}

__global__ void k_prepw(const float* __restrict__ W1, const float* __restrict__ W2)
{
    int i = blockIdx.x * blockDim.x + threadIdx.x;
    if (i < HID * F_IN) {
        int n = i / F_IN, k = i % F_IN;
        split1(W1[k * HID + n], g_w1hi[i], g_w1lo[i]);
    }
    int j = i - HID * F_IN;
    if (j >= 0 && j < HID * HID) {
        int n = j / HID, k = j % HID;
        split1(W2[k * HID + n], g_w2hi[j], g_w2lo[j]);
    }
}

// convert x to fp16 (4 elems / thread)
__global__ void k_prepx(const float* __restrict__ x)
{
    int i = blockIdx.x * blockDim.x + threadIdx.x;
    if (i >= NNODES * F_IN / 4) return;
    float4 v = ((const float4*)x)[i];
    __half2 a = __floats2half2_rn(v.x, v.y);
    __half2 b = __floats2half2_rn(v.z, v.w);
    uint2 u;
    u.x = *(uint32_t*)&a; u.y = *(uint32_t*)&b;
    ((uint2*)g_xh)[i] = u;
}

// ---------------- sparse aggregation: warp per destination node --------------
// gathers fp16 rows (4 edges in flight), fp32 accum, emits bf16 hi/lo split
template <int F>
__device__ __forceinline__ void agg_impl(const __half* __restrict__ in,
                                         __nv_bfloat16* __restrict__ ohi,
                                         __nv_bfloat16* __restrict__ olo)
{
    const int warp = (blockIdx.x * blockDim.x + threadIdx.x) >> 5;
    const int lane = threadIdx.x & 31;
    if (warp >= NNODES) return;

    constexpr int V = F / 128;          // uint2 (4 halves) chunks per lane
    float4 acc[V];

    const float dn = g_dinv[warp];
    const float w0 = dn * dn;
    const uint2* selfrow = (const uint2*)(in + (size_t)warp * F);
    #pragma unroll
    for (int v = 0; v < V; v++) {
        uint2 u = __ldg(&selfrow[lane + 32 * v]);
        float2 f0 = __half22float2(*(const __half2*)&u.x);
        float2 f1 = __half22float2(*(const __half2*)&u.y);
        acc[v].x = w0 * f0.x; acc[v].y = w0 * f0.y;
        acc[v].z = w0 * f1.x; acc[v].w = w0 * f1.y;
    }

    const int beg = g_off[warp];
    const int end = beg + g_cnt[warp];
    int i = beg;
    // 4 edges in flight
    for (; i + 4 <= end; i += 4) {
        int2 e[4];
        #pragma unroll
        for (int q = 0; q < 4; q++) e[q] = g_edge[i + q];
        uint2 u[4][V];
        #pragma unroll
        for (int q = 0; q < 4; q++) {
            const uint2* r = (const uint2*)(in + (size_t)e[q].x * F);
            #pragma unroll
            for (int v = 0; v < V; v++)
                u[q][v] = __ldg(&r[lane + 32 * v]);
        }
        #pragma unroll
        for (int q = 0; q < 4; q++) {
            const float we = __int_as_float(e[q].y);
            #pragma unroll
            for (int v = 0; v < V; v++) {
                float2 f0 = __half22float2(*(const __half2*)&u[q][v].x);
                float2 f1 = __half22float2(*(const __half2*)&u[q][v].y);
                acc[v].x += we * f0.x; acc[v].y += we * f0.y;
                acc[v].z += we * f1.x; acc[v].w += we * f1.y;
            }
        }
    }
    for (; i < end; i++) {
        const int2 e0 = g_edge[i];
        const float we = __int_as_float(e0.y);
        const uint2* r = (const uint2*)(in + (size_t)e0.x * F);
        #pragma unroll
        for (int v = 0; v < V; v++) {
            uint2 u0 = __ldg(&r[lane + 32 * v]);
            float2 f0 = __half22float2(*(const __half2*)&u0.x);
            float2 f1 = __half22float2(*(const __half2*)&u0.y);
            acc[v].x += we * f0.x; acc[v].y += we * f0.y;
            acc[v].z += we * f1.x; acc[v].w += we * f1.y;
        }
    }

    #pragma unroll
    for (int v = 0; v < V; v++) {
        size_t o = (size_t)warp * F + 4 * (lane + 32 * v);
        uint2 hi, lo;
        split4(acc[v], hi, lo);
        *(uint2*)(ohi + o) = hi;
        *(uint2*)(olo + o) = lo;
    }
}

__global__ void k_agg_x()  { agg_impl<F_IN>(g_xh,  g_ax_hi, g_ax_lo); }
__global__ void k_agg_h1() { agg_impl<HID>(g_h1h, g_a1_hi, g_a1_lo); }

// ---------------- HMMA bf16 GEMM: C = relu(A' @ B'^T + bias) -----------------
// Virtual K' = 3F, A' = [hi|lo|hi], B' = [hi|hi|lo] -> AhBh + AlBh + AhBl.
// Block 128x128, 8 warps of 64x32. 3-stage cp.async pipeline, ONE sync/iter,
// 2 blocks/SM. OutT selects fp16 (h1) or fp32 (h2) output.
#define SROWB 80
#define T_STG (128 * SROWB)
#define GEMM_SMEM (6 * T_STG)                // 61440 B

template <int F, typename OutT>
__device__ __forceinline__ void gemm_body(const __nv_bfloat16* __restrict__ Ahi,
                                          const __nv_bfloat16* __restrict__ Alo,
                                          const __nv_bfloat16* __restrict__ Bhi,
                                          const __nv_bfloat16* __restrict__ Blo,
                                          const float* __restrict__ bias,
                                          OutT* __restrict__ C)
{
    extern __shared__ __align__(16) uint8_t smem_dyn[];
    uint32_t sA;
    asm("{ .reg .u64 t; cvta.to.shared.u64 t, %1; cvt.u32.u64 %0, t; }"
        : "=r"(sA) : "l"(&smem_dyn[0]));
    const uint32_t sB = sA + 3 * T_STG;

    const int tid  = threadIdx.x;
    const int lane = tid & 31;
    const int wid  = tid >> 5;
    const int g    = lane >> 2;
    const int tg   = lane & 3;
    const int wm   = (wid & 1) * 64;
    const int wn   = (wid >> 1) * 32;
    const int brow = blockIdx.y * 128;
    const int bcol = blockIdx.x * 128;

    float acc[4][4][4];
    #pragma unroll
    for (int mi = 0; mi < 4; mi++)
        #pragma unroll
        for (int ni = 0; ni < 4; ni++)
            #pragma unroll
            for (int c = 0; c < 4; c++) acc[mi][ni][c] = 0.f;

    const int lrow = tid >> 2;
    const int lseg = tid & 3;
    auto load_stage = [&](int st, int k0) {
        const int seg = k0 / F;
        const int kk0 = k0 - seg * F;
        const __nv_bfloat16* a_src = (seg == 1) ? Alo : Ahi;
        const __nv_bfloat16* b_src = (seg == 2) ? Blo : Bhi;
        #pragma unroll
        for (int i = 0; i < 2; i++) {
            int row = lrow + i * 64;
            uint32_t soA = sA + (uint32_t)st * T_STG + row * SROWB + lseg * 16;
            const __nv_bfloat16* ga = a_src + (size_t)(brow + row) * F + kk0 + lseg * 8;
            asm volatile("cp.async.cg.shared.global [%0], [%1], 16;"
                         :: "r"(soA), "l"(ga));
            uint32_t soB = sB + (uint32_t)st * T_STG + row * SROWB + lseg * 16;
            const __nv_bfloat16* gb = b_src + (size_t)(bcol + row) * F + kk0 + lseg * 8;
            asm volatile("cp.async.cg.shared.global [%0], [%1], 16;"
                         :: "r"(soB), "l"(gb));
        }
        asm volatile("cp.async.commit_group;");
    };

    constexpr int NK = 3 * F / 32;
    load_stage(0, 0);
    load_stage(1, 32);

    const int lr  = lane & 15;
    const int lhi = (lane >> 4) * 16;

    int st = 0;
    for (int ki = 0; ki < NK; ki++) {
        asm volatile("cp.async.wait_group 1;");
        __syncthreads();
        if (ki + 2 < NK) {
            int st2 = st + 2; if (st2 >= 3) st2 -= 3;
            load_stage(st2, (ki + 2) * 32);
        }

        const uint32_t bufA = sA + st * T_STG;
        const uint32_t bufB = sB + st * T_STG;

        #pragma unroll
        for (int kk = 0; kk < 2; kk++) {
            const uint32_t kb = kk * 32;
            uint32_t af[4][4];
            #pragma unroll
            for (int mi = 0; mi < 4; mi++) {
                uint32_t addr = bufA + (wm + mi * 16 + lr) * SROWB + kb + lhi;
                asm volatile("ldmatrix.sync.aligned.m8n8.x4.shared.b16 {%0,%1,%2,%3}, [%4];"
                             : "=r"(af[mi][0]), "=r"(af[mi][1]),
                               "=r"(af[mi][2]), "=r"(af[mi][3]) : "r"(addr));
            }
            #pragma unroll
            for (int p = 0; p < 2; p++) {
                uint32_t r0, r1, r2, r3;
                uint32_t addr = bufB + (wn + p * 16 + lr) * SROWB + kb + lhi;
                asm volatile("ldmatrix.sync.aligned.m8n8.x4.shared.b16 {%0,%1,%2,%3}, [%4];"
                             : "=r"(r0), "=r"(r1), "=r"(r2), "=r"(r3) : "r"(addr));
                #pragma unroll
                for (int mi = 0; mi < 4; mi++) {
                    asm volatile(
                        "mma.sync.aligned.m16n8k16.row.col.f32.bf16.bf16.f32 "
                        "{%0,%1,%2,%3},{%4,%5,%6,%7},{%8,%9},{%0,%1,%2,%3};"
                        : "+f"(acc[mi][2 * p][0]), "+f"(acc[mi][2 * p][1]),
                          "+f"(acc[mi][2 * p][2]), "+f"(acc[mi][2 * p][3])
                        : "r"(af[mi][0]), "r"(af[mi][1]), "r"(af[mi][2]), "r"(af[mi][3]),
                          "r"(r0), "r"(r2));
                    asm volatile(
                        "mma.sync.aligned.m16n8k16.row.col.f32.bf16.bf16.f32 "
                        "{%0,%1,%2,%3},{%4,%5,%6,%7},{%8,%9},{%0,%1,%2,%3};"
                        : "+f"(acc[mi][2 * p + 1][0]), "+f"(acc[mi][2 * p + 1][1]),
                          "+f"(acc[mi][2 * p + 1][2]), "+f"(acc[mi][2 * p + 1][3])
                        : "r"(af[mi][0]), "r"(af[mi][1]), "r"(af[mi][2]), "r"(af[mi][3]),
                          "r"(r1), "r"(r3));
                }
            }
        }
        if (++st == 3) st = 0;
    }

    // ---- epilogue: bias + relu, fp16 or fp32 store ----
    #pragma unroll
    for (int ni = 0; ni < 4; ni++) {
        const int col = bcol + wn + ni * 8 + tg * 2;
        const float b0 = __ldg(bias + col);
        const float b1 = __ldg(bias + col + 1);
        #pragma unroll
        for (int mi = 0; mi < 4; mi++) {
            int r0 = brow + wm + mi * 16 + g;
            if (r0 < NNODES) {
                float v0 = fmaxf(acc[mi][ni][0] + b0, 0.f);
                float v1 = fmaxf(acc[mi][ni][1] + b1, 0.f);
                if constexpr (sizeof(OutT) == 2) {
                    __half2 o = __floats2half2_rn(v0, v1);
                    *(__half2*)((__half*)C + (size_t)r0 * HID + col) = o;
                } else {
                    *(float2*)((float*)C + (size_t)r0 * HID + col) = make_float2(v0, v1);
                }
            }
            int r1 = r0 + 8;
            if (r1 < NNODES) {
                float v0 = fmaxf(acc[mi][ni][2] + b0, 0.f);
                float v1 = fmaxf(acc[mi][ni][3] + b1, 0.f);
                if constexpr (sizeof(OutT) == 2) {
                    __half2 o = __floats2half2_rn(v0, v1);
                    *(__half2*)((__half*)C + (size_t)r1 * HID + col) = o;
                } else {
                    *(float2*)((float*)C + (size_t)r1 * HID + col) = make_float2(v0, v1);
                }
            }
        }
    }
}

__global__ void __launch_bounds__(256, 2) k_gemm1(const float* __restrict__ b1)
{
    gemm_body<F_IN, __half>(g_ax_hi, g_ax_lo, g_w1hi, g_w1lo, b1, g_h1h);
}
__global__ void __launch_bounds__(256, 2) k_gemm2(const float* __restrict__ b2)
{
    gemm_body<HID, float>(g_a1_hi, g_a1_lo, g_w2hi, g_w2lo, b2, g_h2);
}

// ---------------- classifier: out[Nx40] = h2[Nx256] @ Wc[256x40] + bc --------
__global__ void __launch_bounds__(256) k_cls(const float* __restrict__ Wc,
                                             const float* __restrict__ bc,
                                             float* __restrict__ out)
{
    __shared__ float Ws[HID * NOUT];
    const int tid = threadIdx.x;
    for (int i = tid; i < HID * NOUT; i += 256) Ws[i] = Wc[i];
    __syncthreads();

    const int s  = tid >> 2;
    const int cg = (tid & 3) * 10;
    const int r0 = blockIdx.x * 128 + s;
    const int r1 = r0 + 64;
    const bool v0 = r0 < NNODES;
    const bool v1 = r1 < NNODES;
    if (!v0) return;

    const float* h0 = g_h2 + (size_t)r0 * HID;
    const float* h1 = g_h2 + (size_t)(v1 ? r1 : r0) * HID;

    unsigned long long acc0[5] = {0, 0, 0, 0, 0};
    unsigned long long acc1[5] = {0, 0, 0, 0, 0};

    #pragma unroll 2
    for (int k = 0; k < HID; k += 4) {
        float4 a0 = *(const float4*)(h0 + k);
        float4 a1 = *(const float4*)(h1 + k);
        const float av0[4] = {a0.x, a0.y, a0.z, a0.w};
        const float av1[4] = {a1.x, a1.y, a1.z, a1.w};
        #pragma unroll
        for (int kk = 0; kk < 4; kk++) {
            unsigned long long hb0, hb1;
            asm("mov.b64 %0, {%1, %1};" : "=l"(hb0) : "r"(__float_as_uint(av0[kk])));
            asm("mov.b64 %0, {%1, %1};" : "=l"(hb1) : "r"(__float_as_uint(av1[kk])));
            const float* wrow = Ws + (k + kk) * NOUT + cg;
            #pragma unroll
            for (int j = 0; j < 5; j++) {
                unsigned long long w = *(const unsigned long long*)(wrow + 2 * j);
                asm("fma.rn.f32x2 %0, %1, %2, %0;" : "+l"(acc0[j]) : "l"(hb0), "l"(w));
                asm("fma.rn.f32x2 %0, %1, %2, %0;" : "+l"(acc1[j]) : "l"(hb1), "l"(w));
            }
        }
    }

    #pragma unroll
    for (int j = 0; j < 5; j++) {
        uint32_t lo, hi;
        float bcl = __ldg(bc + cg + 2 * j);
        float bch = __ldg(bc + cg + 2 * j + 1);
        asm("mov.b64 {%0, %1}, %2;" : "=r"(lo), "=r"(hi) : "l"(acc0[j]));
        out[(size_t)r0 * NOUT + cg + 2 * j]     = __uint_as_float(lo) + bcl;
        out[(size_t)r0 * NOUT + cg + 2 * j + 1] = __uint_as_float(hi) + bch;
        if (v1) {
            asm("mov.b64 {%0, %1}, %2;" : "=r"(lo), "=r"(hi) : "l"(acc1[j]));
            out[(size_t)r1 * NOUT + cg + 2 * j]     = __uint_as_float(lo) + bcl;
            out[(size_t)r1 * NOUT + cg + 2 * j + 1] = __uint_as_float(hi) + bch;
        }
    }
}

// ---------------- launch ------------------------------------------------------
extern "C" void kernel_launch(void* const* d_in, const int* in_sizes, int n_in,
                              void* d_out, int out_size)
{
    const float* x   = (const float*)d_in[0];
    const float* W1  = (const float*)d_in[1];
    const float* b1  = (const float*)d_in[2];
    const float* W2  = (const float*)d_in[3];
    const float* b2  = (const float*)d_in[4];
    const float* Wc  = (const float*)d_in[5];
    const float* bc  = (const float*)d_in[6];
    const int*   ei  = (const int*)  d_in[7];
    float*       out = (float*)d_out;

    cudaFuncSetAttribute(k_gemm1, cudaFuncAttributeMaxDynamicSharedMemorySize, GEMM_SMEM);
    cudaFuncSetAttribute(k_gemm2, cudaFuncAttributeMaxDynamicSharedMemorySize, GEMM_SMEM);

    // --- CSR build (scan-free offsets, single-atomic scatter) ---
    k_init   <<<(NNODES + 255) / 256, 256>>>();
    k_count  <<<(NEDGES + 255) / 256, 256>>>(ei);
    k_offsets<<<(NNODES + 255) / 256, 256>>>();
    k_scatter<<<(NEDGES + 255) / 256, 256>>>(ei);

    // --- weight transpose/split + x fp16 conversion ---
    k_prepw<<<(HID * F_IN + HID * HID + 255) / 256, 256>>>(W1, W2);
    k_prepx<<<(NNODES * F_IN / 4 + 255) / 256, 256>>>(x);

    const int aggBlocks = (NNODES * 32 + 255) / 256;
    dim3 gemmGrid(HID / 128, MTILES);

    // --- layer 1: relu(agg(x) @ W1 + b1) -> fp16 h1 ---
    k_agg_x<<<aggBlocks, 256>>>();
    k_gemm1<<<gemmGrid, 256, GEMM_SMEM>>>(b1);

    // --- layer 2: relu(agg(h1) @ W2 + b2) -> fp32 h2 ---
    k_agg_h1<<<aggBlocks, 256>>>();
    k_gemm2<<<gemmGrid, 256, GEMM_SMEM>>>(b2);

    // --- classifier ---
    k_cls<<<MTILES, 256>>>(Wc, bc, out);
}

// round 12
// speedup vs baseline: 1.6097x; 1.3962x over previous
#include <cuda_runtime.h>
#include <cuda_fp16.h>
#include <cstdint>

#define NNODES 50000
#define NODPAD 50048
#define NEDGES 800000
#define F_IN   128
#define HID    256
#define NOUT   40
#define MTILES (NODPAD / 128)   // 391

// ---------------- scratch (static device memory, no allocations) ------------
__device__ int   g_cnt[NNODES];
__device__ int   g_off[NNODES];
__device__ int   g_cur[NNODES];
__device__ int   g_total;
__device__ float g_dinv[NNODES];
__device__ __align__(16) int2 g_edge[NEDGES];   // (src, weight bits)
__device__ __align__(16) __half g_xh[(size_t)NNODES * F_IN];     // fp16 x
__device__ __align__(16) __half g_h1h[(size_t)NNODES * HID];     // fp16 h1
__device__ __align__(16) __half g_ax[(size_t)NODPAD * F_IN];     // agg(x) fp16
__device__ __align__(16) __half g_a1[(size_t)NODPAD * HID];      // agg(h1) fp16
__device__ __align__(16) float  g_h2[(size_t)NNODES * HID];
__device__ __align__(16) __half g_w1h[HID * F_IN];               // W1^T fp16
__device__ __align__(16) __half g_w2h[HID * HID];                // W2^T fp16

// ---------------- graph preprocessing ---------------------------------------
__global__ void k_init()
{
    int i = blockIdx.x * blockDim.x + threadIdx.x;
    if (i < NNODES) g_cnt[i] = 0;
    if (i == 0) g_total = 0;
}

__global__ void k_count(const int* __restrict__ ei)
{
    int e = blockIdx.x * blockDim.x + threadIdx.x;
    if (e < NEDGES) atomicAdd(&g_cnt[ei[NEDGES + e]], 1);
}

__global__ void k_offsets()
{
    int i = blockIdx.x * blockDim.x + threadIdx.x;
    if (i >= NNODES) return;
    int c = g_cnt[i];
    int off = atomicAdd(&g_total, c);
    g_off[i]  = off;
    g_cur[i]  = off;
    g_dinv[i] = rsqrtf((float)(c + 1));
}

__global__ void k_scatter(const int* __restrict__ ei)
{
    int e = blockIdx.x * blockDim.x + threadIdx.x;
    if (e >= NEDGES) return;
    int s = ei[e];
    int d = ei[NEDGES + e];
    float w = g_dinv[s] * g_dinv[d];
    int pos = atomicAdd(&g_cur[d], 1);
    g_edge[pos] = make_int2(s, __float_as_int(w));
}

// transpose weights to [n][k], fp16
__global__ void k_prepw(const float* __restrict__ W1, const float* __restrict__ W2)
{
    int i = blockIdx.x * blockDim.x + threadIdx.x;
    if (i < HID * F_IN) {
        int n = i / F_IN, k = i % F_IN;
        g_w1h[i] = __float2half_rn(W1[k * HID + n]);
    }
    int j = i - HID * F_IN;
    if (j >= 0 && j < HID * HID) {
        int n = j / HID, k = j % HID;
        g_w2h[j] = __float2half_rn(W2[k * HID + n]);
    }
}

// convert x to fp16 (4 elems / thread)
__global__ void k_prepx(const float* __restrict__ x)
{
    int i = blockIdx.x * blockDim.x + threadIdx.x;
    if (i >= NNODES * F_IN / 4) return;
    float4 v = ((const float4*)x)[i];
    __half2 a = __floats2half2_rn(v.x, v.y);
    __half2 b = __floats2half2_rn(v.z, v.w);
    uint2 u;
    u.x = *(uint32_t*)&a; u.y = *(uint32_t*)&b;
    ((uint2*)g_xh)[i] = u;
}

// ---------------- sparse aggregation: warp per destination node --------------
// gathers fp16 rows (4 edges in flight), fp32 accum, emits single fp16 row
template <int F>
__device__ __forceinline__ void agg_impl(const __half* __restrict__ in,
                                         __half* __restrict__ outp)
{
    const int warp = (blockIdx.x * blockDim.x + threadIdx.x) >> 5;
    const int lane = threadIdx.x & 31;
    if (warp >= NNODES) return;

    constexpr int V = F / 128;          // uint2 (4 halves) chunks per lane
    float4 acc[V];

    const float dn = g_dinv[warp];
    const float w0 = dn * dn;
    const uint2* selfrow = (const uint2*)(in + (size_t)warp * F);
    #pragma unroll
    for (int v = 0; v < V; v++) {
        uint2 u = __ldg(&selfrow[lane + 32 * v]);
        float2 f0 = __half22float2(*(const __half2*)&u.x);
        float2 f1 = __half22float2(*(const __half2*)&u.y);
        acc[v].x = w0 * f0.x; acc[v].y = w0 * f0.y;
        acc[v].z = w0 * f1.x; acc[v].w = w0 * f1.y;
    }

    const int beg = g_off[warp];
    const int end = beg + g_cnt[warp];
    int i = beg;
    for (; i + 4 <= end; i += 4) {
        int2 e[4];
        #pragma unroll
        for (int q = 0; q < 4; q++) e[q] = g_edge[i + q];
        uint2 u[4][V];
        #pragma unroll
        for (int q = 0; q < 4; q++) {
            const uint2* r = (const uint2*)(in + (size_t)e[q].x * F);
            #pragma unroll
            for (int v = 0; v < V; v++)
                u[q][v] = __ldg(&r[lane + 32 * v]);
        }
        #pragma unroll
        for (int q = 0; q < 4; q++) {
            const float we = __int_as_float(e[q].y);
            #pragma unroll
            for (int v = 0; v < V; v++) {
                float2 f0 = __half22float2(*(const __half2*)&u[q][v].x);
                float2 f1 = __half22float2(*(const __half2*)&u[q][v].y);
                acc[v].x += we * f0.x; acc[v].y += we * f0.y;
                acc[v].z += we * f1.x; acc[v].w += we * f1.y;
            }
        }
    }
    for (; i < end; i++) {
        const int2 e0 = g_edge[i];
        const float we = __int_as_float(e0.y);
        const uint2* r = (const uint2*)(in + (size_t)e0.x * F);
        #pragma unroll
        for (int v = 0; v < V; v++) {
            uint2 u0 = __ldg(&r[lane + 32 * v]);
            float2 f0 = __half22float2(*(const __half2*)&u0.x);
            float2 f1 = __half22float2(*(const __half2*)&u0.y);
            acc[v].x += we * f0.x; acc[v].y += we * f0.y;
            acc[v].z += we * f1.x; acc[v].w += we * f1.y;
        }
    }

    #pragma unroll
    for (int v = 0; v < V; v++) {
        size_t o = (size_t)warp * F + 4 * (lane + 32 * v);
        __half2 p0 = __floats2half2_rn(acc[v].x, acc[v].y);
        __half2 p1 = __floats2half2_rn(acc[v].z, acc[v].w);
        uint2 u;
        u.x = *(uint32_t*)&p0; u.y = *(uint32_t*)&p1;
        *(uint2*)(outp + o) = u;
    }
}

__global__ void k_agg_x()  { agg_impl<F_IN>(g_xh,  g_ax); }
__global__ void k_agg_h1() { agg_impl<HID>(g_h1h, g_a1); }

// ---------------- fp16 HMMA GEMM: C = relu(A @ B^T + bias) -------------------
// A: [NODPAD][F] fp16 row-major; B: [HID][F] fp16 (W^T). Single product.
// Block 128x128, 8 warps of 64x32. 3-stage cp.async pipeline, ONE sync/iter,
// 2 blocks/SM. OutT selects fp16 (h1) or fp32 (h2) output.
#define SROWB 80
#define T_STG (128 * SROWB)
#define GEMM_SMEM (6 * T_STG)                // 61440 B

template <int F, typename OutT>
__device__ __forceinline__ void gemm_body(const __half* __restrict__ A,
                                          const __half* __restrict__ B,
                                          const float* __restrict__ bias,
                                          OutT* __restrict__ C)
{
    extern __shared__ __align__(16) uint8_t smem_dyn[];
    uint32_t sA;
    asm("{ .reg .u64 t; cvta.to.shared.u64 t, %1; cvt.u32.u64 %0, t; }"
        : "=r"(sA) : "l"(&smem_dyn[0]));
    const uint32_t sB = sA + 3 * T_STG;

    const int tid  = threadIdx.x;
    const int lane = tid & 31;
    const int wid  = tid >> 5;
    const int g    = lane >> 2;
    const int tg   = lane & 3;
    const int wm   = (wid & 1) * 64;
    const int wn   = (wid >> 1) * 32;
    const int brow = blockIdx.y * 128;
    const int bcol = blockIdx.x * 128;

    float acc[4][4][4];
    #pragma unroll
    for (int mi = 0; mi < 4; mi++)
        #pragma unroll
        for (int ni = 0; ni < 4; ni++)
            #pragma unroll
            for (int c = 0; c < 4; c++) acc[mi][ni][c] = 0.f;

    const int lrow = tid >> 2;
    const int lseg = tid & 3;
    auto load_stage = [&](int st, int k0) {
        #pragma unroll
        for (int i = 0; i < 2; i++) {
            int row = lrow + i * 64;
            uint32_t soA = sA + (uint32_t)st * T_STG + row * SROWB + lseg * 16;
            const __half* ga = A + (size_t)(brow + row) * F + k0 + lseg * 8;
            asm volatile("cp.async.cg.shared.global [%0], [%1], 16;"
                         :: "r"(soA), "l"(ga));
            uint32_t soB = sB + (uint32_t)st * T_STG + row * SROWB + lseg * 16;
            const __half* gb = B + (size_t)(bcol + row) * F + k0 + lseg * 8;
            asm volatile("cp.async.cg.shared.global [%0], [%1], 16;"
                         :: "r"(soB), "l"(gb));
        }
        asm volatile("cp.async.commit_group;");
    };

    constexpr int NK = F / 32;
    load_stage(0, 0);
    load_stage(1, 32);

    const int lr  = lane & 15;
    const int lhi = (lane >> 4) * 16;

    int st = 0;
    for (int ki = 0; ki < NK; ki++) {
        if (ki + 1 < NK) {
            asm volatile("cp.async.wait_group 1;");
        } else {
            asm volatile("cp.async.wait_group 0;");   // last stage must be complete
        }
        __syncthreads();
        if (ki + 2 < NK) {
            int st2 = st + 2; if (st2 >= 3) st2 -= 3;
            load_stage(st2, (ki + 2) * 32);
        }

        const uint32_t bufA = sA + st * T_STG;
        const uint32_t bufB = sB + st * T_STG;

        #pragma unroll
        for (int kk = 0; kk < 2; kk++) {
            const uint32_t kb = kk * 32;
            uint32_t af[4][4];
            #pragma unroll
            for (int mi = 0; mi < 4; mi++) {
                uint32_t addr = bufA + (wm + mi * 16 + lr) * SROWB + kb + lhi;
                asm volatile("ldmatrix.sync.aligned.m8n8.x4.shared.b16 {%0,%1,%2,%3}, [%4];"
                             : "=r"(af[mi][0]), "=r"(af[mi][1]),
                               "=r"(af[mi][2]), "=r"(af[mi][3]) : "r"(addr));
            }
            #pragma unroll
            for (int p = 0; p < 2; p++) {
                uint32_t r0, r1, r2, r3;
                uint32_t addr = bufB + (wn + p * 16 + lr) * SROWB + kb + lhi;
                asm volatile("ldmatrix.sync.aligned.m8n8.x4.shared.b16 {%0,%1,%2,%3}, [%4];"
                             : "=r"(r0), "=r"(r1), "=r"(r2), "=r"(r3) : "r"(addr));
                #pragma unroll
                for (int mi = 0; mi < 4; mi++) {
                    asm volatile(
                        "mma.sync.aligned.m16n8k16.row.col.f32.f16.f16.f32 "
                        "{%0,%1,%2,%3},{%4,%5,%6,%7},{%8,%9},{%0,%1,%2,%3};"
                        : "+f"(acc[mi][2 * p][0]), "+f"(acc[mi][2 * p][1]),
                          "+f"(acc[mi][2 * p][2]), "+f"(acc[mi][2 * p][3])
                        : "r"(af[mi][0]), "r"(af[mi][1]), "r"(af[mi][2]), "r"(af[mi][3]),
                          "r"(r0), "r"(r2));
                    asm volatile(
                        "mma.sync.aligned.m16n8k16.row.col.f32.f16.f16.f32 "
                        "{%0,%1,%2,%3},{%4,%5,%6,%7},{%8,%9},{%0,%1,%2,%3};"
                        : "+f"(acc[mi][2 * p + 1][0]), "+f"(acc[mi][2 * p + 1][1]),
                          "+f"(acc[mi][2 * p + 1][2]), "+f"(acc[mi][2 * p + 1][3])
                        : "r"(af[mi][0]), "r"(af[mi][1]), "r"(af[mi][2]), "r"(af[mi][3]),
                          "r"(r1), "r"(r3));
                }
            }
        }
        if (++st == 3) st = 0;
    }

    // ---- epilogue: bias + relu, fp16 or fp32 store ----
    #pragma unroll
    for (int ni = 0; ni < 4; ni++) {
        const int col = bcol + wn + ni * 8 + tg * 2;
        const float b0 = __ldg(bias + col);
        const float b1 = __ldg(bias + col + 1);
        #pragma unroll
        for (int mi = 0; mi < 4; mi++) {
            int r0 = brow + wm + mi * 16 + g;
            if (r0 < NNODES) {
                float v0 = fmaxf(acc[mi][ni][0] + b0, 0.f);
                float v1 = fmaxf(acc[mi][ni][1] + b1, 0.f);
                if constexpr (sizeof(OutT) == 2) {
                    __half2 o = __floats2half2_rn(v0, v1);
                    *(__half2*)((__half*)C + (size_t)r0 * HID + col) = o;
                } else {
                    *(float2*)((float*)C + (size_t)r0 * HID + col) = make_float2(v0, v1);
                }
            }
            int r1 = r0 + 8;
            if (r1 < NNODES) {
                float v0 = fmaxf(acc[mi][ni][2] + b0, 0.f);
                float v1 = fmaxf(acc[mi][ni][3] + b1, 0.f);
                if constexpr (sizeof(OutT) == 2) {
                    __half2 o = __floats2half2_rn(v0, v1);
                    *(__half2*)((__half*)C + (size_t)r1 * HID + col) = o;
                } else {
                    *(float2*)((float*)C + (size_t)r1 * HID + col) = make_float2(v0, v1);
                }
            }
        }
    }
}

__global__ void __launch_bounds__(256, 2) k_gemm1(const float* __restrict__ b1)
{
    gemm_body<F_IN, __half>(g_ax, g_w1h, b1, g_h1h);
}
__global__ void __launch_bounds__(256, 2) k_gemm2(const float* __restrict__ b2)
{
    gemm_body<HID, float>(g_a1, g_w2h, b2, g_h2);
}

// ---------------- classifier: out[Nx40] = h2[Nx256] @ Wc[256x40] + bc --------
__global__ void __launch_bounds__(256) k_cls(const float* __restrict__ Wc,
                                             const float* __restrict__ bc,
                                             float* __restrict__ out)
{
    __shared__ float Ws[HID * NOUT];
    const int tid = threadIdx.x;
    for (int i = tid; i < HID * NOUT; i += 256) Ws[i] = Wc[i];
    __syncthreads();

    const int s  = tid >> 2;
    const int cg = (tid & 3) * 10;
    const int r0 = blockIdx.x * 128 + s;
    const int r1 = r0 + 64;
    const bool v0 = r0 < NNODES;
    const bool v1 = r1 < NNODES;
    if (!v0) return;

    const float* h0 = g_h2 + (size_t)r0 * HID;
    const float* h1 = g_h2 + (size_t)(v1 ? r1 : r0) * HID;

    unsigned long long acc0[5] = {0, 0, 0, 0, 0};
    unsigned long long acc1[5] = {0, 0, 0, 0, 0};

    #pragma unroll 2
    for (int k = 0; k < HID; k += 4) {
        float4 a0 = *(const float4*)(h0 + k);
        float4 a1 = *(const float4*)(h1 + k);
        const float av0[4] = {a0.x, a0.y, a0.z, a0.w};
        const float av1[4] = {a1.x, a1.y, a1.z, a1.w};
        #pragma unroll
        for (int kk = 0; kk < 4; kk++) {
            unsigned long long hb0, hb1;
            asm("mov.b64 %0, {%1, %1};" : "=l"(hb0) : "r"(__float_as_uint(av0[kk])));
            asm("mov.b64 %0, {%1, %1};" : "=l"(hb1) : "r"(__float_as_uint(av1[kk])));
            const float* wrow = Ws + (k + kk) * NOUT + cg;
            #pragma unroll
            for (int j = 0; j < 5; j++) {
                unsigned long long w = *(const unsigned long long*)(wrow + 2 * j);
                asm("fma.rn.f32x2 %0, %1, %2, %0;" : "+l"(acc0[j]) : "l"(hb0), "l"(w));
                asm("fma.rn.f32x2 %0, %1, %2, %0;" : "+l"(acc1[j]) : "l"(hb1), "l"(w));
            }
        }
    }

    #pragma unroll
    for (int j = 0; j < 5; j++) {
        uint32_t lo, hi;
        float bcl = __ldg(bc + cg + 2 * j);
        float bch = __ldg(bc + cg + 2 * j + 1);
        asm("mov.b64 {%0, %1}, %2;" : "=r"(lo), "=r"(hi) : "l"(acc0[j]));
        out[(size_t)r0 * NOUT + cg + 2 * j]     = __uint_as_float(lo) + bcl;
        out[(size_t)r0 * NOUT + cg + 2 * j + 1] = __uint_as_float(hi) + bch;
        if (v1) {
            asm("mov.b64 {%0, %1}, %2;" : "=r"(lo), "=r"(hi) : "l"(acc1[j]));
            out[(size_t)r1 * NOUT + cg + 2 * j]     = __uint_as_float(lo) + bcl;
            out[(size_t)r1 * NOUT + cg + 2 * j + 1] = __uint_as_float(hi) + bch;
        }
    }
}

// ---------------- launch ------------------------------------------------------
extern "C" void kernel_launch(void* const* d_in, const int* in_sizes, int n_in,
                              void* d_out, int out_size)
{
    const float* x   = (const float*)d_in[0];
    const float* W1  = (const float*)d_in[1];
    const float* b1  = (const float*)d_in[2];
    const float* W2  = (const float*)d_in[3];
    const float* b2  = (const float*)d_in[4];
    const float* Wc  = (const float*)d_in[5];
    const float* bc  = (const float*)d_in[6];
    const int*   ei  = (const int*)  d_in[7];
    float*       out = (float*)d_out;

    cudaFuncSetAttribute(k_gemm1, cudaFuncAttributeMaxDynamicSharedMemorySize, GEMM_SMEM);
    cudaFuncSetAttribute(k_gemm2, cudaFuncAttributeMaxDynamicSharedMemorySize, GEMM_SMEM);

    // --- CSR build (scan-free offsets, single-atomic scatter) ---
    k_init   <<<(NNODES + 255) / 256, 256>>>();
    k_count  <<<(NEDGES + 255) / 256, 256>>>(ei);
    k_offsets<<<(NNODES + 255) / 256, 256>>>();
    k_scatter<<<(NEDGES + 255) / 256, 256>>>(ei);

    // --- weight transpose (fp16) + x fp16 conversion ---
    k_prepw<<<(HID * F_IN + HID * HID + 255) / 256, 256>>>(W1, W2);
    k_prepx<<<(NNODES * F_IN / 4 + 255) / 256, 256>>>(x);

    const int aggBlocks = (NNODES * 32 + 255) / 256;
    dim3 gemmGrid(HID / 128, MTILES);

    // --- layer 1: relu(agg(x) @ W1 + b1) -> fp16 h1 ---
    k_agg_x<<<aggBlocks, 256>>>();
    k_gemm1<<<gemmGrid, 256, GEMM_SMEM>>>(b1);

    // --- layer 2: relu(agg(h1) @ W2 + b2) -> fp32 h2 ---
    k_agg_h1<<<aggBlocks, 256>>>();
    k_gemm2<<<gemmGrid, 256, GEMM_SMEM>>>(b2);

    // --- classifier ---
    k_cls<<<MTILES, 256>>>(Wc, bc, out);
}

// round 13
// speedup vs baseline: 1.6195x; 1.0061x over previous
#include <cuda_runtime.h>
#include <cuda_fp16.h>
#include <cstdint>

#define NNODES 50000
#define NODPAD 50048
#define NEDGES 800000
#define F_IN   128
#define HID    256
#define NOUT   40
#define MTILES (NODPAD / 128)   // 391

// ---------------- scratch (static device memory, no allocations) ------------
__device__ int   g_cnt[NNODES];
__device__ int   g_off[NNODES];
__device__ int   g_cur[NNODES];
__device__ int   g_total;
__device__ float g_dinv[NNODES];
__device__ __align__(16) int2 g_edge[NEDGES];   // (src, weight bits)
__device__ __align__(16) __half g_xh[(size_t)NNODES * F_IN];     // fp16 x
__device__ __align__(16) __half g_h1h[(size_t)NNODES * HID];     // fp16 h1
__device__ __align__(16) __half g_ax[(size_t)NODPAD * F_IN];     // agg(x) fp16
__device__ __align__(16) __half g_a1[(size_t)NODPAD * HID];      // agg(h1) fp16
__device__ __align__(16) __half g_h2h[(size_t)NNODES * HID];     // fp16 h2
__device__ __align__(16) __half g_w1h[HID * F_IN];               // W1^T fp16
__device__ __align__(16) __half g_w2h[HID * HID];                // W2^T fp16

// ---------------- graph preprocessing ---------------------------------------
__global__ void k_init()
{
    int i = blockIdx.x * blockDim.x + threadIdx.x;
    if (i < NNODES) g_cnt[i] = 0;
    if (i == 0) g_total = 0;
}

__global__ void k_count(const int* __restrict__ ei)
{
    int e = blockIdx.x * blockDim.x + threadIdx.x;
    if (e < NEDGES) atomicAdd(&g_cnt[ei[NEDGES + e]], 1);
}

__global__ void k_offsets()
{
    int i = blockIdx.x * blockDim.x + threadIdx.x;
    if (i >= NNODES) return;
    int c = g_cnt[i];
    int off = atomicAdd(&g_total, c);
    g_off[i]  = off;
    g_cur[i]  = off;
    g_dinv[i] = rsqrtf((float)(c + 1));
}

__global__ void k_scatter(const int* __restrict__ ei)
{
    int e = blockIdx.x * blockDim.x + threadIdx.x;
    if (e >= NEDGES) return;
    int s = ei[e];
    int d = ei[NEDGES + e];
    float w = g_dinv[s] * g_dinv[d];
    int pos = atomicAdd(&g_cur[d], 1);
    g_edge[pos] = make_int2(s, __float_as_int(w));
}

// transpose weights to [n][k], fp16
__global__ void k_prepw(const float* __restrict__ W1, const float* __restrict__ W2)
{
    int i = blockIdx.x * blockDim.x + threadIdx.x;
    if (i < HID * F_IN) {
        int n = i / F_IN, k = i % F_IN;
        g_w1h[i] = __float2half_rn(W1[k * HID + n]);
    }
    int j = i - HID * F_IN;
    if (j >= 0 && j < HID * HID) {
        int n = j / HID, k = j % HID;
        g_w2h[j] = __float2half_rn(W2[k * HID + n]);
    }
}

// convert x to fp16 (4 elems / thread)
__global__ void k_prepx(const float* __restrict__ x)
{
    int i = blockIdx.x * blockDim.x + threadIdx.x;
    if (i >= NNODES * F_IN / 4) return;
    float4 v = ((const float4*)x)[i];
    __half2 a = __floats2half2_rn(v.x, v.y);
    __half2 b = __floats2half2_rn(v.z, v.w);
    uint2 u;
    u.x = *(uint32_t*)&a; u.y = *(uint32_t*)&b;
    ((uint2*)g_xh)[i] = u;
}

// ---------------- sparse aggregation ----------------------------------------
// F/128 warps per node; each warp owns a 128-feature slice (uint2 per lane).
// 4 edges in flight; fp32 accum; fp16 output.
template <int F>
__device__ __forceinline__ void agg_impl(const __half* __restrict__ in,
                                         __half* __restrict__ outp)
{
    constexpr int WPN = F / 128;
    const int gw   = (blockIdx.x * blockDim.x + threadIdx.x) >> 5;
    const int node = gw / WPN;
    const int slc  = gw - node * WPN;
    const int lane = threadIdx.x & 31;
    if (node >= NNODES) return;

    const int coff = slc * 128 + 4 * lane;   // half offset within a row

    float4 acc;
    const float dn = g_dinv[node];
    const float w0 = dn * dn;
    {
        uint2 u = __ldg((const uint2*)(in + (size_t)node * F + coff));
        float2 f0 = __half22float2(*(const __half2*)&u.x);
        float2 f1 = __half22float2(*(const __half2*)&u.y);
        acc.x = w0 * f0.x; acc.y = w0 * f0.y;
        acc.z = w0 * f1.x; acc.w = w0 * f1.y;
    }

    const int beg = g_off[node];
    const int end = beg + g_cnt[node];
    int i = beg;
    for (; i + 4 <= end; i += 4) {
        int2 e[4];
        #pragma unroll
        for (int q = 0; q < 4; q++) e[q] = g_edge[i + q];
        uint2 u[4];
        #pragma unroll
        for (int q = 0; q < 4; q++)
            u[q] = __ldg((const uint2*)(in + (size_t)e[q].x * F + coff));
        #pragma unroll
        for (int q = 0; q < 4; q++) {
            const float we = __int_as_float(e[q].y);
            float2 f0 = __half22float2(*(const __half2*)&u[q].x);
            float2 f1 = __half22float2(*(const __half2*)&u[q].y);
            acc.x += we * f0.x; acc.y += we * f0.y;
            acc.z += we * f1.x; acc.w += we * f1.y;
        }
    }
    for (; i < end; i++) {
        const int2 e0 = g_edge[i];
        const float we = __int_as_float(e0.y);
        uint2 u0 = __ldg((const uint2*)(in + (size_t)e0.x * F + coff));
        float2 f0 = __half22float2(*(const __half2*)&u0.x);
        float2 f1 = __half22float2(*(const __half2*)&u0.y);
        acc.x += we * f0.x; acc.y += we * f0.y;
        acc.z += we * f1.x; acc.w += we * f1.y;
    }

    __half2 p0 = __floats2half2_rn(acc.x, acc.y);
    __half2 p1 = __floats2half2_rn(acc.z, acc.w);
    uint2 u;
    u.x = *(uint32_t*)&p0; u.y = *(uint32_t*)&p1;
    *(uint2*)(outp + (size_t)node * F + coff) = u;
}

__global__ void k_agg_x()  { agg_impl<F_IN>(g_xh,  g_ax); }
__global__ void k_agg_h1() { agg_impl<HID>(g_h1h, g_a1); }

// ---------------- fp16 HMMA GEMM: C = relu(A @ B^T + bias) -------------------
// Block 128x128, 8 warps of 64x32. 3-stage cp.async pipeline, ONE sync/iter,
// 2 blocks/SM. Output fp16.
#define SROWB 80
#define T_STG (128 * SROWB)
#define GEMM_SMEM (6 * T_STG)                // 61440 B

template <int F>
__device__ __forceinline__ void gemm_body(const __half* __restrict__ A,
                                          const __half* __restrict__ B,
                                          const float* __restrict__ bias,
                                          __half* __restrict__ C)
{
    extern __shared__ __align__(16) uint8_t smem_dyn[];
    uint32_t sA;
    asm("{ .reg .u64 t; cvta.to.shared.u64 t, %1; cvt.u32.u64 %0, t; }"
        : "=r"(sA) : "l"(&smem_dyn[0]));
    const uint32_t sB = sA + 3 * T_STG;

    const int tid  = threadIdx.x;
    const int lane = tid & 31;
    const int wid  = tid >> 5;
    const int g    = lane >> 2;
    const int tg   = lane & 3;
    const int wm   = (wid & 1) * 64;
    const int wn   = (wid >> 1) * 32;
    const int brow = blockIdx.y * 128;
    const int bcol = blockIdx.x * 128;

    float acc[4][4][4];
    #pragma unroll
    for (int mi = 0; mi < 4; mi++)
        #pragma unroll
        for (int ni = 0; ni < 4; ni++)
            #pragma unroll
            for (int c = 0; c < 4; c++) acc[mi][ni][c] = 0.f;

    const int lrow = tid >> 2;
    const int lseg = tid & 3;
    auto load_stage = [&](int st, int k0) {
        #pragma unroll
        for (int i = 0; i < 2; i++) {
            int row = lrow + i * 64;
            uint32_t soA = sA + (uint32_t)st * T_STG + row * SROWB + lseg * 16;
            const __half* ga = A + (size_t)(brow + row) * F + k0 + lseg * 8;
            asm volatile("cp.async.cg.shared.global [%0], [%1], 16;"
                         :: "r"(soA), "l"(ga));
            uint32_t soB = sB + (uint32_t)st * T_STG + row * SROWB + lseg * 16;
            const __half* gb = B + (size_t)(bcol + row) * F + k0 + lseg * 8;
            asm volatile("cp.async.cg.shared.global [%0], [%1], 16;"
                         :: "r"(soB), "l"(gb));
        }
        asm volatile("cp.async.commit_group;");
    };

    constexpr int NK = F / 32;
    load_stage(0, 0);
    load_stage(1, 32);

    const int lr  = lane & 15;
    const int lhi = (lane >> 4) * 16;

    int st = 0;
    for (int ki = 0; ki < NK; ki++) {
        if (ki + 1 < NK) {
            asm volatile("cp.async.wait_group 1;");
        } else {
            asm volatile("cp.async.wait_group 0;");
        }
        __syncthreads();
        if (ki + 2 < NK) {
            int st2 = st + 2; if (st2 >= 3) st2 -= 3;
            load_stage(st2, (ki + 2) * 32);
        }

        const uint32_t bufA = sA + st * T_STG;
        const uint32_t bufB = sB + st * T_STG;

        #pragma unroll
        for (int kk = 0; kk < 2; kk++) {
            const uint32_t kb = kk * 32;
            uint32_t af[4][4];
            #pragma unroll
            for (int mi = 0; mi < 4; mi++) {
                uint32_t addr = bufA + (wm + mi * 16 + lr) * SROWB + kb + lhi;
                asm volatile("ldmatrix.sync.aligned.m8n8.x4.shared.b16 {%0,%1,%2,%3}, [%4];"
                             : "=r"(af[mi][0]), "=r"(af[mi][1]),
                               "=r"(af[mi][2]), "=r"(af[mi][3]) : "r"(addr));
            }
            #pragma unroll
            for (int p = 0; p < 2; p++) {
                uint32_t r0, r1, r2, r3;
                uint32_t addr = bufB + (wn + p * 16 + lr) * SROWB + kb + lhi;
                asm volatile("ldmatrix.sync.aligned.m8n8.x4.shared.b16 {%0,%1,%2,%3}, [%4];"
                             : "=r"(r0), "=r"(r1), "=r"(r2), "=r"(r3) : "r"(addr));
                #pragma unroll
                for (int mi = 0; mi < 4; mi++) {
                    asm volatile(
                        "mma.sync.aligned.m16n8k16.row.col.f32.f16.f16.f32 "
                        "{%0,%1,%2,%3},{%4,%5,%6,%7},{%8,%9},{%0,%1,%2,%3};"
                        : "+f"(acc[mi][2 * p][0]), "+f"(acc[mi][2 * p][1]),
                          "+f"(acc[mi][2 * p][2]), "+f"(acc[mi][2 * p][3])
                        : "r"(af[mi][0]), "r"(af[mi][1]), "r"(af[mi][2]), "r"(af[mi][3]),
                          "r"(r0), "r"(r2));
                    asm volatile(
                        "mma.sync.aligned.m16n8k16.row.col.f32.f16.f16.f32 "
                        "{%0,%1,%2,%3},{%4,%5,%6,%7},{%8,%9},{%0,%1,%2,%3};"
                        : "+f"(acc[mi][2 * p + 1][0]), "+f"(acc[mi][2 * p + 1][1]),
                          "+f"(acc[mi][2 * p + 1][2]), "+f"(acc[mi][2 * p + 1][3])
                        : "r"(af[mi][0]), "r"(af[mi][1]), "r"(af[mi][2]), "r"(af[mi][3]),
                          "r"(r1), "r"(r3));
                }
            }
        }
        if (++st == 3) st = 0;
    }

    // ---- epilogue: bias + relu, fp16 store ----
    #pragma unroll
    for (int ni = 0; ni < 4; ni++) {
        const int col = bcol + wn + ni * 8 + tg * 2;
        const float b0 = __ldg(bias + col);
        const float b1 = __ldg(bias + col + 1);
        #pragma unroll
        for (int mi = 0; mi < 4; mi++) {
            int r0 = brow + wm + mi * 16 + g;
            if (r0 < NNODES) {
                __half2 o = __floats2half2_rn(fmaxf(acc[mi][ni][0] + b0, 0.f),
                                              fmaxf(acc[mi][ni][1] + b1, 0.f));
                *(__half2*)(C + (size_t)r0 * HID + col) = o;
            }
            int r1 = r0 + 8;
            if (r1 < NNODES) {
                __half2 o = __floats2half2_rn(fmaxf(acc[mi][ni][2] + b0, 0.f),
                                              fmaxf(acc[mi][ni][3] + b1, 0.f));
                *(__half2*)(C + (size_t)r1 * HID + col) = o;
            }
        }
    }
}

__global__ void __launch_bounds__(256, 2) k_gemm1(const float* __restrict__ b1)
{
    gemm_body<F_IN>(g_ax, g_w1h, b1, g_h1h);
}
__global__ void __launch_bounds__(256, 2) k_gemm2(const float* __restrict__ b2)
{
    gemm_body<HID>(g_a1, g_w2h, b2, g_h2h);
}

// ---------------- classifier: out[Nx40] = h2[Nx256] @ Wc[256x40] + bc --------
// h2 in fp16; 2 rows/thread; f32x2 FMA.
__global__ void __launch_bounds__(256) k_cls(const float* __restrict__ Wc,
                                             const float* __restrict__ bc,
                                             float* __restrict__ out)
{
    __shared__ float Ws[HID * NOUT];
    const int tid = threadIdx.x;
    for (int i = tid; i < HID * NOUT; i += 256) Ws[i] = Wc[i];
    __syncthreads();

    const int s  = tid >> 2;
    const int cg = (tid & 3) * 10;
    const int r0 = blockIdx.x * 128 + s;
    const int r1 = r0 + 64;
    const bool v0 = r0 < NNODES;
    const bool v1 = r1 < NNODES;
    if (!v0) return;

    const __half* h0 = g_h2h + (size_t)r0 * HID;
    const __half* h1 = g_h2h + (size_t)(v1 ? r1 : r0) * HID;

    unsigned long long acc0[5] = {0, 0, 0, 0, 0};
    unsigned long long acc1[5] = {0, 0, 0, 0, 0};

    for (int k = 0; k < HID; k += 8) {
        uint4 ua = *(const uint4*)(h0 + k);
        uint4 ub = *(const uint4*)(h1 + k);
        float a[8], b[8];
        {
            float2 t;
            t = __half22float2(*(const __half2*)&ua.x); a[0] = t.x; a[1] = t.y;
            t = __half22float2(*(const __half2*)&ua.y); a[2] = t.x; a[3] = t.y;
            t = __half22float2(*(const __half2*)&ua.z); a[4] = t.x; a[5] = t.y;
            t = __half22float2(*(const __half2*)&ua.w); a[6] = t.x; a[7] = t.y;
            t = __half22float2(*(const __half2*)&ub.x); b[0] = t.x; b[1] = t.y;
            t = __half22float2(*(const __half2*)&ub.y); b[2] = t.x; b[3] = t.y;
            t = __half22float2(*(const __half2*)&ub.z); b[4] = t.x; b[5] = t.y;
            t = __half22float2(*(const __half2*)&ub.w); b[6] = t.x; b[7] = t.y;
        }
        #pragma unroll
        for (int kk = 0; kk < 8; kk++) {
            unsigned long long hb0, hb1;
            asm("mov.b64 %0, {%1, %1};" : "=l"(hb0) : "r"(__float_as_uint(a[kk])));
            asm("mov.b64 %0, {%1, %1};" : "=l"(hb1) : "r"(__float_as_uint(b[kk])));
            const float* wrow = Ws + (k + kk) * NOUT + cg;
            #pragma unroll
            for (int j = 0; j < 5; j++) {
                unsigned long long w = *(const unsigned long long*)(wrow + 2 * j);
                asm("fma.rn.f32x2 %0, %1, %2, %0;" : "+l"(acc0[j]) : "l"(hb0), "l"(w));
                asm("fma.rn.f32x2 %0, %1, %2, %0;" : "+l"(acc1[j]) : "l"(hb1), "l"(w));
            }
        }
    }

    #pragma unroll
    for (int j = 0; j < 5; j++) {
        uint32_t lo, hi;
        float bcl = __ldg(bc + cg + 2 * j);
        float bch = __ldg(bc + cg + 2 * j + 1);
        asm("mov.b64 {%0, %1}, %2;" : "=r"(lo), "=r"(hi) : "l"(acc0[j]));
        out[(size_t)r0 * NOUT + cg + 2 * j]     = __uint_as_float(lo) + bcl;
        out[(size_t)r0 * NOUT + cg + 2 * j + 1] = __uint_as_float(hi) + bch;
        if (v1) {
            asm("mov.b64 {%0, %1}, %2;" : "=r"(lo), "=r"(hi) : "l"(acc1[j]));
            out[(size_t)r1 * NOUT + cg + 2 * j]     = __uint_as_float(lo) + bcl;
            out[(size_t)r1 * NOUT + cg + 2 * j + 1] = __uint_as_float(hi) + bch;
        }
    }
}

// ---------------- launch ------------------------------------------------------
extern "C" void kernel_launch(void* const* d_in, const int* in_sizes, int n_in,
                              void* d_out, int out_size)
{
    const float* x   = (const float*)d_in[0];
    const float* W1  = (const float*)d_in[1];
    const float* b1  = (const float*)d_in[2];
    const float* W2  = (const float*)d_in[3];
    const float* b2  = (const float*)d_in[4];
    const float* Wc  = (const float*)d_in[5];
    const float* bc  = (const float*)d_in[6];
    const int*   ei  = (const int*)  d_in[7];
    float*       out = (float*)d_out;

    cudaFuncSetAttribute(k_gemm1, cudaFuncAttributeMaxDynamicSharedMemorySize, GEMM_SMEM);
    cudaFuncSetAttribute(k_gemm2, cudaFuncAttributeMaxDynamicSharedMemorySize, GEMM_SMEM);

    // --- CSR build (scan-free offsets, single-atomic scatter) ---
    k_init   <<<(NNODES + 255) / 256, 256>>>();
    k_count  <<<(NEDGES + 255) / 256, 256>>>(ei);
    k_offsets<<<(NNODES + 255) / 256, 256>>>();
    k_scatter<<<(NEDGES + 255) / 256, 256>>>(ei);

    // --- weight transpose (fp16) + x fp16 conversion ---
    k_prepw<<<(HID * F_IN + HID * HID + 255) / 256, 256>>>(W1, W2);
    k_prepx<<<(NNODES * F_IN / 4 + 255) / 256, 256>>>(x);

    dim3 gemmGrid(HID / 128, MTILES);

    // --- layer 1: relu(agg(x) @ W1 + b1) -> fp16 h1 ---
    k_agg_x<<<(NNODES * 32 + 255) / 256, 256>>>();
    k_gemm1<<<gemmGrid, 256, GEMM_SMEM>>>(b1);

    // --- layer 2: relu(agg(h1) @ W2 + b2) -> fp16 h2 (2 warps/node agg) ---
    k_agg_h1<<<(NNODES * 2 * 32 + 255) / 256, 256>>>();
    k_gemm2<<<gemmGrid, 256, GEMM_SMEM>>>(b2);

    // --- classifier ---
    k_cls<<<MTILES, 256>>>(Wc, bc, out);
}

// round 14
// speedup vs baseline: 1.6264x; 1.0043x over previous
#include <cuda_runtime.h>
#include <cuda_fp16.h>
#include <cstdint>

#define NNODES 50000
#define NODPAD 50048
#define NEDGES 800000
#define F_IN   128
#define HID    256
#define NOUT   40
#define MTILES (NODPAD / 128)   // 391

// ---------------- scratch (static device memory, no allocations) ------------
__device__ int   g_cnt[NNODES];
__device__ int   g_off[NNODES];
__device__ int   g_rank[NEDGES];                 // edge rank within its dst
__device__ int   g_total;
__device__ float g_dinv[NNODES];
__device__ __align__(16) int2 g_edge[NEDGES];    // (src, weight bits)
__device__ __align__(16) __half g_xh[(size_t)NNODES * F_IN];     // fp16 x
__device__ __align__(16) __half g_h1h[(size_t)NNODES * HID];     // fp16 h1
__device__ __align__(16) __half g_ax[(size_t)NODPAD * F_IN];     // agg(x) fp16
__device__ __align__(16) __half g_a1[(size_t)NODPAD * HID];      // agg(h1) fp16
__device__ __align__(16) __half g_h2h[(size_t)NNODES * HID];     // fp16 h2
__device__ __align__(16) __half g_w1h[HID * F_IN];               // W1^T fp16
__device__ __align__(16) __half g_w2h[HID * HID];                // W2^T fp16

// ---------------- fused prep: zero counters + weight transpose + x->fp16 -----
__global__ void k_prep(const float* __restrict__ x,
                       const float* __restrict__ W1,
                       const float* __restrict__ W2)
{
    int i = blockIdx.x * blockDim.x + threadIdx.x;
    if (i == 0) g_total = 0;
    if (i < NNODES) g_cnt[i] = 0;
    if (i < HID * F_IN) {
        int n = i / F_IN, k = i % F_IN;
        g_w1h[i] = __float2half_rn(W1[k * HID + n]);
    }
    if (i < HID * HID) {
        int n = i / HID, k = i % HID;
        g_w2h[i] = __float2half_rn(W2[k * HID + n]);
    }
    if (i < NNODES * F_IN / 4) {
        float4 v = ((const float4*)x)[i];
        __half2 a = __floats2half2_rn(v.x, v.y);
        __half2 b = __floats2half2_rn(v.z, v.w);
        uint2 u;
        u.x = *(uint32_t*)&a; u.y = *(uint32_t*)&b;
        ((uint2*)g_xh)[i] = u;
    }
}

// count + record per-edge rank (atomicAdd return value)
__global__ void k_count(const int* __restrict__ ei)
{
    int e = blockIdx.x * blockDim.x + threadIdx.x;
    if (e >= NEDGES) return;
    int d = ei[NEDGES + e];
    g_rank[e] = atomicAdd(&g_cnt[d], 1);
}

// warp-aggregated offsets: shfl scan + 1 atomic per warp
__global__ void k_offsets()
{
    int i = blockIdx.x * blockDim.x + threadIdx.x;
    int lane = threadIdx.x & 31;
    int c = (i < NNODES) ? g_cnt[i] : 0;
    int sum = c;
    #pragma unroll
    for (int o = 1; o < 32; o <<= 1) {
        int t = __shfl_up_sync(0xFFFFFFFF, sum, o);
        if (lane >= o) sum += t;
    }
    int wtotal = __shfl_sync(0xFFFFFFFF, sum, 31);
    int base;
    if (lane == 31) base = atomicAdd(&g_total, wtotal);
    base = __shfl_sync(0xFFFFFFFF, base, 31);
    if (i < NNODES) {
        g_off[i]  = base + sum - c;
        g_dinv[i] = rsqrtf((float)(c + 1));
    }
}

// atomic-free scatter: pos = off[dst] + rank[e]
__global__ void k_scatter(const int* __restrict__ ei)
{
    int e = blockIdx.x * blockDim.x + threadIdx.x;
    if (e >= NEDGES) return;
    int s = ei[e];
    int d = ei[NEDGES + e];
    float w = g_dinv[s] * g_dinv[d];
    int pos = g_off[d] + g_rank[e];
    g_edge[pos] = make_int2(s, __float_as_int(w));
}

// ---------------- sparse aggregation ----------------------------------------
// F/128 warps per node; each warp owns a 128-feature slice (uint2 per lane).
// 8 edges in flight; fp32 accum; fp16 output.
template <int F>
__device__ __forceinline__ void agg_impl(const __half* __restrict__ in,
                                         __half* __restrict__ outp)
{
    constexpr int WPN = F / 128;
    const int gw   = (blockIdx.x * blockDim.x + threadIdx.x) >> 5;
    const int node = gw / WPN;
    const int slc  = gw - node * WPN;
    const int lane = threadIdx.x & 31;
    if (node >= NNODES) return;

    const int coff = slc * 128 + 4 * lane;   // half offset within a row

    float4 acc;
    const float dn = g_dinv[node];
    const float w0 = dn * dn;
    {
        uint2 u = __ldg((const uint2*)(in + (size_t)node * F + coff));
        float2 f0 = __half22float2(*(const __half2*)&u.x);
        float2 f1 = __half22float2(*(const __half2*)&u.y);
        acc.x = w0 * f0.x; acc.y = w0 * f0.y;
        acc.z = w0 * f1.x; acc.w = w0 * f1.y;
    }

    const int beg = g_off[node];
    const int end = beg + g_cnt[node];
    int i = beg;
    for (; i + 8 <= end; i += 8) {
        int2 e[8];
        #pragma unroll
        for (int q = 0; q < 8; q++) e[q] = g_edge[i + q];
        uint2 u[8];
        #pragma unroll
        for (int q = 0; q < 8; q++)
            u[q] = __ldg((const uint2*)(in + (size_t)e[q].x * F + coff));
        #pragma unroll
        for (int q = 0; q < 8; q++) {
            const float we = __int_as_float(e[q].y);
            float2 f0 = __half22float2(*(const __half2*)&u[q].x);
            float2 f1 = __half22float2(*(const __half2*)&u[q].y);
            acc.x += we * f0.x; acc.y += we * f0.y;
            acc.z += we * f1.x; acc.w += we * f1.y;
        }
    }
    for (; i + 4 <= end; i += 4) {
        int2 e[4];
        #pragma unroll
        for (int q = 0; q < 4; q++) e[q] = g_edge[i + q];
        uint2 u[4];
        #pragma unroll
        for (int q = 0; q < 4; q++)
            u[q] = __ldg((const uint2*)(in + (size_t)e[q].x * F + coff));
        #pragma unroll
        for (int q = 0; q < 4; q++) {
            const float we = __int_as_float(e[q].y);
            float2 f0 = __half22float2(*(const __half2*)&u[q].x);
            float2 f1 = __half22float2(*(const __half2*)&u[q].y);
            acc.x += we * f0.x; acc.y += we * f0.y;
            acc.z += we * f1.x; acc.w += we * f1.y;
        }
    }
    for (; i < end; i++) {
        const int2 e0 = g_edge[i];
        const float we = __int_as_float(e0.y);
        uint2 u0 = __ldg((const uint2*)(in + (size_t)e0.x * F + coff));
        float2 f0 = __half22float2(*(const __half2*)&u0.x);
        float2 f1 = __half22float2(*(const __half2*)&u0.y);
        acc.x += we * f0.x; acc.y += we * f0.y;
        acc.z += we * f1.x; acc.w += we * f1.y;
    }

    __half2 p0 = __floats2half2_rn(acc.x, acc.y);
    __half2 p1 = __floats2half2_rn(acc.z, acc.w);
    uint2 u;
    u.x = *(uint32_t*)&p0; u.y = *(uint32_t*)&p1;
    *(uint2*)(outp + (size_t)node * F + coff) = u;
}

__global__ void k_agg_x()  { agg_impl<F_IN>(g_xh,  g_ax); }
__global__ void k_agg_h1() { agg_impl<HID>(g_h1h, g_a1); }

// ---------------- fp16 HMMA GEMM: C = relu(A @ B^T + bias) -------------------
// Block 128x128, 8 warps of 64x32. 3-stage cp.async pipeline, ONE sync/iter,
// 2 blocks/SM. Output fp16.
#define SROWB 80
#define T_STG (128 * SROWB)
#define GEMM_SMEM (6 * T_STG)                // 61440 B

template <int F>
__device__ __forceinline__ void gemm_body(const __half* __restrict__ A,
                                          const __half* __restrict__ B,
                                          const float* __restrict__ bias,
                                          __half* __restrict__ C)
{
    extern __shared__ __align__(16) uint8_t smem_dyn[];
    uint32_t sA;
    asm("{ .reg .u64 t; cvta.to.shared.u64 t, %1; cvt.u32.u64 %0, t; }"
        : "=r"(sA) : "l"(&smem_dyn[0]));
    const uint32_t sB = sA + 3 * T_STG;

    const int tid  = threadIdx.x;
    const int lane = tid & 31;
    const int wid  = tid >> 5;
    const int g    = lane >> 2;
    const int tg   = lane & 3;
    const int wm   = (wid & 1) * 64;
    const int wn   = (wid >> 1) * 32;
    const int brow = blockIdx.y * 128;
    const int bcol = blockIdx.x * 128;

    float acc[4][4][4];
    #pragma unroll
    for (int mi = 0; mi < 4; mi++)
        #pragma unroll
        for (int ni = 0; ni < 4; ni++)
            #pragma unroll
            for (int c = 0; c < 4; c++) acc[mi][ni][c] = 0.f;

    const int lrow = tid >> 2;
    const int lseg = tid & 3;
    auto load_stage = [&](int st, int k0) {
        #pragma unroll
        for (int i = 0; i < 2; i++) {
            int row = lrow + i * 64;
            uint32_t soA = sA + (uint32_t)st * T_STG + row * SROWB + lseg * 16;
            const __half* ga = A + (size_t)(brow + row) * F + k0 + lseg * 8;
            asm volatile("cp.async.cg.shared.global [%0], [%1], 16;"
                         :: "r"(soA), "l"(ga));
            uint32_t soB = sB + (uint32_t)st * T_STG + row * SROWB + lseg * 16;
            const __half* gb = B + (size_t)(bcol + row) * F + k0 + lseg * 8;
            asm volatile("cp.async.cg.shared.global [%0], [%1], 16;"
                         :: "r"(soB), "l"(gb));
        }
        asm volatile("cp.async.commit_group;");
    };

    constexpr int NK = F / 32;
    load_stage(0, 0);
    load_stage(1, 32);

    const int lr  = lane & 15;
    const int lhi = (lane >> 4) * 16;

    int st = 0;
    for (int ki = 0; ki < NK; ki++) {
        if (ki + 1 < NK) {
            asm volatile("cp.async.wait_group 1;");
        } else {
            asm volatile("cp.async.wait_group 0;");
        }
        __syncthreads();
        if (ki + 2 < NK) {
            int st2 = st + 2; if (st2 >= 3) st2 -= 3;
            load_stage(st2, (ki + 2) * 32);
        }

        const uint32_t bufA = sA + st * T_STG;
        const uint32_t bufB = sB + st * T_STG;

        #pragma unroll
        for (int kk = 0; kk < 2; kk++) {
            const uint32_t kb = kk * 32;
            uint32_t af[4][4];
            #pragma unroll
            for (int mi = 0; mi < 4; mi++) {
                uint32_t addr = bufA + (wm + mi * 16 + lr) * SROWB + kb + lhi;
                asm volatile("ldmatrix.sync.aligned.m8n8.x4.shared.b16 {%0,%1,%2,%3}, [%4];"
                             : "=r"(af[mi][0]), "=r"(af[mi][1]),
                               "=r"(af[mi][2]), "=r"(af[mi][3]) : "r"(addr));
            }
            #pragma unroll
            for (int p = 0; p < 2; p++) {
                uint32_t r0, r1, r2, r3;
                uint32_t addr = bufB + (wn + p * 16 + lr) * SROWB + kb + lhi;
                asm volatile("ldmatrix.sync.aligned.m8n8.x4.shared.b16 {%0,%1,%2,%3}, [%4];"
                             : "=r"(r0), "=r"(r1), "=r"(r2), "=r"(r3) : "r"(addr));
                #pragma unroll
                for (int mi = 0; mi < 4; mi++) {
                    asm volatile(
                        "mma.sync.aligned.m16n8k16.row.col.f32.f16.f16.f32 "
                        "{%0,%1,%2,%3},{%4,%5,%6,%7},{%8,%9},{%0,%1,%2,%3};"
                        : "+f"(acc[mi][2 * p][0]), "+f"(acc[mi][2 * p][1]),
                          "+f"(acc[mi][2 * p][2]), "+f"(acc[mi][2 * p][3])
                        : "r"(af[mi][0]), "r"(af[mi][1]), "r"(af[mi][2]), "r"(af[mi][3]),
                          "r"(r0), "r"(r2));
                    asm volatile(
                        "mma.sync.aligned.m16n8k16.row.col.f32.f16.f16.f32 "
                        "{%0,%1,%2,%3},{%4,%5,%6,%7},{%8,%9},{%0,%1,%2,%3};"
                        : "+f"(acc[mi][2 * p + 1][0]), "+f"(acc[mi][2 * p + 1][1]),
                          "+f"(acc[mi][2 * p + 1][2]), "+f"(acc[mi][2 * p + 1][3])
                        : "r"(af[mi][0]), "r"(af[mi][1]), "r"(af[mi][2]), "r"(af[mi][3]),
                          "r"(r1), "r"(r3));
                }
            }
        }
        if (++st == 3) st = 0;
    }

    // ---- epilogue: bias + relu, fp16 store ----
    #pragma unroll
    for (int ni = 0; ni < 4; ni++) {
        const int col = bcol + wn + ni * 8 + tg * 2;
        const float b0 = __ldg(bias + col);
        const float b1 = __ldg(bias + col + 1);
        #pragma unroll
        for (int mi = 0; mi < 4; mi++) {
            int r0 = brow + wm + mi * 16 + g;
            if (r0 < NNODES) {
                __half2 o = __floats2half2_rn(fmaxf(acc[mi][ni][0] + b0, 0.f),
                                              fmaxf(acc[mi][ni][1] + b1, 0.f));
                *(__half2*)(C + (size_t)r0 * HID + col) = o;
            }
            int r1 = r0 + 8;
            if (r1 < NNODES) {
                __half2 o = __floats2half2_rn(fmaxf(acc[mi][ni][2] + b0, 0.f),
                                              fmaxf(acc[mi][ni][3] + b1, 0.f));
                *(__half2*)(C + (size_t)r1 * HID + col) = o;
            }
        }
    }
}

__global__ void __launch_bounds__(256, 2) k_gemm1(const float* __restrict__ b1)
{
    gemm_body<F_IN>(g_ax, g_w1h, b1, g_h1h);
}
__global__ void __launch_bounds__(256, 2) k_gemm2(const float* __restrict__ b2)
{
    gemm_body<HID>(g_a1, g_w2h, b2, g_h2h);
}

// ---------------- classifier: out[Nx40] = h2[Nx256] @ Wc[256x40] + bc --------
__global__ void __launch_bounds__(256) k_cls(const float* __restrict__ Wc,
                                             const float* __restrict__ bc,
                                             float* __restrict__ out)
{
    __shared__ float Ws[HID * NOUT];
    const int tid = threadIdx.x;
    for (int i = tid; i < HID * NOUT; i += 256) Ws[i] = Wc[i];
    __syncthreads();

    const int s  = tid >> 2;
    const int cg = (tid & 3) * 10;
    const int r0 = blockIdx.x * 128 + s;
    const int r1 = r0 + 64;
    const bool v0 = r0 < NNODES;
    const bool v1 = r1 < NNODES;
    if (!v0) return;

    const __half* h0 = g_h2h + (size_t)r0 * HID;
    const __half* h1 = g_h2h + (size_t)(v1 ? r1 : r0) * HID;

    unsigned long long acc0[5] = {0, 0, 0, 0, 0};
    unsigned long long acc1[5] = {0, 0, 0, 0, 0};

    for (int k = 0; k < HID; k += 8) {
        uint4 ua = *(const uint4*)(h0 + k);
        uint4 ub = *(const uint4*)(h1 + k);
        float a[8], b[8];
        {
            float2 t;
            t = __half22float2(*(const __half2*)&ua.x); a[0] = t.x; a[1] = t.y;
            t = __half22float2(*(const __half2*)&ua.y); a[2] = t.x; a[3] = t.y;
            t = __half22float2(*(const __half2*)&ua.z); a[4] = t.x; a[5] = t.y;
            t = __half22float2(*(const __half2*)&ua.w); a[6] = t.x; a[7] = t.y;
            t = __half22float2(*(const __half2*)&ub.x); b[0] = t.x; b[1] = t.y;
            t = __half22float2(*(const __half2*)&ub.y); b[2] = t.x; b[3] = t.y;
            t = __half22float2(*(const __half2*)&ub.z); b[4] = t.x; b[5] = t.y;
            t = __half22float2(*(const __half2*)&ub.w); b[6] = t.x; b[7] = t.y;
        }
        #pragma unroll
        for (int kk = 0; kk < 8; kk++) {
            unsigned long long hb0, hb1;
            asm("mov.b64 %0, {%1, %1};" : "=l"(hb0) : "r"(__float_as_uint(a[kk])));
            asm("mov.b64 %0, {%1, %1};" : "=l"(hb1) : "r"(__float_as_uint(b[kk])));
            const float* wrow = Ws + (k + kk) * NOUT + cg;
            #pragma unroll
            for (int j = 0; j < 5; j++) {
                unsigned long long w = *(const unsigned long long*)(wrow + 2 * j);
                asm("fma.rn.f32x2 %0, %1, %2, %0;" : "+l"(acc0[j]) : "l"(hb0), "l"(w));
                asm("fma.rn.f32x2 %0, %1, %2, %0;" : "+l"(acc1[j]) : "l"(hb1), "l"(w));
            }
        }
    }

    #pragma unroll
    for (int j = 0; j < 5; j++) {
        uint32_t lo, hi;
        float bcl = __ldg(bc + cg + 2 * j);
        float bch = __ldg(bc + cg + 2 * j + 1);
        asm("mov.b64 {%0, %1}, %2;" : "=r"(lo), "=r"(hi) : "l"(acc0[j]));
        out[(size_t)r0 * NOUT + cg + 2 * j]     = __uint_as_float(lo) + bcl;
        out[(size_t)r0 * NOUT + cg + 2 * j + 1] = __uint_as_float(hi) + bch;
        if (v1) {
            asm("mov.b64 {%0, %1}, %2;" : "=r"(lo), "=r"(hi) : "l"(acc1[j]));
            out[(size_t)r1 * NOUT + cg + 2 * j]     = __uint_as_float(lo) + bcl;
            out[(size_t)r1 * NOUT + cg + 2 * j + 1] = __uint_as_float(hi) + bch;
        }
    }
}

// ---------------- launch ------------------------------------------------------
extern "C" void kernel_launch(void* const* d_in, const int* in_sizes, int n_in,
                              void* d_out, int out_size)
{
    const float* x   = (const float*)d_in[0];
    const float* W1  = (const float*)d_in[1];
    const float* b1  = (const float*)d_in[2];
    const float* W2  = (const float*)d_in[3];
    const float* b2  = (const float*)d_in[4];
    const float* Wc  = (const float*)d_in[5];
    const float* bc  = (const float*)d_in[6];
    const int*   ei  = (const int*)  d_in[7];
    float*       out = (float*)d_out;

    cudaFuncSetAttribute(k_gemm1, cudaFuncAttributeMaxDynamicSharedMemorySize, GEMM_SMEM);
    cudaFuncSetAttribute(k_gemm2, cudaFuncAttributeMaxDynamicSharedMemorySize, GEMM_SMEM);

    // fused prep: zero counters, transpose weights, convert x (grid = prepx size)
    const int prepN = NNODES * F_IN / 4;   // 1.6M threads, covers all sub-tasks
    k_prep<<<(prepN + 255) / 256, 256>>>(x, W1, W2);

    // CSR build: count(+rank) -> warp-scan offsets -> atomic-free scatter
    k_count  <<<(NEDGES + 255) / 256, 256>>>(ei);
    k_offsets<<<(NNODES + 255) / 256, 256>>>();
    k_scatter<<<(NEDGES + 255) / 256, 256>>>(ei);

    dim3 gemmGrid(HID / 128, MTILES);

    // layer 1: relu(agg(x) @ W1 + b1) -> fp16 h1
    k_agg_x<<<(NNODES * 32 + 255) / 256, 256>>>();
    k_gemm1<<<gemmGrid, 256, GEMM_SMEM>>>(b1);

    // layer 2: relu(agg(h1) @ W2 + b2) -> fp16 h2 (2 warps/node agg)
    k_agg_h1<<<(NNODES * 2 * 32 + 255) / 256, 256>>>();
    k_gemm2<<<gemmGrid, 256, GEMM_SMEM>>>(b2);

    // classifier
    k_cls<<<MTILES, 256>>>(Wc, bc, out);
}

// round 15
// speedup vs baseline: 1.9837x; 1.2197x over previous
#include <cuda_runtime.h>
#include <cuda_fp16.h>
#include <cstdint>

#define NNODES 50000
#define NODPAD 50048
#define NEDGES 800000
#define F_IN   128
#define HID    256
#define NOUT   40
#define MTILES (NODPAD / 128)   // 391

// ---------------- scratch (static device memory, no allocations) ------------
__device__ int   g_cnt[NNODES];
__device__ int   g_off[NNODES];
__device__ int   g_rank[NEDGES];                 // edge rank within its dst
__device__ int   g_total;
__device__ float g_dinv[NNODES];
__device__ __align__(16) int2 g_edge[NEDGES];    // (src, weight bits)
__device__ __align__(16) __half g_xh[(size_t)NNODES * F_IN];     // fp16 x
__device__ __align__(16) __half g_h1h[(size_t)NNODES * HID];     // fp16 h1
__device__ __align__(16) __half g_ax[(size_t)NODPAD * F_IN];     // agg(x) fp16
__device__ __align__(16) __half g_a1[(size_t)NODPAD * HID];      // agg(h1) fp16
__device__ __align__(16) __half g_w1h[HID * F_IN];               // W1^T fp16
__device__ __align__(16) __half g_w2h[HID * HID];                // W2^T fp16
__device__ __align__(16) __half g_wchi[NOUT * HID];              // Wc^T hi fp16
__device__ __align__(16) __half g_wclo[NOUT * HID];              // Wc^T lo fp16

// ---------------- fused prep ---------------------------------------------------
__global__ void k_prep(const float* __restrict__ x,
                       const float* __restrict__ W1,
                       const float* __restrict__ W2,
                       const float* __restrict__ Wc)
{
    int i = blockIdx.x * blockDim.x + threadIdx.x;
    if (i == 0) g_total = 0;
    if (i < NNODES) g_cnt[i] = 0;
    if (i < HID * F_IN) {
        int n = i / F_IN, k = i % F_IN;
        g_w1h[i] = __float2half_rn(W1[k * HID + n]);
    }
    if (i < HID * HID) {
        int n = i / HID, k = i % HID;
        g_w2h[i] = __float2half_rn(W2[k * HID + n]);
    }
    if (i < NOUT * HID) {
        int n = i / HID, k = i % HID;
        float v = Wc[k * NOUT + n];
        __half h = __float2half_rn(v);
        g_wchi[i] = h;
        g_wclo[i] = __float2half_rn(v - __half2float(h));
    }
    if (i < NNODES * F_IN / 4) {
        float4 v = ((const float4*)x)[i];
        __half2 a = __floats2half2_rn(v.x, v.y);
        __half2 b = __floats2half2_rn(v.z, v.w);
        uint2 u;
        u.x = *(uint32_t*)&a; u.y = *(uint32_t*)&b;
        ((uint2*)g_xh)[i] = u;
    }
}

__global__ void k_count(const int* __restrict__ ei)
{
    int e = blockIdx.x * blockDim.x + threadIdx.x;
    if (e >= NEDGES) return;
    int d = ei[NEDGES + e];
    g_rank[e] = atomicAdd(&g_cnt[d], 1);
}

__global__ void k_offsets()
{
    int i = blockIdx.x * blockDim.x + threadIdx.x;
    int lane = threadIdx.x & 31;
    int c = (i < NNODES) ? g_cnt[i] : 0;
    int sum = c;
    #pragma unroll
    for (int o = 1; o < 32; o <<= 1) {
        int t = __shfl_up_sync(0xFFFFFFFF, sum, o);
        if (lane >= o) sum += t;
    }
    int wtotal = __shfl_sync(0xFFFFFFFF, sum, 31);
    int base;
    if (lane == 31) base = atomicAdd(&g_total, wtotal);
    base = __shfl_sync(0xFFFFFFFF, base, 31);
    if (i < NNODES) {
        g_off[i]  = base + sum - c;
        g_dinv[i] = rsqrtf((float)(c + 1));
    }
}

__global__ void k_scatter(const int* __restrict__ ei)
{
    int e = blockIdx.x * blockDim.x + threadIdx.x;
    if (e >= NEDGES) return;
    int s = ei[e];
    int d = ei[NEDGES + e];
    float w = g_dinv[s] * g_dinv[d];
    int pos = g_off[d] + g_rank[e];
    g_edge[pos] = make_int2(s, __float_as_int(w));
}

// ---------------- sparse aggregation ----------------------------------------
template <int F>
__device__ __forceinline__ void agg_impl(const __half* __restrict__ in,
                                         __half* __restrict__ outp)
{
    constexpr int WPN = F / 128;
    const int gw   = (blockIdx.x * blockDim.x + threadIdx.x) >> 5;
    const int node = gw / WPN;
    const int slc  = gw - node * WPN;
    const int lane = threadIdx.x & 31;
    if (node >= NNODES) return;

    const int coff = slc * 128 + 4 * lane;

    float4 acc;
    const float dn = g_dinv[node];
    const float w0 = dn * dn;
    {
        uint2 u = __ldg((const uint2*)(in + (size_t)node * F + coff));
        float2 f0 = __half22float2(*(const __half2*)&u.x);
        float2 f1 = __half22float2(*(const __half2*)&u.y);
        acc.x = w0 * f0.x; acc.y = w0 * f0.y;
        acc.z = w0 * f1.x; acc.w = w0 * f1.y;
    }

    const int beg = g_off[node];
    const int end = beg + g_cnt[node];
    int i = beg;
    for (; i + 8 <= end; i += 8) {
        int2 e[8];
        #pragma unroll
        for (int q = 0; q < 8; q++) e[q] = g_edge[i + q];
        uint2 u[8];
        #pragma unroll
        for (int q = 0; q < 8; q++)
            u[q] = __ldg((const uint2*)(in + (size_t)e[q].x * F + coff));
        #pragma unroll
        for (int q = 0; q < 8; q++) {
            const float we = __int_as_float(e[q].y);
            float2 f0 = __half22float2(*(const __half2*)&u[q].x);
            float2 f1 = __half22float2(*(const __half2*)&u[q].y);
            acc.x += we * f0.x; acc.y += we * f0.y;
            acc.z += we * f1.x; acc.w += we * f1.y;
        }
    }
    for (; i + 4 <= end; i += 4) {
        int2 e[4];
        #pragma unroll
        for (int q = 0; q < 4; q++) e[q] = g_edge[i + q];
        uint2 u[4];
        #pragma unroll
        for (int q = 0; q < 4; q++)
            u[q] = __ldg((const uint2*)(in + (size_t)e[q].x * F + coff));
        #pragma unroll
        for (int q = 0; q < 4; q++) {
            const float we = __int_as_float(e[q].y);
            float2 f0 = __half22float2(*(const __half2*)&u[q].x);
            float2 f1 = __half22float2(*(const __half2*)&u[q].y);
            acc.x += we * f0.x; acc.y += we * f0.y;
            acc.z += we * f1.x; acc.w += we * f1.y;
        }
    }
    for (; i < end; i++) {
        const int2 e0 = g_edge[i];
        const float we = __int_as_float(e0.y);
        uint2 u0 = __ldg((const uint2*)(in + (size_t)e0.x * F + coff));
        float2 f0 = __half22float2(*(const __half2*)&u0.x);
        float2 f1 = __half22float2(*(const __half2*)&u0.y);
        acc.x += we * f0.x; acc.y += we * f0.y;
        acc.z += we * f1.x; acc.w += we * f1.y;
    }

    __half2 p0 = __floats2half2_rn(acc.x, acc.y);
    __half2 p1 = __floats2half2_rn(acc.z, acc.w);
    uint2 u;
    u.x = *(uint32_t*)&p0; u.y = *(uint32_t*)&p1;
    *(uint2*)(outp + (size_t)node * F + coff) = u;
}

__global__ void k_agg_x()  { agg_impl<F_IN>(g_xh,  g_ax); }
__global__ void k_agg_h1() { agg_impl<HID>(g_h1h, g_a1); }

// ---------------- GEMM1: 128x128 tile, 3-stage, 2 blocks/SM (unchanged core) --
#define SROWB 80
#define T_STG (128 * SROWB)
#define GEMM_SMEM (6 * T_STG)                // 61440 B

__global__ void __launch_bounds__(256, 2) k_gemm1(const float* __restrict__ bias)
{
    constexpr int F = F_IN;
    const __half* A = g_ax;
    const __half* B = g_w1h;
    __half* C = g_h1h;

    extern __shared__ __align__(16) uint8_t smem_dyn[];
    uint32_t sA;
    asm("{ .reg .u64 t; cvta.to.shared.u64 t, %1; cvt.u32.u64 %0, t; }"
        : "=r"(sA) : "l"(&smem_dyn[0]));
    const uint32_t sB = sA + 3 * T_STG;

    const int tid  = threadIdx.x;
    const int lane = tid & 31;
    const int wid  = tid >> 5;
    const int g    = lane >> 2;
    const int tg   = lane & 3;
    const int wm   = (wid & 1) * 64;
    const int wn   = (wid >> 1) * 32;
    const int brow = blockIdx.y * 128;
    const int bcol = blockIdx.x * 128;

    float acc[4][4][4];
    #pragma unroll
    for (int mi = 0; mi < 4; mi++)
        #pragma unroll
        for (int ni = 0; ni < 4; ni++)
            #pragma unroll
            for (int c = 0; c < 4; c++) acc[mi][ni][c] = 0.f;

    const int lrow = tid >> 2;
    const int lseg = tid & 3;
    auto load_stage = [&](int st, int k0) {
        #pragma unroll
        for (int i = 0; i < 2; i++) {
            int row = lrow + i * 64;
            uint32_t soA = sA + (uint32_t)st * T_STG + row * SROWB + lseg * 16;
            const __half* ga = A + (size_t)(brow + row) * F + k0 + lseg * 8;
            asm volatile("cp.async.cg.shared.global [%0], [%1], 16;"
                         :: "r"(soA), "l"(ga));
            uint32_t soB = sB + (uint32_t)st * T_STG + row * SROWB + lseg * 16;
            const __half* gb = B + (size_t)(bcol + row) * F + k0 + lseg * 8;
            asm volatile("cp.async.cg.shared.global [%0], [%1], 16;"
                         :: "r"(soB), "l"(gb));
        }
        asm volatile("cp.async.commit_group;");
    };

    constexpr int NK = F / 32;
    load_stage(0, 0);
    load_stage(1, 32);

    const int lr  = lane & 15;
    const int lhi = (lane >> 4) * 16;

    int st = 0;
    for (int ki = 0; ki < NK; ki++) {
        if (ki + 1 < NK) asm volatile("cp.async.wait_group 1;");
        else             asm volatile("cp.async.wait_group 0;");
        __syncthreads();
        if (ki + 2 < NK) {
            int st2 = st + 2; if (st2 >= 3) st2 -= 3;
            load_stage(st2, (ki + 2) * 32);
        }
        const uint32_t bufA = sA + st * T_STG;
        const uint32_t bufB = sB + st * T_STG;

        #pragma unroll
        for (int kk = 0; kk < 2; kk++) {
            const uint32_t kb = kk * 32;
            uint32_t af[4][4];
            #pragma unroll
            for (int mi = 0; mi < 4; mi++) {
                uint32_t addr = bufA + (wm + mi * 16 + lr) * SROWB + kb + lhi;
                asm volatile("ldmatrix.sync.aligned.m8n8.x4.shared.b16 {%0,%1,%2,%3}, [%4];"
                             : "=r"(af[mi][0]), "=r"(af[mi][1]),
                               "=r"(af[mi][2]), "=r"(af[mi][3]) : "r"(addr));
            }
            #pragma unroll
            for (int p = 0; p < 2; p++) {
                uint32_t r0, r1, r2, r3;
                uint32_t addr = bufB + (wn + p * 16 + lr) * SROWB + kb + lhi;
                asm volatile("ldmatrix.sync.aligned.m8n8.x4.shared.b16 {%0,%1,%2,%3}, [%4];"
                             : "=r"(r0), "=r"(r1), "=r"(r2), "=r"(r3) : "r"(addr));
                #pragma unroll
                for (int mi = 0; mi < 4; mi++) {
                    asm volatile(
                        "mma.sync.aligned.m16n8k16.row.col.f32.f16.f16.f32 "
                        "{%0,%1,%2,%3},{%4,%5,%6,%7},{%8,%9},{%0,%1,%2,%3};"
                        : "+f"(acc[mi][2 * p][0]), "+f"(acc[mi][2 * p][1]),
                          "+f"(acc[mi][2 * p][2]), "+f"(acc[mi][2 * p][3])
                        : "r"(af[mi][0]), "r"(af[mi][1]), "r"(af[mi][2]), "r"(af[mi][3]),
                          "r"(r0), "r"(r2));
                    asm volatile(
                        "mma.sync.aligned.m16n8k16.row.col.f32.f16.f16.f32 "
                        "{%0,%1,%2,%3},{%4,%5,%6,%7},{%8,%9},{%0,%1,%2,%3};"
                        : "+f"(acc[mi][2 * p + 1][0]), "+f"(acc[mi][2 * p + 1][1]),
                          "+f"(acc[mi][2 * p + 1][2]), "+f"(acc[mi][2 * p + 1][3])
                        : "r"(af[mi][0]), "r"(af[mi][1]), "r"(af[mi][2]), "r"(af[mi][3]),
                          "r"(r1), "r"(r3));
                }
            }
        }
        if (++st == 3) st = 0;
    }

    #pragma unroll
    for (int ni = 0; ni < 4; ni++) {
        const int col = bcol + wn + ni * 8 + tg * 2;
        const float b0 = __ldg(bias + col);
        const float b1 = __ldg(bias + col + 1);
        #pragma unroll
        for (int mi = 0; mi < 4; mi++) {
            int r0 = brow + wm + mi * 16 + g;
            if (r0 < NNODES) {
                __half2 o = __floats2half2_rn(fmaxf(acc[mi][ni][0] + b0, 0.f),
                                              fmaxf(acc[mi][ni][1] + b1, 0.f));
                *(__half2*)(C + (size_t)r0 * HID + col) = o;
            }
            int r1 = r0 + 8;
            if (r1 < NNODES) {
                __half2 o = __floats2half2_rn(fmaxf(acc[mi][ni][2] + b0, 0.f),
                                              fmaxf(acc[mi][ni][3] + b1, 0.f));
                *(__half2*)(C + (size_t)r1 * HID + col) = o;
            }
        }
    }
}

// ---------------- GEMM2 + classifier fused -----------------------------------
// 128x256 block (BN = HID). Mainloop: 3-stage cp.async, acc[4][8][4].
// Epilogue: h2 tile -> smem fp16 (528B stride), then HMMA out = h2 @ Wc^T
// with Wc hi/lo split (fp32-accurate), direct store to out.
#define A_STG2 10240                  // 128*80
#define B_STG2 20480                  // 256*80
#define H2ROWB 528                    // 264 halves per row
#define H2S_OFF 0
#define WHI_OFF (128 * H2ROWB)        // 67584
#define WLO_OFF (WHI_OFF + 64 * H2ROWB)  // 101376
#define GEMM2_SMEM (WLO_OFF + 64 * H2ROWB)  // 135168

__global__ void __launch_bounds__(256) k_gemm2f(const float* __restrict__ b2,
                                                const float* __restrict__ bc,
                                                float* __restrict__ out)
{
    constexpr int F = HID;
    const __half* A = g_a1;
    const __half* B = g_w2h;

    extern __shared__ __align__(16) uint8_t smem_dyn[];
    uint32_t sbase;
    asm("{ .reg .u64 t; cvta.to.shared.u64 t, %1; cvt.u32.u64 %0, t; }"
        : "=r"(sbase) : "l"(&smem_dyn[0]));
    const uint32_t sA = sbase;
    const uint32_t sB = sbase + 3 * A_STG2;

    const int tid  = threadIdx.x;
    const int lane = tid & 31;
    const int wid  = tid >> 5;
    const int g    = lane >> 2;
    const int tg   = lane & 3;
    const int wm   = (wid & 1) * 64;
    const int wn   = (wid >> 1) * 64;
    const int brow = blockIdx.x * 128;

    float acc[4][8][4];
    #pragma unroll
    for (int mi = 0; mi < 4; mi++)
        #pragma unroll
        for (int ni = 0; ni < 8; ni++)
            #pragma unroll
            for (int c = 0; c < 4; c++) acc[mi][ni][c] = 0.f;

    const int lrow = tid >> 2;
    const int lseg = tid & 3;
    auto load_stage = [&](int st, int k0) {
        #pragma unroll
        for (int i = 0; i < 2; i++) {
            int row = lrow + i * 64;
            uint32_t soA = sA + (uint32_t)st * A_STG2 + row * SROWB + lseg * 16;
            const __half* ga = A + (size_t)(brow + row) * F + k0 + lseg * 8;
            asm volatile("cp.async.cg.shared.global [%0], [%1], 16;"
                         :: "r"(soA), "l"(ga));
        }
        #pragma unroll
        for (int i = 0; i < 4; i++) {
            int row = lrow + i * 64;
            uint32_t soB = sB + (uint32_t)st * B_STG2 + row * SROWB + lseg * 16;
            const __half* gb = B + (size_t)row * F + k0 + lseg * 8;
            asm volatile("cp.async.cg.shared.global [%0], [%1], 16;"
                         :: "r"(soB), "l"(gb));
        }
        asm volatile("cp.async.commit_group;");
    };

    constexpr int NK = F / 32;   // 8
    load_stage(0, 0);
    load_stage(1, 32);

    const int lr  = lane & 15;
    const int lhi = (lane >> 4) * 16;

    int st = 0;
    for (int ki = 0; ki < NK; ki++) {
        if (ki + 1 < NK) asm volatile("cp.async.wait_group 1;");
        else             asm volatile("cp.async.wait_group 0;");
        __syncthreads();
        if (ki + 2 < NK) {
            int st2 = st + 2; if (st2 >= 3) st2 -= 3;
            load_stage(st2, (ki + 2) * 32);
        }
        const uint32_t bufA = sA + st * A_STG2;
        const uint32_t bufB = sB + st * B_STG2;

        #pragma unroll
        for (int kk = 0; kk < 2; kk++) {
            const uint32_t kb = kk * 32;
            uint32_t af[4][4];
            #pragma unroll
            for (int mi = 0; mi < 4; mi++) {
                uint32_t addr = bufA + (wm + mi * 16 + lr) * SROWB + kb + lhi;
                asm volatile("ldmatrix.sync.aligned.m8n8.x4.shared.b16 {%0,%1,%2,%3}, [%4];"
                             : "=r"(af[mi][0]), "=r"(af[mi][1]),
                               "=r"(af[mi][2]), "=r"(af[mi][3]) : "r"(addr));
            }
            #pragma unroll
            for (int p = 0; p < 4; p++) {
                uint32_t r0, r1, r2, r3;
                uint32_t addr = bufB + (wn + p * 16 + lr) * SROWB + kb + lhi;
                asm volatile("ldmatrix.sync.aligned.m8n8.x4.shared.b16 {%0,%1,%2,%3}, [%4];"
                             : "=r"(r0), "=r"(r1), "=r"(r2), "=r"(r3) : "r"(addr));
                #pragma unroll
                for (int mi = 0; mi < 4; mi++) {
                    asm volatile(
                        "mma.sync.aligned.m16n8k16.row.col.f32.f16.f16.f32 "
                        "{%0,%1,%2,%3},{%4,%5,%6,%7},{%8,%9},{%0,%1,%2,%3};"
                        : "+f"(acc[mi][2 * p][0]), "+f"(acc[mi][2 * p][1]),
                          "+f"(acc[mi][2 * p][2]), "+f"(acc[mi][2 * p][3])
                        : "r"(af[mi][0]), "r"(af[mi][1]), "r"(af[mi][2]), "r"(af[mi][3]),
                          "r"(r0), "r"(r2));
                    asm volatile(
                        "mma.sync.aligned.m16n8k16.row.col.f32.f16.f16.f32 "
                        "{%0,%1,%2,%3},{%4,%5,%6,%7},{%8,%9},{%0,%1,%2,%3};"
                        : "+f"(acc[mi][2 * p + 1][0]), "+f"(acc[mi][2 * p + 1][1]),
                          "+f"(acc[mi][2 * p + 1][2]), "+f"(acc[mi][2 * p + 1][3])
                        : "r"(af[mi][0]), "r"(af[mi][1]), "r"(af[mi][2]), "r"(af[mi][3]),
                          "r"(r1), "r"(r3));
                }
            }
        }
        if (++st == 3) st = 0;
    }
    __syncthreads();   // all warps done reading pipeline smem

    // ---- epilogue 1: h2 = relu(acc + b2) -> smem fp16 tile [128][264] ----
    __half* h2s = (__half*)(smem_dyn + H2S_OFF);
    #pragma unroll
    for (int ni = 0; ni < 8; ni++) {
        const int col = wn + ni * 8 + tg * 2;
        const float b0 = __ldg(b2 + col);
        const float b1 = __ldg(b2 + col + 1);
        #pragma unroll
        for (int mi = 0; mi < 4; mi++) {
            int r0 = wm + mi * 16 + g;
            __half2 o0 = __floats2half2_rn(fmaxf(acc[mi][ni][0] + b0, 0.f),
                                           fmaxf(acc[mi][ni][1] + b1, 0.f));
            *(__half2*)(h2s + r0 * 264 + col) = o0;
            __half2 o1 = __floats2half2_rn(fmaxf(acc[mi][ni][2] + b0, 0.f),
                                           fmaxf(acc[mi][ni][3] + b1, 0.f));
            *(__half2*)(h2s + (r0 + 8) * 264 + col) = o1;
        }
    }
    // copy Wc hi/lo into smem [64 rows][264 stride], only 40 real rows
    {
        __half* whi = (__half*)(smem_dyn + WHI_OFF);
        __half* wlo = (__half*)(smem_dyn + WLO_OFF);
        for (int i = tid; i < NOUT * HID / 8; i += 256) {
            int n = (i * 8) / HID, k = (i * 8) % HID;
            *(uint4*)(whi + n * 264 + k) = *(const uint4*)(g_wchi + n * HID + k);
            *(uint4*)(wlo + n * 264 + k) = *(const uint4*)(g_wclo + n * HID + k);
        }
    }
    __syncthreads();

    // ---- epilogue 2: out = h2s @ Wc^T (hi + lo), HMMA, K=256 ----
    float oacc[6][4];
    #pragma unroll
    for (int ni = 0; ni < 6; ni++)
        #pragma unroll
        for (int c = 0; c < 4; c++) oacc[ni][c] = 0.f;

    const uint32_t h2a = sbase + H2S_OFF;
    const uint32_t wha = sbase + WHI_OFF;
    const uint32_t wla = sbase + WLO_OFF;
    const int mrow = wid * 16;   // 8 warps x 16 rows = 128

    #pragma unroll
    for (int kk = 0; kk < 16; kk++) {
        uint32_t a0, a1, a2, a3;
        uint32_t addrA = h2a + (mrow + lr) * H2ROWB + kk * 32 + lhi;
        asm volatile("ldmatrix.sync.aligned.m8n8.x4.shared.b16 {%0,%1,%2,%3}, [%4];"
                     : "=r"(a0), "=r"(a1), "=r"(a2), "=r"(a3) : "r"(addrA));
        #pragma unroll
        for (int p = 0; p < 3; p++) {
            uint32_t r0, r1, r2, r3;
            uint32_t addrB = wha + (p * 16 + lr) * H2ROWB + kk * 32 + lhi;
            asm volatile("ldmatrix.sync.aligned.m8n8.x4.shared.b16 {%0,%1,%2,%3}, [%4];"
                         : "=r"(r0), "=r"(r1), "=r"(r2), "=r"(r3) : "r"(addrB));
            asm volatile(
                "mma.sync.aligned.m16n8k16.row.col.f32.f16.f16.f32 "
                "{%0,%1,%2,%3},{%4,%5,%6,%7},{%8,%9},{%0,%1,%2,%3};"
                : "+f"(oacc[2 * p][0]), "+f"(oacc[2 * p][1]),
                  "+f"(oacc[2 * p][2]), "+f"(oacc[2 * p][3])
                : "r"(a0), "r"(a1), "r"(a2), "r"(a3), "r"(r0), "r"(r2));
            asm volatile(
                "mma.sync.aligned.m16n8k16.row.col.f32.f16.f16.f32 "
                "{%0,%1,%2,%3},{%4,%5,%6,%7},{%8,%9},{%0,%1,%2,%3};"
                : "+f"(oacc[2 * p + 1][0]), "+f"(oacc[2 * p + 1][1]),
                  "+f"(oacc[2 * p + 1][2]), "+f"(oacc[2 * p + 1][3])
                : "r"(a0), "r"(a1), "r"(a2), "r"(a3), "r"(r1), "r"(r3));
            uint32_t addrL = wla + (p * 16 + lr) * H2ROWB + kk * 32 + lhi;
            asm volatile("ldmatrix.sync.aligned.m8n8.x4.shared.b16 {%0,%1,%2,%3}, [%4];"
                         : "=r"(r0), "=r"(r1), "=r"(r2), "=r"(r3) : "r"(addrL));
            asm volatile(
                "mma.sync.aligned.m16n8k16.row.col.f32.f16.f16.f32 "
                "{%0,%1,%2,%3},{%4,%5,%6,%7},{%8,%9},{%0,%1,%2,%3};"
                : "+f"(oacc[2 * p][0]), "+f"(oacc[2 * p][1]),
                  "+f"(oacc[2 * p][2]), "+f"(oacc[2 * p][3])
                : "r"(a0), "r"(a1), "r"(a2), "r"(a3), "r"(r0), "r"(r2));
            asm volatile(
                "mma.sync.aligned.m16n8k16.row.col.f32.f16.f16.f32 "
                "{%0,%1,%2,%3},{%4,%5,%6,%7},{%8,%9},{%0,%1,%2,%3};"
                : "+f"(oacc[2 * p + 1][0]), "+f"(oacc[2 * p + 1][1]),
                  "+f"(oacc[2 * p + 1][2]), "+f"(oacc[2 * p + 1][3])
                : "r"(a0), "r"(a1), "r"(a2), "r"(a3), "r"(r1), "r"(r3));
        }
    }

    // store out[row][0..39] (ni = 5 tile covers cols 40-47: junk, skipped)
    #pragma unroll
    for (int ni = 0; ni < 5; ni++) {
        const int col = ni * 8 + tg * 2;
        const float bcl = __ldg(bc + col);
        const float bch = __ldg(bc + col + 1);
        int r0 = brow + mrow + g;
        if (r0 < NNODES) {
            float2 o = make_float2(oacc[ni][0] + bcl, oacc[ni][1] + bch);
            *(float2*)(out + (size_t)r0 * NOUT + col) = o;
        }
        int r1 = r0 + 8;
        if (r1 < NNODES) {
            float2 o = make_float2(oacc[ni][2] + bcl, oacc[ni][3] + bch);
            *(float2*)(out + (size_t)r1 * NOUT + col) = o;
        }
    }
}

// ---------------- launch ------------------------------------------------------
extern "C" void kernel_launch(void* const* d_in, const int* in_sizes, int n_in,
                              void* d_out, int out_size)
{
    const float* x   = (const float*)d_in[0];
    const float* W1  = (const float*)d_in[1];
    const float* b1  = (const float*)d_in[2];
    const float* W2  = (const float*)d_in[3];
    const float* b2  = (const float*)d_in[4];
    const float* Wc  = (const float*)d_in[5];
    const float* bc  = (const float*)d_in[6];
    const int*   ei  = (const int*)  d_in[7];
    float*       out = (float*)d_out;

    cudaFuncSetAttribute(k_gemm1,  cudaFuncAttributeMaxDynamicSharedMemorySize, GEMM_SMEM);
    cudaFuncSetAttribute(k_gemm2f, cudaFuncAttributeMaxDynamicSharedMemorySize, GEMM2_SMEM);

    const int prepN = NNODES * F_IN / 4;
    k_prep<<<(prepN + 255) / 256, 256>>>(x, W1, W2, Wc);

    k_count  <<<(NEDGES + 255) / 256, 256>>>(ei);
    k_offsets<<<(NNODES + 255) / 256, 256>>>();
    k_scatter<<<(NEDGES + 255) / 256, 256>>>(ei);

    // layer 1: relu(agg(x) @ W1 + b1) -> fp16 h1
    k_agg_x<<<(NNODES * 32 + 255) / 256, 256>>>();
    dim3 g1(HID / 128, MTILES);
    k_gemm1<<<g1, 256, GEMM_SMEM>>>(b1);

    // layer 2 + classifier fused: out = relu(agg(h1) @ W2 + b2) @ Wc + bc
    k_agg_h1<<<(NNODES * 2 * 32 + 255) / 256, 256>>>();
    k_gemm2f<<<MTILES, 256, GEMM2_SMEM>>>(b2, bc, out);
}

// round 16
// speedup vs baseline: 2.0119x; 1.0142x over previous
#include <cuda_runtime.h>
#include <cuda_fp16.h>
#include <cstdint>

#define NNODES 50000
#define NODPAD 50048
#define NEDGES 800000
#define F_IN   128
#define HID    256
#define NOUT   40
#define MTILES (NODPAD / 128)   // 391

// ---------------- scratch (static device memory, no allocations) ------------
// g_cnt / g_total are ZERO at module load and re-zeroed at the end of k_gemm2f
// each run (self-cleaning), so k_precount can atomically count immediately.
__device__ int   g_cnt[NNODES];
__device__ int   g_off[NNODES];
__device__ int   g_rank[NEDGES];
__device__ int   g_total;
__device__ float g_dinv[NNODES];
__device__ __align__(16) int2 g_edge[NEDGES];    // (src, weight bits)
__device__ __align__(16) __half g_xh[(size_t)NNODES * F_IN];     // fp16 x
__device__ __align__(16) __half g_h1h[(size_t)NNODES * HID];     // fp16 h1
__device__ __align__(16) __half g_ax[(size_t)NODPAD * F_IN];     // agg(x) fp16
__device__ __align__(16) __half g_a1[(size_t)NODPAD * HID];      // agg(h1) fp16
__device__ __align__(16) __half g_w1h[HID * F_IN];               // W1^T fp16
__device__ __align__(16) __half g_w2h[HID * HID];                // W2^T fp16
__device__ __align__(16) __half g_wchi[NOUT * HID];              // Wc^T hi fp16
__device__ __align__(16) __half g_wclo[NOUT * HID];              // Wc^T lo fp16

// ---------------- fused count + prep ------------------------------------------
// 800k threads: edge counting (+rank) hides the streaming prep loads.
__global__ void k_precount(const int* __restrict__ ei,
                           const float* __restrict__ x,
                           const float* __restrict__ W1,
                           const float* __restrict__ W2,
                           const float* __restrict__ Wc)
{
    int i = blockIdx.x * blockDim.x + threadIdx.x;
    if (i < NEDGES) {
        int d = ei[NEDGES + i];
        g_rank[i] = atomicAdd(&g_cnt[d], 1);
    }
    if (i < HID * F_IN) {
        int n = i / F_IN, k = i % F_IN;
        g_w1h[i] = __float2half_rn(W1[k * HID + n]);
    }
    if (i < HID * HID) {
        int n = i / HID, k = i % HID;
        g_w2h[i] = __float2half_rn(W2[k * HID + n]);
    }
    if (i < NOUT * HID) {
        int n = i / HID, k = i % HID;
        float v = Wc[k * NOUT + n];
        __half h = __float2half_rn(v);
        g_wchi[i] = h;
        g_wclo[i] = __float2half_rn(v - __half2float(h));
    }
    // x conversion: 1.6M float4 chunks = 2 per thread
    #pragma unroll
    for (int q = 0; q < 2; q++) {
        int j = i + q * NEDGES;
        if (j < NNODES * F_IN / 4) {
            float4 v = ((const float4*)x)[j];
            __half2 a = __floats2half2_rn(v.x, v.y);
            __half2 b = __floats2half2_rn(v.z, v.w);
            uint2 u;
            u.x = *(uint32_t*)&a; u.y = *(uint32_t*)&b;
            ((uint2*)g_xh)[j] = u;
        }
    }
}

__global__ void k_offsets()
{
    int i = blockIdx.x * blockDim.x + threadIdx.x;
    int lane = threadIdx.x & 31;
    int c = (i < NNODES) ? g_cnt[i] : 0;
    int sum = c;
    #pragma unroll
    for (int o = 1; o < 32; o <<= 1) {
        int t = __shfl_up_sync(0xFFFFFFFF, sum, o);
        if (lane >= o) sum += t;
    }
    int wtotal = __shfl_sync(0xFFFFFFFF, sum, 31);
    int base;
    if (lane == 31) base = atomicAdd(&g_total, wtotal);
    base = __shfl_sync(0xFFFFFFFF, base, 31);
    if (i < NNODES) {
        g_off[i]  = base + sum - c;
        g_dinv[i] = rsqrtf((float)(c + 1));
    }
}

// atomic-free scatter, 2 edges/thread for doubled MLP
__global__ void k_scatter(const int* __restrict__ ei)
{
    int e = (blockIdx.x * blockDim.x + threadIdx.x) * 2;
    if (e >= NEDGES) return;
    int2 s2 = *(const int2*)(ei + e);
    int2 d2 = *(const int2*)(ei + NEDGES + e);
    int2 r2 = *(const int2*)(g_rank + e);
    float w0 = g_dinv[s2.x] * g_dinv[d2.x];
    float w1 = g_dinv[s2.y] * g_dinv[d2.y];
    int p0 = g_off[d2.x] + r2.x;
    int p1 = g_off[d2.y] + r2.y;
    g_edge[p0] = make_int2(s2.x, __float_as_int(w0));
    g_edge[p1] = make_int2(s2.y, __float_as_int(w1));
}

// ---------------- sparse aggregation ----------------------------------------
template <int F>
__device__ __forceinline__ void agg_impl(const __half* __restrict__ in,
                                         __half* __restrict__ outp)
{
    constexpr int WPN = F / 128;
    const int gw   = (blockIdx.x * blockDim.x + threadIdx.x) >> 5;
    const int node = gw / WPN;
    const int slc  = gw - node * WPN;
    const int lane = threadIdx.x & 31;
    if (node >= NNODES) return;

    const int coff = slc * 128 + 4 * lane;

    float4 acc;
    const float dn = g_dinv[node];
    const float w0 = dn * dn;
    {
        uint2 u = __ldg((const uint2*)(in + (size_t)node * F + coff));
        float2 f0 = __half22float2(*(const __half2*)&u.x);
        float2 f1 = __half22float2(*(const __half2*)&u.y);
        acc.x = w0 * f0.x; acc.y = w0 * f0.y;
        acc.z = w0 * f1.x; acc.w = w0 * f1.y;
    }

    const int beg = g_off[node];
    const int end = beg + g_cnt[node];
    int i = beg;
    for (; i + 8 <= end; i += 8) {
        int2 e[8];
        #pragma unroll
        for (int q = 0; q < 8; q++) e[q] = g_edge[i + q];
        uint2 u[8];
        #pragma unroll
        for (int q = 0; q < 8; q++)
            u[q] = __ldg((const uint2*)(in + (size_t)e[q].x * F + coff));
        #pragma unroll
        for (int q = 0; q < 8; q++) {
            const float we = __int_as_float(e[q].y);
            float2 f0 = __half22float2(*(const __half2*)&u[q].x);
            float2 f1 = __half22float2(*(const __half2*)&u[q].y);
            acc.x += we * f0.x; acc.y += we * f0.y;
            acc.z += we * f1.x; acc.w += we * f1.y;
        }
    }
    for (; i + 4 <= end; i += 4) {
        int2 e[4];
        #pragma unroll
        for (int q = 0; q < 4; q++) e[q] = g_edge[i + q];
        uint2 u[4];
        #pragma unroll
        for (int q = 0; q < 4; q++)
            u[q] = __ldg((const uint2*)(in + (size_t)e[q].x * F + coff));
        #pragma unroll
        for (int q = 0; q < 4; q++) {
            const float we = __int_as_float(e[q].y);
            float2 f0 = __half22float2(*(const __half2*)&u[q].x);
            float2 f1 = __half22float2(*(const __half2*)&u[q].y);
            acc.x += we * f0.x; acc.y += we * f0.y;
            acc.z += we * f1.x; acc.w += we * f1.y;
        }
    }
    for (; i < end; i++) {
        const int2 e0 = g_edge[i];
        const float we = __int_as_float(e0.y);
        uint2 u0 = __ldg((const uint2*)(in + (size_t)e0.x * F + coff));
        float2 f0 = __half22float2(*(const __half2*)&u0.x);
        float2 f1 = __half22float2(*(const __half2*)&u0.y);
        acc.x += we * f0.x; acc.y += we * f0.y;
        acc.z += we * f1.x; acc.w += we * f1.y;
    }

    __half2 p0 = __floats2half2_rn(acc.x, acc.y);
    __half2 p1 = __floats2half2_rn(acc.z, acc.w);
    uint2 u;
    u.x = *(uint32_t*)&p0; u.y = *(uint32_t*)&p1;
    *(uint2*)(outp + (size_t)node * F + coff) = u;
}

__global__ void k_agg_x()  { agg_impl<F_IN>(g_xh,  g_ax); }
__global__ void k_agg_h1() { agg_impl<HID>(g_h1h, g_a1); }

// ---------------- GEMM1: 128x128 tile, 3-stage, 2 blocks/SM -------------------
#define SROWB 80
#define T_STG (128 * SROWB)
#define GEMM_SMEM (6 * T_STG)                // 61440 B

__global__ void __launch_bounds__(256, 2) k_gemm1(const float* __restrict__ bias)
{
    constexpr int F = F_IN;
    const __half* A = g_ax;
    const __half* B = g_w1h;
    __half* C = g_h1h;

    extern __shared__ __align__(16) uint8_t smem_dyn[];
    uint32_t sA;
    asm("{ .reg .u64 t; cvta.to.shared.u64 t, %1; cvt.u32.u64 %0, t; }"
        : "=r"(sA) : "l"(&smem_dyn[0]));
    const uint32_t sB = sA + 3 * T_STG;

    const int tid  = threadIdx.x;
    const int lane = tid & 31;
    const int wid  = tid >> 5;
    const int g    = lane >> 2;
    const int tg   = lane & 3;
    const int wm   = (wid & 1) * 64;
    const int wn   = (wid >> 1) * 32;
    const int brow = blockIdx.y * 128;
    const int bcol = blockIdx.x * 128;

    float acc[4][4][4];
    #pragma unroll
    for (int mi = 0; mi < 4; mi++)
        #pragma unroll
        for (int ni = 0; ni < 4; ni++)
            #pragma unroll
            for (int c = 0; c < 4; c++) acc[mi][ni][c] = 0.f;

    const int lrow = tid >> 2;
    const int lseg = tid & 3;
    auto load_stage = [&](int st, int k0) {
        #pragma unroll
        for (int i = 0; i < 2; i++) {
            int row = lrow + i * 64;
            uint32_t soA = sA + (uint32_t)st * T_STG + row * SROWB + lseg * 16;
            const __half* ga = A + (size_t)(brow + row) * F + k0 + lseg * 8;
            asm volatile("cp.async.cg.shared.global [%0], [%1], 16;"
                         :: "r"(soA), "l"(ga));
            uint32_t soB = sB + (uint32_t)st * T_STG + row * SROWB + lseg * 16;
            const __half* gb = B + (size_t)(bcol + row) * F + k0 + lseg * 8;
            asm volatile("cp.async.cg.shared.global [%0], [%1], 16;"
                         :: "r"(soB), "l"(gb));
        }
        asm volatile("cp.async.commit_group;");
    };

    constexpr int NK = F / 32;
    load_stage(0, 0);
    load_stage(1, 32);

    const int lr  = lane & 15;
    const int lhi = (lane >> 4) * 16;

    int st = 0;
    for (int ki = 0; ki < NK; ki++) {
        if (ki + 1 < NK) asm volatile("cp.async.wait_group 1;");
        else             asm volatile("cp.async.wait_group 0;");
        __syncthreads();
        if (ki + 2 < NK) {
            int st2 = st + 2; if (st2 >= 3) st2 -= 3;
            load_stage(st2, (ki + 2) * 32);
        }
        const uint32_t bufA = sA + st * T_STG;
        const uint32_t bufB = sB + st * T_STG;

        #pragma unroll
        for (int kk = 0; kk < 2; kk++) {
            const uint32_t kb = kk * 32;
            uint32_t af[4][4];
            #pragma unroll
            for (int mi = 0; mi < 4; mi++) {
                uint32_t addr = bufA + (wm + mi * 16 + lr) * SROWB + kb + lhi;
                asm volatile("ldmatrix.sync.aligned.m8n8.x4.shared.b16 {%0,%1,%2,%3}, [%4];"
                             : "=r"(af[mi][0]), "=r"(af[mi][1]),
                               "=r"(af[mi][2]), "=r"(af[mi][3]) : "r"(addr));
            }
            #pragma unroll
            for (int p = 0; p < 2; p++) {
                uint32_t r0, r1, r2, r3;
                uint32_t addr = bufB + (wn + p * 16 + lr) * SROWB + kb + lhi;
                asm volatile("ldmatrix.sync.aligned.m8n8.x4.shared.b16 {%0,%1,%2,%3}, [%4];"
                             : "=r"(r0), "=r"(r1), "=r"(r2), "=r"(r3) : "r"(addr));
                #pragma unroll
                for (int mi = 0; mi < 4; mi++) {
                    asm volatile(
                        "mma.sync.aligned.m16n8k16.row.col.f32.f16.f16.f32 "
                        "{%0,%1,%2,%3},{%4,%5,%6,%7},{%8,%9},{%0,%1,%2,%3};"
                        : "+f"(acc[mi][2 * p][0]), "+f"(acc[mi][2 * p][1]),
                          "+f"(acc[mi][2 * p][2]), "+f"(acc[mi][2 * p][3])
                        : "r"(af[mi][0]), "r"(af[mi][1]), "r"(af[mi][2]), "r"(af[mi][3]),
                          "r"(r0), "r"(r2));
                    asm volatile(
                        "mma.sync.aligned.m16n8k16.row.col.f32.f16.f16.f32 "
                        "{%0,%1,%2,%3},{%4,%5,%6,%7},{%8,%9},{%0,%1,%2,%3};"
                        : "+f"(acc[mi][2 * p + 1][0]), "+f"(acc[mi][2 * p + 1][1]),
                          "+f"(acc[mi][2 * p + 1][2]), "+f"(acc[mi][2 * p + 1][3])
                        : "r"(af[mi][0]), "r"(af[mi][1]), "r"(af[mi][2]), "r"(af[mi][3]),
                          "r"(r1), "r"(r3));
                }
            }
        }
        if (++st == 3) st = 0;
    }

    #pragma unroll
    for (int ni = 0; ni < 4; ni++) {
        const int col = bcol + wn + ni * 8 + tg * 2;
        const float b0 = __ldg(bias + col);
        const float b1 = __ldg(bias + col + 1);
        #pragma unroll
        for (int mi = 0; mi < 4; mi++) {
            int r0 = brow + wm + mi * 16 + g;
            if (r0 < NNODES) {
                __half2 o = __floats2half2_rn(fmaxf(acc[mi][ni][0] + b0, 0.f),
                                              fmaxf(acc[mi][ni][1] + b1, 0.f));
                *(__half2*)(C + (size_t)r0 * HID + col) = o;
            }
            int r1 = r0 + 8;
            if (r1 < NNODES) {
                __half2 o = __floats2half2_rn(fmaxf(acc[mi][ni][2] + b0, 0.f),
                                              fmaxf(acc[mi][ni][3] + b1, 0.f));
                *(__half2*)(C + (size_t)r1 * HID + col) = o;
            }
        }
    }
}

// ---------------- GEMM2 + classifier fused (+ counter cleanup) ----------------
#define A_STG2 10240
#define B_STG2 20480
#define H2ROWB 528
#define H2S_OFF 0
#define WHI_OFF (128 * H2ROWB)
#define WLO_OFF (WHI_OFF + 64 * H2ROWB)
#define GEMM2_SMEM (WLO_OFF + 64 * H2ROWB)   // 135168

__global__ void __launch_bounds__(256) k_gemm2f(const float* __restrict__ b2,
                                                const float* __restrict__ bc,
                                                float* __restrict__ out)
{
    constexpr int F = HID;
    const __half* A = g_a1;
    const __half* B = g_w2h;

    extern __shared__ __align__(16) uint8_t smem_dyn[];
    uint32_t sbase;
    asm("{ .reg .u64 t; cvta.to.shared.u64 t, %1; cvt.u32.u64 %0, t; }"
        : "=r"(sbase) : "l"(&smem_dyn[0]));
    const uint32_t sA = sbase;
    const uint32_t sB = sbase + 3 * A_STG2;

    const int tid  = threadIdx.x;
    const int lane = tid & 31;
    const int wid  = tid >> 5;
    const int g    = lane >> 2;
    const int tg   = lane & 3;
    const int wm   = (wid & 1) * 64;
    const int wn   = (wid >> 1) * 64;
    const int brow = blockIdx.x * 128;

    float acc[4][8][4];
    #pragma unroll
    for (int mi = 0; mi < 4; mi++)
        #pragma unroll
        for (int ni = 0; ni < 8; ni++)
            #pragma unroll
            for (int c = 0; c < 4; c++) acc[mi][ni][c] = 0.f;

    const int lrow = tid >> 2;
    const int lseg = tid & 3;
    auto load_stage = [&](int st, int k0) {
        #pragma unroll
        for (int i = 0; i < 2; i++) {
            int row = lrow + i * 64;
            uint32_t soA = sA + (uint32_t)st * A_STG2 + row * SROWB + lseg * 16;
            const __half* ga = A + (size_t)(brow + row) * F + k0 + lseg * 8;
            asm volatile("cp.async.cg.shared.global [%0], [%1], 16;"
                         :: "r"(soA), "l"(ga));
        }
        #pragma unroll
        for (int i = 0; i < 4; i++) {
            int row = lrow + i * 64;
            uint32_t soB = sB + (uint32_t)st * B_STG2 + row * SROWB + lseg * 16;
            const __half* gb = B + (size_t)row * F + k0 + lseg * 8;
            asm volatile("cp.async.cg.shared.global [%0], [%1], 16;"
                         :: "r"(soB), "l"(gb));
        }
        asm volatile("cp.async.commit_group;");
    };

    constexpr int NK = F / 32;   // 8
    load_stage(0, 0);
    load_stage(1, 32);

    const int lr  = lane & 15;
    const int lhi = (lane >> 4) * 16;

    int st = 0;
    for (int ki = 0; ki < NK; ki++) {
        if (ki + 1 < NK) asm volatile("cp.async.wait_group 1;");
        else             asm volatile("cp.async.wait_group 0;");
        __syncthreads();
        if (ki + 2 < NK) {
            int st2 = st + 2; if (st2 >= 3) st2 -= 3;
            load_stage(st2, (ki + 2) * 32);
        }
        const uint32_t bufA = sA + st * A_STG2;
        const uint32_t bufB = sB + st * B_STG2;

        #pragma unroll
        for (int kk = 0; kk < 2; kk++) {
            const uint32_t kb = kk * 32;
            uint32_t af[4][4];
            #pragma unroll
            for (int mi = 0; mi < 4; mi++) {
                uint32_t addr = bufA + (wm + mi * 16 + lr) * SROWB + kb + lhi;
                asm volatile("ldmatrix.sync.aligned.m8n8.x4.shared.b16 {%0,%1,%2,%3}, [%4];"
                             : "=r"(af[mi][0]), "=r"(af[mi][1]),
                               "=r"(af[mi][2]), "=r"(af[mi][3]) : "r"(addr));
            }
            #pragma unroll
            for (int p = 0; p < 4; p++) {
                uint32_t r0, r1, r2, r3;
                uint32_t addr = bufB + (wn + p * 16 + lr) * SROWB + kb + lhi;
                asm volatile("ldmatrix.sync.aligned.m8n8.x4.shared.b16 {%0,%1,%2,%3}, [%4];"
                             : "=r"(r0), "=r"(r1), "=r"(r2), "=r"(r3) : "r"(addr));
                #pragma unroll
                for (int mi = 0; mi < 4; mi++) {
                    asm volatile(
                        "mma.sync.aligned.m16n8k16.row.col.f32.f16.f16.f32 "
                        "{%0,%1,%2,%3},{%4,%5,%6,%7},{%8,%9},{%0,%1,%2,%3};"
                        : "+f"(acc[mi][2 * p][0]), "+f"(acc[mi][2 * p][1]),
                          "+f"(acc[mi][2 * p][2]), "+f"(acc[mi][2 * p][3])
                        : "r"(af[mi][0]), "r"(af[mi][1]), "r"(af[mi][2]), "r"(af[mi][3]),
                          "r"(r0), "r"(r2));
                    asm volatile(
                        "mma.sync.aligned.m16n8k16.row.col.f32.f16.f16.f32 "
                        "{%0,%1,%2,%3},{%4,%5,%6,%7},{%8,%9},{%0,%1,%2,%3};"
                        : "+f"(acc[mi][2 * p + 1][0]), "+f"(acc[mi][2 * p + 1][1]),
                          "+f"(acc[mi][2 * p + 1][2]), "+f"(acc[mi][2 * p + 1][3])
                        : "r"(af[mi][0]), "r"(af[mi][1]), "r"(af[mi][2]), "r"(af[mi][3]),
                          "r"(r1), "r"(r3));
                }
            }
        }
        if (++st == 3) st = 0;
    }
    __syncthreads();

    // ---- epilogue 1: h2 = relu(acc + b2) -> smem fp16 tile [128][264] ----
    __half* h2s = (__half*)(smem_dyn + H2S_OFF);
    #pragma unroll
    for (int ni = 0; ni < 8; ni++) {
        const int col = wn + ni * 8 + tg * 2;
        const float b0 = __ldg(b2 + col);
        const float b1 = __ldg(b2 + col + 1);
        #pragma unroll
        for (int mi = 0; mi < 4; mi++) {
            int r0 = wm + mi * 16 + g;
            __half2 o0 = __floats2half2_rn(fmaxf(acc[mi][ni][0] + b0, 0.f),
                                           fmaxf(acc[mi][ni][1] + b1, 0.f));
            *(__half2*)(h2s + r0 * 264 + col) = o0;
            __half2 o1 = __floats2half2_rn(fmaxf(acc[mi][ni][2] + b0, 0.f),
                                           fmaxf(acc[mi][ni][3] + b1, 0.f));
            *(__half2*)(h2s + (r0 + 8) * 264 + col) = o1;
        }
    }
    {
        __half* whi = (__half*)(smem_dyn + WHI_OFF);
        __half* wlo = (__half*)(smem_dyn + WLO_OFF);
        for (int i = tid; i < NOUT * HID / 8; i += 256) {
            int n = (i * 8) / HID, k = (i * 8) % HID;
            *(uint4*)(whi + n * 264 + k) = *(const uint4*)(g_wchi + n * HID + k);
            *(uint4*)(wlo + n * 264 + k) = *(const uint4*)(g_wclo + n * HID + k);
        }
    }
    __syncthreads();

    // ---- epilogue 2: out = h2s @ Wc^T (hi + lo), HMMA, K=256 ----
    float oacc[6][4];
    #pragma unroll
    for (int ni = 0; ni < 6; ni++)
        #pragma unroll
        for (int c = 0; c < 4; c++) oacc[ni][c] = 0.f;

    const uint32_t h2a = sbase + H2S_OFF;
    const uint32_t wha = sbase + WHI_OFF;
    const uint32_t wla = sbase + WLO_OFF;
    const int mrow = wid * 16;

    #pragma unroll
    for (int kk = 0; kk < 16; kk++) {
        uint32_t a0, a1, a2, a3;
        uint32_t addrA = h2a + (mrow + lr) * H2ROWB + kk * 32 + lhi;
        asm volatile("ldmatrix.sync.aligned.m8n8.x4.shared.b16 {%0,%1,%2,%3}, [%4];"
                     : "=r"(a0), "=r"(a1), "=r"(a2), "=r"(a3) : "r"(addrA));
        #pragma unroll
        for (int p = 0; p < 3; p++) {
            uint32_t r0, r1, r2, r3;
            uint32_t addrB = wha + (p * 16 + lr) * H2ROWB + kk * 32 + lhi;
            asm volatile("ldmatrix.sync.aligned.m8n8.x4.shared.b16 {%0,%1,%2,%3}, [%4];"
                         : "=r"(r0), "=r"(r1), "=r"(r2), "=r"(r3) : "r"(addrB));
            asm volatile(
                "mma.sync.aligned.m16n8k16.row.col.f32.f16.f16.f32 "
                "{%0,%1,%2,%3},{%4,%5,%6,%7},{%8,%9},{%0,%1,%2,%3};"
                : "+f"(oacc[2 * p][0]), "+f"(oacc[2 * p][1]),
                  "+f"(oacc[2 * p][2]), "+f"(oacc[2 * p][3])
                : "r"(a0), "r"(a1), "r"(a2), "r"(a3), "r"(r0), "r"(r2));
            asm volatile(
                "mma.sync.aligned.m16n8k16.row.col.f32.f16.f16.f32 "
                "{%0,%1,%2,%3},{%4,%5,%6,%7},{%8,%9},{%0,%1,%2,%3};"
                : "+f"(oacc[2 * p + 1][0]), "+f"(oacc[2 * p + 1][1]),
                  "+f"(oacc[2 * p + 1][2]), "+f"(oacc[2 * p + 1][3])
                : "r"(a0), "r"(a1), "r"(a2), "r"(a3), "r"(r1), "r"(r3));
            uint32_t addrL = wla + (p * 16 + lr) * H2ROWB + kk * 32 + lhi;
            asm volatile("ldmatrix.sync.aligned.m8n8.x4.shared.b16 {%0,%1,%2,%3}, [%4];"
                         : "=r"(r0), "=r"(r1), "=r"(r2), "=r"(r3) : "r"(addrL));
            asm volatile(
                "mma.sync.aligned.m16n8k16.row.col.f32.f16.f16.f32 "
                "{%0,%1,%2,%3},{%4,%5,%6,%7},{%8,%9},{%0,%1,%2,%3};"
                : "+f"(oacc[2 * p][0]), "+f"(oacc[2 * p][1]),
                  "+f"(oacc[2 * p][2]), "+f"(oacc[2 * p][3])
                : "r"(a0), "r"(a1), "r"(a2), "r"(a3), "r"(r0), "r"(r2));
            asm volatile(
                "mma.sync.aligned.m16n8k16.row.col.f32.f16.f16.f32 "
                "{%0,%1,%2,%3},{%4,%5,%6,%7},{%8,%9},{%0,%1,%2,%3};"
                : "+f"(oacc[2 * p + 1][0]), "+f"(oacc[2 * p + 1][1]),
                  "+f"(oacc[2 * p + 1][2]), "+f"(oacc[2 * p + 1][3])
                : "r"(a0), "r"(a1), "r"(a2), "r"(a3), "r"(r1), "r"(r3));
        }
    }

    #pragma unroll
    for (int ni = 0; ni < 5; ni++) {
        const int col = ni * 8 + tg * 2;
        const float bcl = __ldg(bc + col);
        const float bch = __ldg(bc + col + 1);
        int r0 = brow + mrow + g;
        if (r0 < NNODES) {
            float2 o = make_float2(oacc[ni][0] + bcl, oacc[ni][1] + bch);
            *(float2*)(out + (size_t)r0 * NOUT + col) = o;
        }
        int r1 = r0 + 8;
        if (r1 < NNODES) {
            float2 o = make_float2(oacc[ni][2] + bcl, oacc[ni][3] + bch);
            *(float2*)(out + (size_t)r1 * NOUT + col) = o;
        }
    }

    // ---- cleanup: re-zero counters for the next invocation ----
    {
        int i = blockIdx.x * 256 + tid;
        if (i < NNODES) g_cnt[i] = 0;
        if (i == 0) g_total = 0;
    }
}

// ---------------- launch ------------------------------------------------------
extern "C" void kernel_launch(void* const* d_in, const int* in_sizes, int n_in,
                              void* d_out, int out_size)
{
    const float* x   = (const float*)d_in[0];
    const float* W1  = (const float*)d_in[1];
    const float* b1  = (const float*)d_in[2];
    const float* W2  = (const float*)d_in[3];
    const float* b2  = (const float*)d_in[4];
    const float* Wc  = (const float*)d_in[5];
    const float* bc  = (const float*)d_in[6];
    const int*   ei  = (const int*)  d_in[7];
    float*       out = (float*)d_out;

    cudaFuncSetAttribute(k_gemm1,  cudaFuncAttributeMaxDynamicSharedMemorySize, GEMM_SMEM);
    cudaFuncSetAttribute(k_gemm2f, cudaFuncAttributeMaxDynamicSharedMemorySize, GEMM2_SMEM);

    // fused count + prep (counters are zero: static init / previous cleanup)
    k_precount<<<(NEDGES + 255) / 256, 256>>>(ei, x, W1, W2, Wc);
    k_offsets <<<(NNODES + 255) / 256, 256>>>();
    k_scatter <<<(NEDGES / 2 + 255) / 256, 256>>>(ei);

    // layer 1: relu(agg(x) @ W1 + b1) -> fp16 h1
    k_agg_x<<<(NNODES * 32 + 255) / 256, 256>>>();
    dim3 g1(HID / 128, MTILES);
    k_gemm1<<<g1, 256, GEMM_SMEM>>>(b1);

    // layer 2 + classifier fused (+ counter cleanup)
    k_agg_h1<<<(NNODES * 2 * 32 + 255) / 256, 256>>>();
    k_gemm2f<<<MTILES, 256, GEMM2_SMEM>>>(b2, bc, out);
}